// round 1
// baseline (speedup 1.0000x reference)
#include <cuda_runtime.h>
#include <math.h>

// Problem dims
#define Bc   64
#define Pc   196
#define Sc   22
#define Tc   21
#define Vc   10000
#define Ec   512
#define Ac   512
#define Uc   512
#define ENCc 2048
#define KXH  3072   // E + ENC + U
#define N4U  2048   // 4*U

// ---------------- scratch (static __device__ arrays; no allocation) -------------
__device__ float g_enc[Bc * Pc * ENCc];    // sorted encoder output  (102.8 MB)
__device__ float g_att1[Bc * Pc * Ac];     // enc @ W_att_enc + b    (25.7 MB)
__device__ float g_Wxh[KXH * N4U];         // concat(W_x, W_h)       (25.2 MB)
__device__ float g_mean[Bc * ENCc];
__device__ float g_h[Bc * Uc];
__device__ float g_c[Bc * Uc];
__device__ float g_att2[Bc * Ac];
__device__ float g_alpha[Bc * Pc];
__device__ float g_beta[Bc * ENCc];        // raw (pre-sigmoid) beta logits
__device__ float g_xh[Bc * KXH];           // [emb_t | awe*beta | h]
__device__ float g_z[Bc * N4U];
__device__ float g_logits[Bc * Vc];
__device__ int   g_order[Bc];
__device__ int   g_ilen[Bc];
__device__ int   g_seqs[Bc * Sc];

// ---------------- sort: stable argsort(-lens), write int scratch + float outputs
__global__ void sort_kernel(const int* __restrict__ lens,
                            const int* __restrict__ seqs,
                            float* __restrict__ out_seqs,
                            float* __restrict__ out_ilen,
                            float* __restrict__ out_order) {
    int tid = threadIdx.x;  // 64 threads
    __shared__ int s_len[Bc];
    s_len[tid] = lens[tid];
    __syncthreads();
    int myL = s_len[tid];
    int rank = 0;
    for (int j = 0; j < Bc; j++) {
        int lj = s_len[j];
        rank += (lj > myL) || (lj == myL && j < tid);
    }
    g_order[rank] = tid;
    __syncthreads();
    int src = g_order[tid];
    int il = s_len[src] - 1;
    g_ilen[tid] = il;
    out_ilen[tid] = (float)il;
    out_order[tid] = (float)src;
    for (int s = 0; s < Sc; s++) {
        int v = seqs[src * Sc + s];
        g_seqs[tid * Sc + s] = v;
        out_seqs[tid * Sc + s] = (float)v;
    }
}

// ---------------- permute encoder rows into sorted order ------------------------
__global__ void permute_kernel(const float* __restrict__ enc) {
    int b = blockIdx.x, p = blockIdx.y;
    int src = g_order[b];
    const float4* s = (const float4*)&enc[((long)src * Pc + p) * ENCc];
    float4* d = (float4*)&g_enc[((long)b * Pc + p) * ENCc];
    for (int i = threadIdx.x; i < ENCc / 4; i += 256) d[i] = s[i];
}

// ---------------- build concat weight [W_x ; W_h] --------------------------------
__global__ void wxh_kernel(const float* __restrict__ Wx, const float* __restrict__ Wh) {
    long idx = (long)blockIdx.x * 256 + threadIdx.x;
    if (idx >= (long)KXH * N4U) return;
    int k = (int)(idx / N4U), n = (int)(idx % N4U);
    g_Wxh[idx] = (k < Ec + ENCc) ? Wx[idx] : Wh[(long)(k - (Ec + ENCc)) * N4U + n];
}

// ---------------- mean over pixels ----------------------------------------------
__global__ void mean_kernel() {
    int b = blockIdx.x;
    int e = blockIdx.y * 256 + threadIdx.x;
    const float* encb = &g_enc[(long)b * Pc * ENCc + e];
    float s = 0.f;
#pragma unroll 4
    for (int p = 0; p < Pc; p++) s += encb[(long)p * ENCc];
    g_mean[b * ENCc + e] = s * (1.0f / Pc);
}

// ---------------- generic skinny GEMM: out[64*My, N] (+)= A[64*My, K] @ W[K, N] --
// grid = (ceil(N/64), Mtiles, ksplit). If ksplit==1: store with bias. Else:
// atomicAdd (out must be pre-zeroed; bias handled by consumer).
__global__ __launch_bounds__(256) void gemm64_kernel(
    const float* __restrict__ A, int lda,
    const float* __restrict__ W,
    const float* __restrict__ bias,
    float* __restrict__ out,
    int K, int N) {
    __shared__ float As[64][33];
    __shared__ float Ws[32][65];
    int tid = threadIdx.x;
    int tc = tid & 31, tr = tid >> 5;
    int n0 = blockIdx.x * 64;
    int ksplit = gridDim.z;
    int kchunk = K / ksplit;
    int kbeg = blockIdx.z * kchunk;
    const float* Ab = A + (long)blockIdx.y * 64 * lda;
    float* ob = out + (long)blockIdx.y * 64 * N;

    float acc[8][2];
#pragma unroll
    for (int r = 0; r < 8; r++) { acc[r][0] = 0.f; acc[r][1] = 0.f; }

    for (int k0 = kbeg; k0 < kbeg + kchunk; k0 += 32) {
#pragma unroll
        for (int i = 0; i < 8; i++) {
            int lin = tid + i * 256;
            int r = lin >> 5, kk = lin & 31;
            As[r][kk] = Ab[(long)r * lda + k0 + kk];
        }
#pragma unroll
        for (int i = 0; i < 8; i++) {
            int lin = tid + i * 256;
            int kk = lin >> 6, n = lin & 63;
            int col = n0 + n;
            Ws[kk][n] = (col < N) ? W[(long)(k0 + kk) * N + col] : 0.f;
        }
        __syncthreads();
#pragma unroll
        for (int kk = 0; kk < 32; kk++) {
            float w0 = Ws[kk][tc], w1 = Ws[kk][tc + 32];
#pragma unroll
            for (int r = 0; r < 8; r++) {
                float a = As[tr * 8 + r][kk];
                acc[r][0] = fmaf(a, w0, acc[r][0]);
                acc[r][1] = fmaf(a, w1, acc[r][1]);
            }
        }
        __syncthreads();
    }

    int c0 = n0 + tc, c1 = n0 + tc + 32;
    if (ksplit == 1) {
#pragma unroll
        for (int r = 0; r < 8; r++) {
            int row = tr * 8 + r;
            if (c0 < N) ob[(long)row * N + c0] = acc[r][0] + bias[c0];
            if (c1 < N) ob[(long)row * N + c1] = acc[r][1] + bias[c1];
        }
    } else {
#pragma unroll
        for (int r = 0; r < 8; r++) {
            int row = tr * 8 + r;
            if (c0 < N) atomicAdd(&ob[(long)row * N + c0], acc[r][0]);
            if (c1 < N) atomicAdd(&ob[(long)row * N + c1], acc[r][1]);
        }
    }
}

// ---------------- zero kernels ---------------------------------------------------
__global__ void zero_hc_kernel() {
    int i = blockIdx.x * 256 + threadIdx.x;
    if (i < Bc * Uc) { g_h[i] = 0.f; g_c[i] = 0.f; }
}
__global__ void hc_bias_kernel(const float* __restrict__ bm, const float* __restrict__ bc) {
    int b = blockIdx.x, n = threadIdx.x;
    g_h[b * Uc + n] += bm[n];
    g_c[b * Uc + n] += bc[n];
}
__global__ void zero_step_kernel() {
    int i = blockIdx.x * 256 + threadIdx.x;
    if (i < Bc * N4U) { g_z[i] = 0.f; g_beta[i] = 0.f; }
    if (i < Bc * Ac) g_att2[i] = 0.f;
    if (i < Bc * Vc) g_logits[i] = 0.f;
}

// ---------------- attention scores + softmax over pixels -------------------------
__global__ void attn_kernel(const float* __restrict__ bgen,
                            const float* __restrict__ wf,
                            const float* __restrict__ bf,
                            float* __restrict__ out_alpha, int t) {
    int b = blockIdx.x;
    __shared__ float s_att2[Ac];
    __shared__ float s_wf[Ac];
    __shared__ float s_e[Pc];
    __shared__ float s_m[8];
    __shared__ float s_s[8];
    int tid = threadIdx.x;  // 256
    for (int a = tid; a < Ac; a += 256) {
        s_att2[a] = g_att2[b * Ac + a] + bgen[a];
        s_wf[a] = wf[a];
    }
    __syncthreads();
    int warp = tid >> 5, lane = tid & 31;
    const float* att1b = &g_att1[(long)b * Pc * Ac];
    float bfull = bf[0];
    for (int p = warp; p < Pc; p += 8) {
        const float* row = att1b + (long)p * Ac;
        float s = 0.f;
        for (int a = lane; a < Ac; a += 32) {
            float v = row[a] + s_att2[a];
            if (v > 0.f) s = fmaf(v, s_wf[a], s);
        }
#pragma unroll
        for (int o = 16; o; o >>= 1) s += __shfl_xor_sync(0xffffffff, s, o);
        if (lane == 0) s_e[p] = s + bfull;
    }
    __syncthreads();
    // softmax over Pc
    float m = -1e30f;
    for (int p = tid; p < Pc; p += 256) m = fmaxf(m, s_e[p]);
#pragma unroll
    for (int o = 16; o; o >>= 1) m = fmaxf(m, __shfl_xor_sync(0xffffffff, m, o));
    if (lane == 0) s_m[warp] = m;
    __syncthreads();
    m = s_m[0];
#pragma unroll
    for (int w = 1; w < 8; w++) m = fmaxf(m, s_m[w]);
    float sum = 0.f;
    for (int p = tid; p < Pc; p += 256) {
        float ex = expf(s_e[p] - m);
        s_e[p] = ex;
        sum += ex;
    }
#pragma unroll
    for (int o = 16; o; o >>= 1) sum += __shfl_xor_sync(0xffffffff, sum, o);
    if (lane == 0) s_s[warp] = sum;
    __syncthreads();
    sum = 0.f;
#pragma unroll
    for (int w = 0; w < 8; w++) sum += s_s[w];
    float inv = 1.0f / sum;
    bool mask = t < g_ilen[b];
    for (int p = tid; p < Pc; p += 256) {
        float al = s_e[p] * inv;
        g_alpha[b * Pc + p] = al;
        out_alpha[((long)b * Tc + t) * Pc + p] = mask ? al : 0.f;
    }
}

// ---------------- awe = (alpha . enc) * sigmoid(beta), written into xh ------------
__global__ void awe_kernel(const float* __restrict__ bbeta) {
    int b = blockIdx.x;
    int e = blockIdx.y * 128 + threadIdx.x;
    __shared__ float s_al[Pc];
    for (int p = threadIdx.x; p < Pc; p += 128) s_al[p] = g_alpha[b * Pc + p];
    __syncthreads();
    const float* encb = &g_enc[(long)b * Pc * ENCc + e];
    float s = 0.f;
#pragma unroll 4
    for (int p = 0; p < Pc; p++) s = fmaf(s_al[p], encb[(long)p * ENCc], s);
    float bl = g_beta[b * ENCc + e] + bbeta[e];
    float beta = 1.0f / (1.0f + expf(-bl));
    g_xh[b * KXH + Ec + e] = s * beta;
}

// ---------------- gather embedding + copy h into xh -------------------------------
__global__ void embh_kernel(const float* __restrict__ emb_table, int t) {
    int b = blockIdx.x, e = threadIdx.x;  // 512
    int tok = g_seqs[b * Sc + t];
    g_xh[b * KXH + e] = emb_table[(long)tok * Ec + e];
    g_xh[b * KXH + Ec + ENCc + e] = g_h[b * Uc + e];
}

// ---------------- LSTM gates + masked state update --------------------------------
__global__ void gates_kernel(const float* __restrict__ bl, int t) {
    int b = blockIdx.x, n = threadIdx.x;  // 512
    const float* z = &g_z[b * N4U];
    float zi = z[n]          + bl[n];
    float zf = z[Uc + n]     + bl[Uc + n];
    float zg = z[2 * Uc + n] + bl[2 * Uc + n];
    float zo = z[3 * Uc + n] + bl[3 * Uc + n];
    float c_old = g_c[b * Uc + n], h_old = g_h[b * Uc + n];
    float si = 1.0f / (1.0f + expf(-zi));
    float sf = 1.0f / (1.0f + expf(-zf));
    float so = 1.0f / (1.0f + expf(-zo));
    float c_new = sf * c_old + si * tanhf(zg);
    float h_new = so * tanhf(c_new);
    bool mask = t < g_ilen[b];
    g_c[b * Uc + n] = mask ? c_new : c_old;
    g_h[b * Uc + n] = mask ? h_new : h_old;
}

// ---------------- vocab softmax, masked, straight to output -----------------------
__global__ void pred_softmax_kernel(const float* __restrict__ bo,
                                    float* __restrict__ out_pred, int t) {
    int b = blockIdx.x, tid = threadIdx.x;  // 256
    float* dst = &out_pred[((long)b * Tc + t) * Vc];
    bool mask = t < g_ilen[b];
    if (!mask) {
        for (int v = tid; v < Vc; v += 256) dst[v] = 0.f;
        return;
    }
    const float* lg = &g_logits[(long)b * Vc];
    __shared__ float s_m[8];
    __shared__ float s_s[8];
    int warp = tid >> 5, lane = tid & 31;
    float m = -1e30f;
    for (int v = tid; v < Vc; v += 256) m = fmaxf(m, lg[v] + bo[v]);
#pragma unroll
    for (int o = 16; o; o >>= 1) m = fmaxf(m, __shfl_xor_sync(0xffffffff, m, o));
    if (lane == 0) s_m[warp] = m;
    __syncthreads();
    m = s_m[0];
#pragma unroll
    for (int w = 1; w < 8; w++) m = fmaxf(m, s_m[w]);
    float sum = 0.f;
    for (int v = tid; v < Vc; v += 256) {
        float ex = expf(lg[v] + bo[v] - m);
        dst[v] = ex;
        sum += ex;
    }
#pragma unroll
    for (int o = 16; o; o >>= 1) sum += __shfl_xor_sync(0xffffffff, sum, o);
    if (lane == 0) s_s[warp] = sum;
    __syncthreads();
    sum = 0.f;
#pragma unroll
    for (int w = 0; w < 8; w++) sum += s_s[w];
    float inv = 1.0f / sum;
    for (int v = tid; v < Vc; v += 256) dst[v] *= inv;
}

// ---------------- device symbol helpers (host-visible launcher) -------------------
extern "C" void kernel_launch(void* const* d_in, const int* in_sizes, int n_in,
                              void* d_out, int out_size) {
    const float* enc      = (const float*)d_in[0];
    const int*   seqs     = (const int*)  d_in[1];
    const int*   lens     = (const int*)  d_in[2];
    const float* emb_tab  = (const float*)d_in[3];
    const float* W_ae     = (const float*)d_in[4];
    const float* b_ae     = (const float*)d_in[5];
    const float* W_ag     = (const float*)d_in[6];
    const float* b_ag     = (const float*)d_in[7];
    const float* W_af     = (const float*)d_in[8];
    const float* b_af     = (const float*)d_in[9];
    const float* W_x      = (const float*)d_in[10];
    const float* W_h      = (const float*)d_in[11];
    const float* b_lstm   = (const float*)d_in[12];
    const float* W_im     = (const float*)d_in[13];
    const float* b_im     = (const float*)d_in[14];
    const float* W_ic     = (const float*)d_in[15];
    const float* b_ic     = (const float*)d_in[16];
    const float* W_beta   = (const float*)d_in[17];
    const float* b_beta   = (const float*)d_in[18];
    const float* W_out    = (const float*)d_in[19];
    const float* b_out    = (const float*)d_in[20];

    float* out       = (float*)d_out;
    float* out_pred  = out;                                   // [B,T,V]
    float* out_alpha = out_pred + (size_t)Bc * Tc * Vc;       // [B,T,P]
    float* out_seqs  = out_alpha + (size_t)Bc * Tc * Pc;      // [B,S]
    float* out_ilen  = out_seqs + (size_t)Bc * Sc;            // [B]
    float* out_order = out_ilen + Bc;                         // [B]

    // device scratch symbol addresses (for GEMM args)
    float *p_enc, *p_att1, *p_Wxh, *p_mean, *p_h, *p_c, *p_att2, *p_beta, *p_xh, *p_z, *p_logits;
    cudaGetSymbolAddress((void**)&p_enc, g_enc);
    cudaGetSymbolAddress((void**)&p_att1, g_att1);
    cudaGetSymbolAddress((void**)&p_Wxh, g_Wxh);
    cudaGetSymbolAddress((void**)&p_mean, g_mean);
    cudaGetSymbolAddress((void**)&p_h, g_h);
    cudaGetSymbolAddress((void**)&p_c, g_c);
    cudaGetSymbolAddress((void**)&p_att2, g_att2);
    cudaGetSymbolAddress((void**)&p_beta, g_beta);
    cudaGetSymbolAddress((void**)&p_xh, g_xh);
    cudaGetSymbolAddress((void**)&p_z, g_z);
    cudaGetSymbolAddress((void**)&p_logits, g_logits);

    // ---- setup ----
    sort_kernel<<<1, Bc>>>(lens, seqs, out_seqs, out_ilen, out_order);
    permute_kernel<<<dim3(Bc, Pc), 256>>>(enc);
    wxh_kernel<<<(KXH * N4U + 255) / 256, 256>>>(W_x, W_h);
    zero_hc_kernel<<<(Bc * Uc + 255) / 256, 256>>>();
    mean_kernel<<<dim3(Bc, ENCc / 256), 256>>>();
    // h0 = mean @ W_init_m (ksplit=8, atomic), then +bias; same for c0
    gemm64_kernel<<<dim3(Uc / 64, 1, 8), 256>>>(p_mean, ENCc, W_im, b_im, p_h, ENCc, Uc);
    gemm64_kernel<<<dim3(Uc / 64, 1, 8), 256>>>(p_mean, ENCc, W_ic, b_ic, p_c, ENCc, Uc);
    hc_bias_kernel<<<Bc, Uc>>>(b_im, b_ic);
    // att1 = enc_sorted @ W_att_enc + b  (12544 x 512, K=2048), ksplit=1 w/ bias
    gemm64_kernel<<<dim3(Ac / 64, (Bc * Pc) / 64, 1), 256>>>(p_enc, ENCc, W_ae, b_ae, p_att1, ENCc, Ac);

    // ---- time steps ----
    for (int t = 0; t < Tc; t++) {
        zero_step_kernel<<<(Bc * Vc + 255) / 256, 256>>>();
        // att2 = c @ W_att_gen (bias added in attn kernel)
        gemm64_kernel<<<dim3(Ac / 64, 1, 8), 256>>>(p_c, Uc, W_ag, b_ag, p_att2, Uc, Ac);
        attn_kernel<<<Bc, 256>>>(b_ag, W_af, b_af, out_alpha, t);
        // beta logits = c @ W_beta (sigmoid+bias in awe kernel)
        gemm64_kernel<<<dim3(ENCc / 64, 1, 4), 256>>>(p_c, Uc, W_beta, b_beta, p_beta, Uc, ENCc);
        awe_kernel<<<dim3(Bc, ENCc / 128), 128>>>(b_beta);
        embh_kernel<<<Bc, Ec>>>(emb_tab, t);
        // z = xh @ Wxh (bias in gates kernel)
        gemm64_kernel<<<dim3(N4U / 64, 1, 8), 256>>>(p_xh, KXH, p_Wxh, b_lstm, p_z, KXH, N4U);
        gates_kernel<<<Bc, Uc>>>(b_lstm, t);
        // logits = c2 @ W_out (bias in softmax kernel)
        gemm64_kernel<<<dim3((Vc + 63) / 64, 1, 2), 256>>>(p_c, Uc, W_out, b_out, p_logits, Uc, Vc);
        pred_softmax_kernel<<<Bc, 256>>>(b_out, out_pred, t);
    }
}

// round 2
// speedup vs baseline: 1.2045x; 1.2045x over previous
#include <cuda_runtime.h>
#include <math.h>

// Problem dims
#define Bc   64
#define Pc   196
#define Sc   22
#define Tc   21
#define Vc   10000
#define Ec   512
#define Ac   512
#define Uc   512
#define ENCc 2048
#define KXH  3072   // E + ENC + U
#define N4U  2048   // 4*U
#define CBN  2560   // A + ENC (att2 | beta combined)

// ---------------- scratch (static __device__ arrays; no allocation) -------------
__device__ float g_enc[Bc * Pc * ENCc];      // sorted encoder output  (102.8 MB)
__device__ float g_att1[Bc * Pc * Ac];       // enc @ W_att_enc + b    (25.7 MB)
__device__ float g_Wxh[KXH * N4U];           // concat(W_x, W_h)       (25.2 MB)
__device__ float g_Wcb[Uc * CBN];            // concat(W_att_gen, W_beta) (5.2 MB)
__device__ float g_mean[Bc * ENCc];
__device__ float g_h[Bc * Uc];
__device__ float g_c[Bc * Uc];
__device__ float g_alpha[Bc * Pc];
__device__ float g_xh[Bc * KXH];             // [emb_t | awe*beta | h]
__device__ float g_zpart[8 * Bc * N4U];      // split-K partials for z (also reused for h0/c0)
__device__ float g_cbpart[4 * Bc * CBN];     // split-K partials for att2|beta
__device__ float g_lgpart[2 * Bc * Vc];      // split-K partials for logits
__device__ float g_embAll[Tc * Bc * Ec];     // precomputed embeddings for all steps
__device__ int   g_order[Bc];
__device__ int   g_ilen[Bc];
__device__ int   g_seqs[Bc * Sc];

// ---------------- sort: stable argsort(-lens) ------------------------------------
__global__ void sort_kernel(const int* __restrict__ lens,
                            const int* __restrict__ seqs,
                            float* __restrict__ out_seqs,
                            float* __restrict__ out_ilen,
                            float* __restrict__ out_order) {
    int tid = threadIdx.x;  // 64 threads
    __shared__ int s_len[Bc];
    s_len[tid] = lens[tid];
    __syncthreads();
    int myL = s_len[tid];
    int rank = 0;
    for (int j = 0; j < Bc; j++) {
        int lj = s_len[j];
        rank += (lj > myL) || (lj == myL && j < tid);
    }
    g_order[rank] = tid;
    __syncthreads();
    int src = g_order[tid];
    int il = s_len[src] - 1;
    g_ilen[tid] = il;
    out_ilen[tid] = (float)il;
    out_order[tid] = (float)src;
    for (int s = 0; s < Sc; s++) {
        int v = seqs[src * Sc + s];
        g_seqs[tid * Sc + s] = v;
        out_seqs[tid * Sc + s] = (float)v;
    }
}

// ---------------- permute encoder rows into sorted order ------------------------
__global__ void permute_kernel(const float* __restrict__ enc) {
    int b = blockIdx.x, p = blockIdx.y;
    int src = g_order[b];
    const float4* s = (const float4*)&enc[((size_t)src * Pc + p) * ENCc];
    float4* d = (float4*)&g_enc[((size_t)b * Pc + p) * ENCc];
    for (int i = threadIdx.x; i < ENCc / 4; i += 256) d[i] = s[i];
}

// ---------------- build concat weights -------------------------------------------
__global__ void wxh_kernel(const float* __restrict__ Wx, const float* __restrict__ Wh) {
    size_t idx = (size_t)blockIdx.x * 256 + threadIdx.x;
    if (idx >= (size_t)KXH * N4U) return;
    int k = (int)(idx / N4U), n = (int)(idx % N4U);
    g_Wxh[idx] = (k < Ec + ENCc) ? Wx[idx] : Wh[(size_t)(k - (Ec + ENCc)) * N4U + n];
}
__global__ void wcb_kernel(const float* __restrict__ Wag, const float* __restrict__ Wbeta) {
    size_t idx = (size_t)blockIdx.x * 256 + threadIdx.x;
    if (idx >= (size_t)Uc * CBN) return;
    int k = (int)(idx / CBN), n = (int)(idx % CBN);
    g_Wcb[idx] = (n < Ac) ? Wag[(size_t)k * Ac + n] : Wbeta[(size_t)k * ENCc + (n - Ac)];
}

// ---------------- precompute embeddings for all timesteps ------------------------
__global__ void emb_all_kernel(const float* __restrict__ emb_table) {
    int b = blockIdx.x, t = blockIdx.y;  // 128 threads, float4
    int tok = g_seqs[b * Sc + t];
    float4 v = ((const float4*)(emb_table + (size_t)tok * Ec))[threadIdx.x];
    ((float4*)(g_embAll + ((size_t)t * Bc + b) * Ec))[threadIdx.x] = v;
}

// ---------------- mean over pixels (vectorized) -----------------------------------
__global__ void mean_kernel() {
    int b = blockIdx.x;
    int e0 = blockIdx.y * 1024 + threadIdx.x * 4;
    const float4* encb = (const float4*)(g_enc + (size_t)b * Pc * ENCc + e0);
    const int str = ENCc / 4;
    float4 a0 = {0,0,0,0}, a1 = {0,0,0,0}, a2 = {0,0,0,0}, a3 = {0,0,0,0};
#pragma unroll 2
    for (int p = 0; p < Pc; p += 4) {
        float4 v0 = encb[(size_t)(p + 0) * str];
        float4 v1 = encb[(size_t)(p + 1) * str];
        float4 v2 = encb[(size_t)(p + 2) * str];
        float4 v3 = encb[(size_t)(p + 3) * str];
        a0.x += v0.x; a0.y += v0.y; a0.z += v0.z; a0.w += v0.w;
        a1.x += v1.x; a1.y += v1.y; a1.z += v1.z; a1.w += v1.w;
        a2.x += v2.x; a2.y += v2.y; a2.z += v2.z; a2.w += v2.w;
        a3.x += v3.x; a3.y += v3.y; a3.z += v3.z; a3.w += v3.w;
    }
    float4 r;
    r.x = (a0.x + a1.x + a2.x + a3.x) * (1.0f / Pc);
    r.y = (a0.y + a1.y + a2.y + a3.y) * (1.0f / Pc);
    r.z = (a0.z + a1.z + a2.z + a3.z) * (1.0f / Pc);
    r.w = (a0.w + a1.w + a2.w + a3.w) * (1.0f / Pc);
    *(float4*)(g_mean + (size_t)b * ENCc + e0) = r;
}

// ---------------- GEMM: out[64*My tiles, N] = A[.,K] @ W[K,N] ---------------------
// 64x64 tile, 256 threads, 4x4 per thread, float4 smem loads, k-chunk 16.
// grid = (ceil(N/64), Mtiles, ksplit). ksplit>1: each z-slice writes its own
// partial buffer at out + z*part_stride (no atomics). ksplit==1: store + bias.
__global__ __launch_bounds__(256) void gemm_k(
    const float* __restrict__ A, int lda,
    const float* __restrict__ W,
    const float* __restrict__ bias,
    float* __restrict__ out,
    int K, int N, size_t part_stride) {
    __shared__ float As[16][68];
    __shared__ float Ws[16][68];
    const int tid = threadIdx.x;
    const int tx = tid & 15, ty = tid >> 4;
    const int n0 = blockIdx.x * 64;
    const int kchunk = K / gridDim.z;
    const int kbeg = blockIdx.z * kchunk;
    const float* Ab = A + (size_t)blockIdx.y * 64 * lda;
    float* ob = out + (size_t)blockIdx.y * 64 * N + (size_t)blockIdx.z * part_stride;

    const int lm = tid >> 2;            // A row 0..63
    const int lq = (tid & 3) << 2;      // A k-offset {0,4,8,12}
    const int wk = tid >> 4;            // W k-row 0..15
    const int wn = (tid & 15) << 2;     // W col offset
    const bool wok4 = (n0 + wn + 3 < N);

    float acc[4][4] = {};

    for (int k0 = kbeg; k0 < kbeg + kchunk; k0 += 16) {
        float4 av = *(const float4*)(Ab + (size_t)lm * lda + k0 + lq);
        float4 wv;
        const float* wp = W + (size_t)(k0 + wk) * N + n0 + wn;
        if (wok4) {
            wv = *(const float4*)wp;
        } else {
            wv.x = (n0 + wn + 0 < N) ? wp[0] : 0.f;
            wv.y = (n0 + wn + 1 < N) ? wp[1] : 0.f;
            wv.z = (n0 + wn + 2 < N) ? wp[2] : 0.f;
            wv.w = 0.f;
        }
        __syncthreads();
        As[lq + 0][lm] = av.x; As[lq + 1][lm] = av.y;
        As[lq + 2][lm] = av.z; As[lq + 3][lm] = av.w;
        *(float4*)&Ws[wk][wn] = wv;
        __syncthreads();
#pragma unroll
        for (int kk = 0; kk < 16; kk++) {
            float4 a = *(const float4*)&As[kk][ty << 2];
            float4 w = *(const float4*)&Ws[kk][tx << 2];
            acc[0][0] = fmaf(a.x, w.x, acc[0][0]); acc[0][1] = fmaf(a.x, w.y, acc[0][1]);
            acc[0][2] = fmaf(a.x, w.z, acc[0][2]); acc[0][3] = fmaf(a.x, w.w, acc[0][3]);
            acc[1][0] = fmaf(a.y, w.x, acc[1][0]); acc[1][1] = fmaf(a.y, w.y, acc[1][1]);
            acc[1][2] = fmaf(a.y, w.z, acc[1][2]); acc[1][3] = fmaf(a.y, w.w, acc[1][3]);
            acc[2][0] = fmaf(a.z, w.x, acc[2][0]); acc[2][1] = fmaf(a.z, w.y, acc[2][1]);
            acc[2][2] = fmaf(a.z, w.z, acc[2][2]); acc[2][3] = fmaf(a.z, w.w, acc[2][3]);
            acc[3][0] = fmaf(a.w, w.x, acc[3][0]); acc[3][1] = fmaf(a.w, w.y, acc[3][1]);
            acc[3][2] = fmaf(a.w, w.z, acc[3][2]); acc[3][3] = fmaf(a.w, w.w, acc[3][3]);
        }
    }

    const int c0 = n0 + (tx << 2);
    if (gridDim.z == 1) {
        float4 bv;
        if (c0 + 3 < N) bv = *(const float4*)&bias[c0];
        else {
            bv.x = (c0 + 0 < N) ? bias[c0 + 0] : 0.f;
            bv.y = (c0 + 1 < N) ? bias[c0 + 1] : 0.f;
            bv.z = (c0 + 2 < N) ? bias[c0 + 2] : 0.f;
            bv.w = 0.f;
        }
#pragma unroll
        for (int i = 0; i < 4; i++) {
            int r = (ty << 2) + i;
            float4 o;
            o.x = acc[i][0] + bv.x; o.y = acc[i][1] + bv.y;
            o.z = acc[i][2] + bv.z; o.w = acc[i][3] + bv.w;
            if (c0 + 3 < N) *(float4*)&ob[(size_t)r * N + c0] = o;
            else {
                if (c0 + 0 < N) ob[(size_t)r * N + c0 + 0] = o.x;
                if (c0 + 1 < N) ob[(size_t)r * N + c0 + 1] = o.y;
                if (c0 + 2 < N) ob[(size_t)r * N + c0 + 2] = o.z;
            }
        }
    } else {
#pragma unroll
        for (int i = 0; i < 4; i++) {
            int r = (ty << 2) + i;
            float4 o;
            o.x = acc[i][0]; o.y = acc[i][1]; o.z = acc[i][2]; o.w = acc[i][3];
            if (c0 + 3 < N) *(float4*)&ob[(size_t)r * N + c0] = o;
            else {
                if (c0 + 0 < N) ob[(size_t)r * N + c0 + 0] = o.x;
                if (c0 + 1 < N) ob[(size_t)r * N + c0 + 1] = o.y;
                if (c0 + 2 < N) ob[(size_t)r * N + c0 + 2] = o.z;
            }
        }
    }
}

// ---------------- init h0/c0 from split-K partials + bias, seed xh h-slot ---------
__global__ void init_hc_kernel(const float* __restrict__ bm, const float* __restrict__ bc) {
    int b = blockIdx.x, n = threadIdx.x;  // 512
    float h = bm[n], c = bc[n];
#pragma unroll
    for (int s = 0; s < 8; s++) {
        h += g_zpart[((size_t)s * Bc + b) * Uc + n];
        c += g_zpart[((size_t)(8 + s) * Bc + b) * Uc + n];
    }
    g_h[b * Uc + n] = h;
    g_c[b * Uc + n] = c;
    g_xh[(size_t)b * KXH + Ec + ENCc + n] = h;
}

// ---------------- attention scores + softmax over pixels --------------------------
__global__ void attn_kernel(const float* __restrict__ bgen,
                            const float* __restrict__ wf,
                            const float* __restrict__ bf,
                            float* __restrict__ out_alpha, int t) {
    int b = blockIdx.x;
    __shared__ float s_att2[Ac];
    __shared__ float s_wf[Ac];
    __shared__ float s_e[Pc];
    __shared__ float s_red[32];
    int tid = threadIdx.x;  // 512
    {
        float v = bgen[tid];
#pragma unroll
        for (int s = 0; s < 4; s++) v += g_cbpart[((size_t)s * Bc + b) * CBN + tid];
        s_att2[tid] = v;
        s_wf[tid] = wf[tid];
    }
    __syncthreads();
    int warp = tid >> 5, lane = tid & 31;
    const float* att1b = g_att1 + (size_t)b * Pc * Ac;
    float bfull = bf[0];
    for (int p = warp; p < Pc; p += 16) {
        const float4* row = (const float4*)(att1b + (size_t)p * Ac);
        float s = 0.f;
#pragma unroll
        for (int i = 0; i < 4; i++) {
            int a = lane + i * 32;  // float4 index within 128
            float4 v = row[a];
            float4 t2 = *(const float4*)&s_att2[a * 4];
            float4 wv = *(const float4*)&s_wf[a * 4];
            float x;
            x = v.x + t2.x; if (x > 0.f) s = fmaf(x, wv.x, s);
            x = v.y + t2.y; if (x > 0.f) s = fmaf(x, wv.y, s);
            x = v.z + t2.z; if (x > 0.f) s = fmaf(x, wv.z, s);
            x = v.w + t2.w; if (x > 0.f) s = fmaf(x, wv.w, s);
        }
#pragma unroll
        for (int o = 16; o; o >>= 1) s += __shfl_xor_sync(0xffffffff, s, o);
        if (lane == 0) s_e[p] = s + bfull;
    }
    __syncthreads();
    // softmax over 196 values, one per thread (tid<196)
    float e = (tid < Pc) ? s_e[tid] : -1e30f;
    float m = e;
#pragma unroll
    for (int o = 16; o; o >>= 1) m = fmaxf(m, __shfl_xor_sync(0xffffffff, m, o));
    if (lane == 0) s_red[warp] = m;
    __syncthreads();
    if (tid < 32) {
        float v = (tid < 16) ? s_red[tid] : -1e30f;
#pragma unroll
        for (int o = 8; o; o >>= 1) v = fmaxf(v, __shfl_xor_sync(0xffffffff, v, o));
        if (tid == 0) s_red[0] = v;
    }
    __syncthreads();
    m = s_red[0];
    float ex = (tid < Pc) ? expf(e - m) : 0.f;
    float sm = ex;
#pragma unroll
    for (int o = 16; o; o >>= 1) sm += __shfl_xor_sync(0xffffffff, sm, o);
    if (lane == 0) s_red[16 + warp] = sm;
    __syncthreads();
    if (tid < 32) {
        float v = (tid < 16) ? s_red[16 + tid] : 0.f;
#pragma unroll
        for (int o = 8; o; o >>= 1) v += __shfl_xor_sync(0xffffffff, v, o);
        if (tid == 0) s_red[16] = v;
    }
    __syncthreads();
    float inv = 1.0f / s_red[16];
    if (tid < Pc) {
        float al = ex * inv;
        g_alpha[b * Pc + tid] = al;
        bool mask = t < g_ilen[b];
        out_alpha[((size_t)b * Tc + t) * Pc + tid] = mask ? al : 0.f;
    }
}

// ---------------- awe = (alpha . enc) * sigmoid(beta) -> xh; also copy emb --------
__global__ void awe_kernel(const float* __restrict__ bbeta, int t) {
    int b = blockIdx.x;  // grid (Bc, 2), 256 threads
    __shared__ float s_al[Pc];
    int tid = threadIdx.x;
    if (tid < Pc) s_al[tid] = g_alpha[b * Pc + tid];
    __syncthreads();
    int e0 = blockIdx.y * 1024 + tid * 4;
    const float4* encb = (const float4*)(g_enc + (size_t)b * Pc * ENCc + e0);
    const int str = ENCc / 4;
    float4 a0 = {0,0,0,0}, a1 = {0,0,0,0}, a2 = {0,0,0,0}, a3 = {0,0,0,0};
#pragma unroll 2
    for (int p = 0; p < Pc; p += 4) {
        float l0 = s_al[p + 0], l1 = s_al[p + 1], l2 = s_al[p + 2], l3 = s_al[p + 3];
        float4 v0 = encb[(size_t)(p + 0) * str];
        float4 v1 = encb[(size_t)(p + 1) * str];
        float4 v2 = encb[(size_t)(p + 2) * str];
        float4 v3 = encb[(size_t)(p + 3) * str];
        a0.x = fmaf(l0, v0.x, a0.x); a0.y = fmaf(l0, v0.y, a0.y);
        a0.z = fmaf(l0, v0.z, a0.z); a0.w = fmaf(l0, v0.w, a0.w);
        a1.x = fmaf(l1, v1.x, a1.x); a1.y = fmaf(l1, v1.y, a1.y);
        a1.z = fmaf(l1, v1.z, a1.z); a1.w = fmaf(l1, v1.w, a1.w);
        a2.x = fmaf(l2, v2.x, a2.x); a2.y = fmaf(l2, v2.y, a2.y);
        a2.z = fmaf(l2, v2.z, a2.z); a2.w = fmaf(l2, v2.w, a2.w);
        a3.x = fmaf(l3, v3.x, a3.x); a3.y = fmaf(l3, v3.y, a3.y);
        a3.z = fmaf(l3, v3.z, a3.z); a3.w = fmaf(l3, v3.w, a3.w);
    }
    float4 s;
    s.x = a0.x + a1.x + a2.x + a3.x;
    s.y = a0.y + a1.y + a2.y + a3.y;
    s.z = a0.z + a1.z + a2.z + a3.z;
    s.w = a0.w + a1.w + a2.w + a3.w;
    // beta logits = sum of 4 cb partials (cols 512..2559) + bias, then sigmoid
    float4 bl = *(const float4*)&bbeta[e0];
#pragma unroll
    for (int sp = 0; sp < 4; sp++) {
        float4 pv = *(const float4*)&g_cbpart[((size_t)sp * Bc + b) * CBN + Ac + e0];
        bl.x += pv.x; bl.y += pv.y; bl.z += pv.z; bl.w += pv.w;
    }
    float4 o;
    o.x = s.x / (1.0f + expf(-bl.x));
    o.y = s.y / (1.0f + expf(-bl.y));
    o.z = s.z / (1.0f + expf(-bl.z));
    o.w = s.w / (1.0f + expf(-bl.w));
    *(float4*)&g_xh[(size_t)b * KXH + Ec + e0] = o;
    if (blockIdx.y == 0) {  // copy this step's embedding into xh[0:512)
        *(float2*)&g_xh[(size_t)b * KXH + tid * 2] =
            *(const float2*)&g_embAll[((size_t)t * Bc + b) * Ec + tid * 2];
    }
}

// ---------------- LSTM gates from split-K partials + masked state update ----------
__global__ void gates_kernel(const float* __restrict__ bl, int t) {
    int b = blockIdx.x, n = threadIdx.x;  // 512
    float zi = bl[n], zf = bl[Uc + n], zg = bl[2 * Uc + n], zo = bl[3 * Uc + n];
#pragma unroll
    for (int s = 0; s < 8; s++) {
        const float* zp = g_zpart + ((size_t)s * Bc + b) * N4U;
        zi += zp[n];
        zf += zp[Uc + n];
        zg += zp[2 * Uc + n];
        zo += zp[3 * Uc + n];
    }
    float c_old = g_c[b * Uc + n], h_old = g_h[b * Uc + n];
    float si = 1.0f / (1.0f + expf(-zi));
    float sf = 1.0f / (1.0f + expf(-zf));
    float so = 1.0f / (1.0f + expf(-zo));
    float c_new = sf * c_old + si * tanhf(zg);
    float h_new = so * tanhf(c_new);
    bool mask = t < g_ilen[b];
    float c2 = mask ? c_new : c_old;
    float h2 = mask ? h_new : h_old;
    g_c[b * Uc + n] = c2;
    g_h[b * Uc + n] = h2;
    g_xh[(size_t)b * KXH + Ec + ENCc + n] = h2;
}

// ---------------- vocab softmax from split-K partials, masked, to output ----------
__global__ void pred_softmax_kernel(const float* __restrict__ bo,
                                    float* __restrict__ out_pred, int t) {
    int b = blockIdx.x, tid = threadIdx.x;  // 256
    float4* dst = (float4*)(out_pred + ((size_t)b * Tc + t) * Vc);
    bool mask = t < g_ilen[b];
    const int NV4 = Vc / 4;  // 2500
    if (!mask) {
        float4 z = {0, 0, 0, 0};
        for (int i = tid; i < NV4; i += 256) dst[i] = z;
        return;
    }
    const float4* l0 = (const float4*)(g_lgpart + (size_t)b * Vc);
    const float4* l1 = (const float4*)(g_lgpart + ((size_t)Bc + b) * Vc);
    const float4* bo4 = (const float4*)bo;
    __shared__ float s_red[16];
    int warp = tid >> 5, lane = tid & 31;
    float m = -1e30f;
    for (int i = tid; i < NV4; i += 256) {
        float4 a = l0[i], c = l1[i], bb = bo4[i];
        float4 v;
        v.x = a.x + c.x + bb.x; v.y = a.y + c.y + bb.y;
        v.z = a.z + c.z + bb.z; v.w = a.w + c.w + bb.w;
        dst[i] = v;
        m = fmaxf(m, fmaxf(fmaxf(v.x, v.y), fmaxf(v.z, v.w)));
    }
#pragma unroll
    for (int o = 16; o; o >>= 1) m = fmaxf(m, __shfl_xor_sync(0xffffffff, m, o));
    if (lane == 0) s_red[warp] = m;
    __syncthreads();
    m = s_red[0];
#pragma unroll
    for (int w = 1; w < 8; w++) m = fmaxf(m, s_red[w]);
    float sum = 0.f;
    for (int i = tid; i < NV4; i += 256) {
        float4 v = dst[i];
        v.x = expf(v.x - m); v.y = expf(v.y - m);
        v.z = expf(v.z - m); v.w = expf(v.w - m);
        dst[i] = v;
        sum += v.x + v.y + v.z + v.w;
    }
#pragma unroll
    for (int o = 16; o; o >>= 1) sum += __shfl_xor_sync(0xffffffff, sum, o);
    __syncthreads();
    if (lane == 0) s_red[warp] = sum;
    __syncthreads();
    sum = 0.f;
#pragma unroll
    for (int w = 0; w < 8; w++) sum += s_red[w];
    float inv = 1.0f / sum;
    for (int i = tid; i < NV4; i += 256) {
        float4 v = dst[i];
        v.x *= inv; v.y *= inv; v.z *= inv; v.w *= inv;
        dst[i] = v;
    }
}

// ---------------- launcher ---------------------------------------------------------
extern "C" void kernel_launch(void* const* d_in, const int* in_sizes, int n_in,
                              void* d_out, int out_size) {
    const float* enc      = (const float*)d_in[0];
    const int*   seqs     = (const int*)  d_in[1];
    const int*   lens     = (const int*)  d_in[2];
    const float* emb_tab  = (const float*)d_in[3];
    const float* W_ae     = (const float*)d_in[4];
    const float* b_ae     = (const float*)d_in[5];
    const float* W_ag     = (const float*)d_in[6];
    const float* b_ag     = (const float*)d_in[7];
    const float* W_af     = (const float*)d_in[8];
    const float* b_af     = (const float*)d_in[9];
    const float* W_x      = (const float*)d_in[10];
    const float* W_h      = (const float*)d_in[11];
    const float* b_lstm   = (const float*)d_in[12];
    const float* W_im     = (const float*)d_in[13];
    const float* b_im     = (const float*)d_in[14];
    const float* W_ic     = (const float*)d_in[15];
    const float* b_ic     = (const float*)d_in[16];
    const float* W_beta   = (const float*)d_in[17];
    const float* b_beta   = (const float*)d_in[18];
    const float* W_out    = (const float*)d_in[19];
    const float* b_out    = (const float*)d_in[20];

    float* out       = (float*)d_out;
    float* out_pred  = out;                                   // [B,T,V]
    float* out_alpha = out_pred + (size_t)Bc * Tc * Vc;       // [B,T,P]
    float* out_seqs  = out_alpha + (size_t)Bc * Tc * Pc;      // [B,S]
    float* out_ilen  = out_seqs + (size_t)Bc * Sc;            // [B]
    float* out_order = out_ilen + Bc;                         // [B]

    float *p_enc, *p_att1, *p_Wxh, *p_Wcb, *p_mean, *p_c, *p_xh, *p_zpart, *p_cbpart, *p_lgpart;
    cudaGetSymbolAddress((void**)&p_enc, g_enc);
    cudaGetSymbolAddress((void**)&p_att1, g_att1);
    cudaGetSymbolAddress((void**)&p_Wxh, g_Wxh);
    cudaGetSymbolAddress((void**)&p_Wcb, g_Wcb);
    cudaGetSymbolAddress((void**)&p_mean, g_mean);
    cudaGetSymbolAddress((void**)&p_c, g_c);
    cudaGetSymbolAddress((void**)&p_xh, g_xh);
    cudaGetSymbolAddress((void**)&p_zpart, g_zpart);
    cudaGetSymbolAddress((void**)&p_cbpart, g_cbpart);
    cudaGetSymbolAddress((void**)&p_lgpart, g_lgpart);

    // ---- setup ----
    sort_kernel<<<1, Bc>>>(lens, seqs, out_seqs, out_ilen, out_order);
    permute_kernel<<<dim3(Bc, Pc), 256>>>(enc);
    wxh_kernel<<<(int)(((size_t)KXH * N4U + 255) / 256), 256>>>(W_x, W_h);
    wcb_kernel<<<(int)(((size_t)Uc * CBN + 255) / 256), 256>>>(W_ag, W_beta);
    emb_all_kernel<<<dim3(Bc, Tc), 128>>>(emb_tab);
    mean_kernel<<<dim3(Bc, 2), 256>>>();
    // h0/c0 partials into g_zpart[0..7] and g_zpart[8..15] (K=2048, ksplit=8)
    gemm_k<<<dim3(Uc / 64, 1, 8), 256>>>(p_mean, ENCc, W_im, nullptr, p_zpart, ENCc, Uc, (size_t)Bc * Uc);
    gemm_k<<<dim3(Uc / 64, 1, 8), 256>>>(p_mean, ENCc, W_ic, nullptr, p_zpart + (size_t)8 * Bc * Uc, ENCc, Uc, (size_t)Bc * Uc);
    init_hc_kernel<<<Bc, Uc>>>(b_im, b_ic);
    // att1 = enc_sorted @ W_att_enc + b  (12544 x 512, K=2048)
    gemm_k<<<dim3(Ac / 64, (Bc * Pc) / 64, 1), 256>>>(p_enc, ENCc, W_ae, b_ae, p_att1, ENCc, Ac, 0);

    // ---- time steps ----
    for (int t = 0; t < Tc; t++) {
        // [att2 | beta] = c @ [W_att_gen | W_beta]   (K=512, ksplit=4)
        gemm_k<<<dim3(CBN / 64, 1, 4), 256>>>(p_c, Uc, p_Wcb, nullptr, p_cbpart, Uc, CBN, (size_t)Bc * CBN);
        attn_kernel<<<Bc, 512>>>(b_ag, W_af, b_af, out_alpha, t);
        awe_kernel<<<dim3(Bc, 2), 256>>>(b_beta, t);
        // z = xh @ Wxh  (K=3072, ksplit=8)
        gemm_k<<<dim3(N4U / 64, 1, 8), 256>>>(p_xh, KXH, p_Wxh, nullptr, p_zpart, KXH, N4U, (size_t)Bc * N4U);
        gates_kernel<<<Bc, Uc>>>(b_lstm, t);
        // logits = c2 @ W_out  (K=512, ksplit=2)
        gemm_k<<<dim3((Vc + 63) / 64, 1, 2), 256>>>(p_c, Uc, W_out, nullptr, p_lgpart, Uc, Vc, (size_t)Bc * Vc);
        pred_softmax_kernel<<<Bc, 256>>>(b_out, out_pred, t);
    }
}

// round 3
// speedup vs baseline: 1.2889x; 1.0701x over previous
#include <cuda_runtime.h>
#include <math.h>
#include <stdint.h>

// Problem dims
#define Bc   64
#define Pc   196
#define Sc   22
#define Tc   21
#define Vc   10000
#define Ec   512
#define Ac   512
#define Uc   512
#define ENCc 2048
#define KXH  3072   // E + ENC + U
#define N4U  2048   // 4*U
#define CBN  2560   // A + ENC (att2 | beta combined)

// ---------------- scratch (static __device__ arrays; no allocation) -------------
__device__ float g_enc[Bc * Pc * ENCc];      // sorted encoder output  (102.8 MB)
__device__ float g_att1[Bc * Pc * Ac];       // enc @ W_att_enc + b    (25.7 MB)
__device__ float g_Wxh[KXH * N4U];           // concat(W_x, W_h)       (25.2 MB)
__device__ float g_Wcb[Uc * CBN];            // concat(W_att_gen, W_beta) (5.2 MB)
__device__ float g_mean[Bc * ENCc];
__device__ float g_h[Bc * Uc];
__device__ float g_c[Bc * Uc];
__device__ float g_xh[Bc * KXH];             // [emb_t | awe*beta | h]
__device__ float g_zpart[8 * Bc * N4U];      // split-K partials for z (reused for h0/c0)
__device__ float g_cbpart[4 * Bc * CBN];     // split-K partials for att2|beta
__device__ float g_logits[Bc * Vc];          // logits (bias included)
__device__ float g_embAll[Tc * Bc * Ec];     // precomputed embeddings for all steps
__device__ int   g_order[Bc];
__device__ int   g_ilen[Bc];
__device__ int   g_seqs[Bc * Sc];

// ---------------- sort: stable argsort(-lens) ------------------------------------
__global__ void sort_kernel(const int* __restrict__ lens,
                            const int* __restrict__ seqs,
                            float* __restrict__ out_seqs,
                            float* __restrict__ out_ilen,
                            float* __restrict__ out_order) {
    int tid = threadIdx.x;  // 64 threads
    __shared__ int s_len[Bc];
    s_len[tid] = lens[tid];
    __syncthreads();
    int myL = s_len[tid];
    int rank = 0;
    for (int j = 0; j < Bc; j++) {
        int lj = s_len[j];
        rank += (lj > myL) || (lj == myL && j < tid);
    }
    g_order[rank] = tid;
    __syncthreads();
    int src = g_order[tid];
    int il = s_len[src] - 1;
    g_ilen[tid] = il;
    out_ilen[tid] = (float)il;
    out_order[tid] = (float)src;
    for (int s = 0; s < Sc; s++) {
        int v = seqs[src * Sc + s];
        g_seqs[tid * Sc + s] = v;
        out_seqs[tid * Sc + s] = (float)v;
    }
}

// ---------------- permute encoder rows into sorted order ------------------------
__global__ void permute_kernel(const float* __restrict__ enc) {
    int b = blockIdx.x, p = blockIdx.y;
    int src = g_order[b];
    const float4* s = (const float4*)&enc[((size_t)src * Pc + p) * ENCc];
    float4* d = (float4*)&g_enc[((size_t)b * Pc + p) * ENCc];
    for (int i = threadIdx.x; i < ENCc / 4; i += 256) d[i] = s[i];
}

// ---------------- build concat weights -------------------------------------------
__global__ void wxh_kernel(const float* __restrict__ Wx, const float* __restrict__ Wh) {
    size_t idx = (size_t)blockIdx.x * 256 + threadIdx.x;
    if (idx >= (size_t)KXH * N4U) return;
    int k = (int)(idx / N4U), n = (int)(idx % N4U);
    g_Wxh[idx] = (k < Ec + ENCc) ? Wx[idx] : Wh[(size_t)(k - (Ec + ENCc)) * N4U + n];
}
__global__ void wcb_kernel(const float* __restrict__ Wag, const float* __restrict__ Wbeta) {
    size_t idx = (size_t)blockIdx.x * 256 + threadIdx.x;
    if (idx >= (size_t)Uc * CBN) return;
    int k = (int)(idx / CBN), n = (int)(idx % CBN);
    g_Wcb[idx] = (n < Ac) ? Wag[(size_t)k * Ac + n] : Wbeta[(size_t)k * ENCc + (n - Ac)];
}

// ---------------- precompute embeddings for all timesteps ------------------------
__global__ void emb_all_kernel(const float* __restrict__ emb_table) {
    int b = blockIdx.x, t = blockIdx.y;  // 128 threads, float4
    int tok = g_seqs[b * Sc + t];
    float4 v = ((const float4*)(emb_table + (size_t)tok * Ec))[threadIdx.x];
    ((float4*)(g_embAll + ((size_t)t * Bc + b) * Ec))[threadIdx.x] = v;
}

// ---------------- mean over pixels (vectorized) -----------------------------------
__global__ void mean_kernel() {
    int b = blockIdx.x;
    int e0 = blockIdx.y * 1024 + threadIdx.x * 4;
    const float4* encb = (const float4*)(g_enc + (size_t)b * Pc * ENCc + e0);
    const int str = ENCc / 4;
    float4 a0 = {0,0,0,0}, a1 = {0,0,0,0}, a2 = {0,0,0,0}, a3 = {0,0,0,0};
#pragma unroll 2
    for (int p = 0; p < Pc; p += 4) {
        float4 v0 = encb[(size_t)(p + 0) * str];
        float4 v1 = encb[(size_t)(p + 1) * str];
        float4 v2 = encb[(size_t)(p + 2) * str];
        float4 v3 = encb[(size_t)(p + 3) * str];
        a0.x += v0.x; a0.y += v0.y; a0.z += v0.z; a0.w += v0.w;
        a1.x += v1.x; a1.y += v1.y; a1.z += v1.z; a1.w += v1.w;
        a2.x += v2.x; a2.y += v2.y; a2.z += v2.z; a2.w += v2.w;
        a3.x += v3.x; a3.y += v3.y; a3.z += v3.z; a3.w += v3.w;
    }
    float4 r;
    r.x = (a0.x + a1.x + a2.x + a3.x) * (1.0f / Pc);
    r.y = (a0.y + a1.y + a2.y + a3.y) * (1.0f / Pc);
    r.z = (a0.z + a1.z + a2.z + a3.z) * (1.0f / Pc);
    r.w = (a0.w + a1.w + a2.w + a3.w) * (1.0f / Pc);
    *(float4*)(g_mean + (size_t)b * ENCc + e0) = r;
}

// ---------------- TF32 tensor-core GEMM ------------------------------------------
__device__ __forceinline__ float to_tf32(float x) {
    uint32_t r;
    asm("cvt.rna.tf32.f32 %0, %1;" : "=r"(r) : "f"(x));
    return __uint_as_float(r);
}
__device__ __forceinline__ void mma_tf32(float* c, const uint32_t* a, const uint32_t* b) {
    asm volatile(
        "mma.sync.aligned.m16n8k8.row.col.f32.tf32.tf32.f32 "
        "{%0,%1,%2,%3}, {%4,%5,%6,%7}, {%8,%9}, {%0,%1,%2,%3};"
        : "+f"(c[0]), "+f"(c[1]), "+f"(c[2]), "+f"(c[3])
        : "r"(a[0]), "r"(a[1]), "r"(a[2]), "r"(a[3]), "r"(b[0]), "r"(b[1]));
}

// C[M,N] = A[M,K] @ W[K,N] + bias.  BM in {64,128}, BN=64. THREADS = (BM/32)*(BN/32)*32.
// Warp tile 32x32 (m16n8k8: 2 M-frags x 4 N-frags x 4 k-steps per k32).
template <int BM, int THREADS>
__global__ __launch_bounds__(256) void tf32_gemm(
    const float* __restrict__ A, const float* __restrict__ W,
    const float* __restrict__ bias, float* __restrict__ C,
    int K, int N) {
    __shared__ float As[BM][36];
    __shared__ float Ws[32][72];
    const int tid = threadIdx.x;
    const int warp = tid >> 5, lane = tid & 31;
    const int WGM = BM / 32;              // warps along M
    const int wm = (warp % WGM) << 5;
    const int wn = (warp / WGM) << 5;
    const int m0 = blockIdx.y * BM;
    const int n0 = blockIdx.x * 64;
    const float* Ab = A + (size_t)m0 * K;

    float acc[2][4][4];
#pragma unroll
    for (int i = 0; i < 2; i++)
#pragma unroll
        for (int j = 0; j < 4; j++)
#pragma unroll
            for (int q = 0; q < 4; q++) acc[i][j][q] = 0.f;

    for (int k0 = 0; k0 < K; k0 += 32) {
        __syncthreads();
        // load A tile BM x 32
#pragma unroll
        for (int j = 0; j < (BM * 8) / THREADS; j++) {
            int idx = tid + j * THREADS;
            int r = idx >> 3, kq = (idx & 7) << 2;
            float4 v = *(const float4*)(Ab + (size_t)r * K + k0 + kq);
            float4 cv;
            cv.x = to_tf32(v.x); cv.y = to_tf32(v.y);
            cv.z = to_tf32(v.z); cv.w = to_tf32(v.w);
            *(float4*)&As[r][kq] = cv;
        }
        // load W tile 32 x 64 (guard N)
#pragma unroll
        for (int j = 0; j < 512 / THREADS; j++) {
            int idx = tid + j * THREADS;
            int kr = idx >> 4, nq = (idx & 15) << 2;
            const float* wp = W + (size_t)(k0 + kr) * N + n0 + nq;
            float4 v;
            if (n0 + nq + 3 < N) v = *(const float4*)wp;
            else {
                v.x = (n0 + nq + 0 < N) ? wp[0] : 0.f;
                v.y = (n0 + nq + 1 < N) ? wp[1] : 0.f;
                v.z = (n0 + nq + 2 < N) ? wp[2] : 0.f;
                v.w = (n0 + nq + 3 < N) ? wp[3] : 0.f;
            }
            float4 cv;
            cv.x = to_tf32(v.x); cv.y = to_tf32(v.y);
            cv.z = to_tf32(v.z); cv.w = to_tf32(v.w);
            *(float4*)&Ws[kr][nq] = cv;
        }
        __syncthreads();
#pragma unroll
        for (int ks = 0; ks < 32; ks += 8) {
            uint32_t af[2][4];
            const int r = lane >> 2, c = ks + (lane & 3);
#pragma unroll
            for (int mi = 0; mi < 2; mi++) {
                int rr = wm + mi * 16 + r;
                af[mi][0] = __float_as_uint(As[rr][c]);
                af[mi][1] = __float_as_uint(As[rr + 8][c]);
                af[mi][2] = __float_as_uint(As[rr][c + 4]);
                af[mi][3] = __float_as_uint(As[rr + 8][c + 4]);
            }
            uint32_t bfr[4][2];
            const int bk = ks + (lane & 3), bn = lane >> 2;
#pragma unroll
            for (int nj = 0; nj < 4; nj++) {
                bfr[nj][0] = __float_as_uint(Ws[bk][wn + nj * 8 + bn]);
                bfr[nj][1] = __float_as_uint(Ws[bk + 4][wn + nj * 8 + bn]);
            }
#pragma unroll
            for (int mi = 0; mi < 2; mi++)
#pragma unroll
                for (int nj = 0; nj < 4; nj++)
                    mma_tf32(acc[mi][nj], af[mi], bfr[nj]);
        }
    }
    // epilogue
    const int r = lane >> 2, cc = (lane & 3) << 1;
#pragma unroll
    for (int mi = 0; mi < 2; mi++) {
#pragma unroll
        for (int nj = 0; nj < 4; nj++) {
            int row = m0 + wm + mi * 16 + r;
            int col = n0 + wn + nj * 8 + cc;
            if (col < N) {
                float b0 = bias[col], b1 = bias[col + 1];
                float2 o0 = {acc[mi][nj][0] + b0, acc[mi][nj][1] + b1};
                float2 o1 = {acc[mi][nj][2] + b0, acc[mi][nj][3] + b1};
                *(float2*)&C[(size_t)row * N + col] = o0;
                *(float2*)&C[(size_t)(row + 8) * N + col] = o1;
            }
        }
    }
}

// ---------------- fp32 GEMM (recurrent path): out[64,N] partials ------------------
__global__ __launch_bounds__(256) void gemm_k(
    const float* __restrict__ A, int lda,
    const float* __restrict__ W,
    float* __restrict__ out,
    int K, int N, size_t part_stride) {
    __shared__ float As[16][68];
    __shared__ float Ws[16][68];
    const int tid = threadIdx.x;
    const int tx = tid & 15, ty = tid >> 4;
    const int n0 = blockIdx.x * 64;
    const int kchunk = K / gridDim.z;
    const int kbeg = blockIdx.z * kchunk;
    float* ob = out + (size_t)blockIdx.z * part_stride;

    const int lm = tid >> 2;
    const int lq = (tid & 3) << 2;
    const int wk = tid >> 4;
    const int wn = (tid & 15) << 2;

    float acc[4][4] = {};

    for (int k0 = kbeg; k0 < kbeg + kchunk; k0 += 16) {
        float4 av = *(const float4*)(A + (size_t)lm * lda + k0 + lq);
        float4 wv = *(const float4*)(W + (size_t)(k0 + wk) * N + n0 + wn);
        __syncthreads();
        As[lq + 0][lm] = av.x; As[lq + 1][lm] = av.y;
        As[lq + 2][lm] = av.z; As[lq + 3][lm] = av.w;
        *(float4*)&Ws[wk][wn] = wv;
        __syncthreads();
#pragma unroll
        for (int kk = 0; kk < 16; kk++) {
            float4 a = *(const float4*)&As[kk][ty << 2];
            float4 w = *(const float4*)&Ws[kk][tx << 2];
            acc[0][0] = fmaf(a.x, w.x, acc[0][0]); acc[0][1] = fmaf(a.x, w.y, acc[0][1]);
            acc[0][2] = fmaf(a.x, w.z, acc[0][2]); acc[0][3] = fmaf(a.x, w.w, acc[0][3]);
            acc[1][0] = fmaf(a.y, w.x, acc[1][0]); acc[1][1] = fmaf(a.y, w.y, acc[1][1]);
            acc[1][2] = fmaf(a.y, w.z, acc[1][2]); acc[1][3] = fmaf(a.y, w.w, acc[1][3]);
            acc[2][0] = fmaf(a.z, w.x, acc[2][0]); acc[2][1] = fmaf(a.z, w.y, acc[2][1]);
            acc[2][2] = fmaf(a.z, w.z, acc[2][2]); acc[2][3] = fmaf(a.z, w.w, acc[2][3]);
            acc[3][0] = fmaf(a.w, w.x, acc[3][0]); acc[3][1] = fmaf(a.w, w.y, acc[3][1]);
            acc[3][2] = fmaf(a.w, w.z, acc[3][2]); acc[3][3] = fmaf(a.w, w.w, acc[3][3]);
        }
    }
    const int c0 = n0 + (tx << 2);
#pragma unroll
    for (int i = 0; i < 4; i++) {
        int r = (ty << 2) + i;
        float4 o = {acc[i][0], acc[i][1], acc[i][2], acc[i][3]};
        *(float4*)&ob[(size_t)r * N + c0] = o;
    }
}

// ---------------- init h0/c0 from split-K partials + bias; seed xh ---------------
__global__ void init_hc_kernel(const float* __restrict__ bm, const float* __restrict__ bc) {
    int b = blockIdx.x, n = threadIdx.x;  // 512
    float h = bm[n], c = bc[n];
#pragma unroll
    for (int s = 0; s < 8; s++) {
        h += g_zpart[((size_t)s * Bc + b) * Uc + n];
        c += g_zpart[((size_t)(8 + s) * Bc + b) * Uc + n];
    }
    g_h[b * Uc + n] = h;
    g_c[b * Uc + n] = c;
    g_xh[(size_t)b * KXH + Ec + ENCc + n] = h;
    g_xh[(size_t)b * KXH + n] = g_embAll[(size_t)b * Ec + n];  // emb for t=0
}

// ---------------- fused attention + softmax + awe (with early-exit) --------------
__global__ __launch_bounds__(512) void attn_awe_kernel(
    const float* __restrict__ bgen,
    const float* __restrict__ wf,
    const float* __restrict__ bf,
    const float* __restrict__ bbeta,
    float* __restrict__ out_alpha, int t) {
    int b = blockIdx.x, tid = threadIdx.x;  // 512
    if (t >= g_ilen[b]) {
        if (tid < Pc) out_alpha[((size_t)b * Tc + t) * Pc + tid] = 0.f;
        return;
    }
    __shared__ float s_att2[Ac];
    __shared__ float s_wf[Ac];
    __shared__ float s_e[Pc];
    __shared__ float s_red[32];
    {
        float v = bgen[tid];
#pragma unroll
        for (int s = 0; s < 4; s++) v += g_cbpart[((size_t)s * Bc + b) * CBN + tid];
        s_att2[tid] = v;
        s_wf[tid] = wf[tid];
    }
    __syncthreads();
    int warp = tid >> 5, lane = tid & 31;
    const float* att1b = g_att1 + (size_t)b * Pc * Ac;
    float bfull = bf[0];
    for (int p = warp; p < Pc; p += 16) {
        const float4* row = (const float4*)(att1b + (size_t)p * Ac);
        float s = 0.f;
#pragma unroll
        for (int i = 0; i < 4; i++) {
            int a = lane + i * 32;
            float4 v = row[a];
            float4 t2 = *(const float4*)&s_att2[a * 4];
            float4 wv = *(const float4*)&s_wf[a * 4];
            float x;
            x = v.x + t2.x; if (x > 0.f) s = fmaf(x, wv.x, s);
            x = v.y + t2.y; if (x > 0.f) s = fmaf(x, wv.y, s);
            x = v.z + t2.z; if (x > 0.f) s = fmaf(x, wv.z, s);
            x = v.w + t2.w; if (x > 0.f) s = fmaf(x, wv.w, s);
        }
#pragma unroll
        for (int o = 16; o; o >>= 1) s += __shfl_xor_sync(0xffffffff, s, o);
        if (lane == 0) s_e[p] = s + bfull;
    }
    __syncthreads();
    // softmax over 196 values (one per thread for tid<196)
    float e = (tid < Pc) ? s_e[tid] : -1e30f;
    float m = e;
#pragma unroll
    for (int o = 16; o; o >>= 1) m = fmaxf(m, __shfl_xor_sync(0xffffffff, m, o));
    if (lane == 0) s_red[warp] = m;
    __syncthreads();
    if (tid < 32) {
        float v = (tid < 16) ? s_red[tid] : -1e30f;
#pragma unroll
        for (int o = 8; o; o >>= 1) v = fmaxf(v, __shfl_xor_sync(0xffffffff, v, o));
        if (tid == 0) s_red[0] = v;
    }
    __syncthreads();
    m = s_red[0];
    float ex = (tid < Pc) ? expf(e - m) : 0.f;
    float sm = ex;
#pragma unroll
    for (int o = 16; o; o >>= 1) sm += __shfl_xor_sync(0xffffffff, sm, o);
    __syncthreads();
    if (lane == 0) s_red[warp] = sm;
    __syncthreads();
    if (tid < 32) {
        float v = (tid < 16) ? s_red[tid] : 0.f;
#pragma unroll
        for (int o = 8; o; o >>= 1) v += __shfl_xor_sync(0xffffffff, v, o);
        if (tid == 0) s_red[0] = v;
    }
    __syncthreads();
    float inv = 1.0f / s_red[0];
    __syncthreads();
    if (tid < Pc) {
        float al = ex * inv;
        s_e[tid] = al;
        out_alpha[((size_t)b * Tc + t) * Pc + tid] = al;
    }
    __syncthreads();
    // awe over ENC: thread handles float4 at e0
    int e0 = tid * 4;
    const float4* encb = (const float4*)(g_enc + (size_t)b * Pc * ENCc + e0);
    const int str = ENCc / 4;
    float4 a0 = {0,0,0,0}, a1 = {0,0,0,0}, a2 = {0,0,0,0}, a3 = {0,0,0,0};
#pragma unroll 2
    for (int p = 0; p < Pc; p += 4) {
        float l0 = s_e[p + 0], l1 = s_e[p + 1], l2 = s_e[p + 2], l3 = s_e[p + 3];
        float4 v0 = encb[(size_t)(p + 0) * str];
        float4 v1 = encb[(size_t)(p + 1) * str];
        float4 v2 = encb[(size_t)(p + 2) * str];
        float4 v3 = encb[(size_t)(p + 3) * str];
        a0.x = fmaf(l0, v0.x, a0.x); a0.y = fmaf(l0, v0.y, a0.y);
        a0.z = fmaf(l0, v0.z, a0.z); a0.w = fmaf(l0, v0.w, a0.w);
        a1.x = fmaf(l1, v1.x, a1.x); a1.y = fmaf(l1, v1.y, a1.y);
        a1.z = fmaf(l1, v1.z, a1.z); a1.w = fmaf(l1, v1.w, a1.w);
        a2.x = fmaf(l2, v2.x, a2.x); a2.y = fmaf(l2, v2.y, a2.y);
        a2.z = fmaf(l2, v2.z, a2.z); a2.w = fmaf(l2, v2.w, a2.w);
        a3.x = fmaf(l3, v3.x, a3.x); a3.y = fmaf(l3, v3.y, a3.y);
        a3.z = fmaf(l3, v3.z, a3.z); a3.w = fmaf(l3, v3.w, a3.w);
    }
    float4 s;
    s.x = a0.x + a1.x + a2.x + a3.x;
    s.y = a0.y + a1.y + a2.y + a3.y;
    s.z = a0.z + a1.z + a2.z + a3.z;
    s.w = a0.w + a1.w + a2.w + a3.w;
    float4 bl = *(const float4*)&bbeta[e0];
#pragma unroll
    for (int sp = 0; sp < 4; sp++) {
        float4 pv = *(const float4*)&g_cbpart[((size_t)sp * Bc + b) * CBN + Ac + e0];
        bl.x += pv.x; bl.y += pv.y; bl.z += pv.z; bl.w += pv.w;
    }
    float4 o;
    o.x = s.x / (1.0f + expf(-bl.x));
    o.y = s.y / (1.0f + expf(-bl.y));
    o.z = s.z / (1.0f + expf(-bl.z));
    o.w = s.w / (1.0f + expf(-bl.w));
    *(float4*)&g_xh[(size_t)b * KXH + Ec + e0] = o;
}

// ---------------- LSTM gates; also stage next step's embedding --------------------
__global__ void gates_kernel(const float* __restrict__ bl, int t) {
    int b = blockIdx.x, n = threadIdx.x;  // 512
    float zi = bl[n], zf = bl[Uc + n], zg = bl[2 * Uc + n], zo = bl[3 * Uc + n];
#pragma unroll
    for (int s = 0; s < 8; s++) {
        const float* zp = g_zpart + ((size_t)s * Bc + b) * N4U;
        zi += zp[n];
        zf += zp[Uc + n];
        zg += zp[2 * Uc + n];
        zo += zp[3 * Uc + n];
    }
    float c_old = g_c[b * Uc + n], h_old = g_h[b * Uc + n];
    float si = 1.0f / (1.0f + expf(-zi));
    float sf = 1.0f / (1.0f + expf(-zf));
    float so = 1.0f / (1.0f + expf(-zo));
    float c_new = sf * c_old + si * tanhf(zg);
    float h_new = so * tanhf(c_new);
    bool mask = t < g_ilen[b];
    float c2 = mask ? c_new : c_old;
    float h2 = mask ? h_new : h_old;
    g_c[b * Uc + n] = c2;
    g_h[b * Uc + n] = h2;
    g_xh[(size_t)b * KXH + Ec + ENCc + n] = h2;
    if (t + 1 < Tc)
        g_xh[(size_t)b * KXH + n] = g_embAll[((size_t)(t + 1) * Bc + b) * Ec + n];
}

// ---------------- vocab softmax (bias already in logits), masked ------------------
__global__ void pred_softmax_kernel(float* __restrict__ out_pred, int t) {
    int b = blockIdx.x, tid = threadIdx.x;  // 256
    float4* dst = (float4*)(out_pred + ((size_t)b * Tc + t) * Vc);
    const int NV4 = Vc / 4;  // 2500
    if (t >= g_ilen[b]) {
        float4 z = {0, 0, 0, 0};
        for (int i = tid; i < NV4; i += 256) dst[i] = z;
        return;
    }
    const float4* lg = (const float4*)(g_logits + (size_t)b * Vc);
    __shared__ float s_red[8];
    int warp = tid >> 5, lane = tid & 31;
    float m = -1e30f;
    for (int i = tid; i < NV4; i += 256) {
        float4 v = lg[i];
        m = fmaxf(m, fmaxf(fmaxf(v.x, v.y), fmaxf(v.z, v.w)));
    }
#pragma unroll
    for (int o = 16; o; o >>= 1) m = fmaxf(m, __shfl_xor_sync(0xffffffff, m, o));
    if (lane == 0) s_red[warp] = m;
    __syncthreads();
    m = s_red[0];
#pragma unroll
    for (int w = 1; w < 8; w++) m = fmaxf(m, s_red[w]);
    float sum = 0.f;
    for (int i = tid; i < NV4; i += 256) {
        float4 v = lg[i];
        v.x = expf(v.x - m); v.y = expf(v.y - m);
        v.z = expf(v.z - m); v.w = expf(v.w - m);
        dst[i] = v;
        sum += v.x + v.y + v.z + v.w;
    }
#pragma unroll
    for (int o = 16; o; o >>= 1) sum += __shfl_xor_sync(0xffffffff, sum, o);
    __syncthreads();
    if (lane == 0) s_red[warp] = sum;
    __syncthreads();
    sum = 0.f;
#pragma unroll
    for (int w = 0; w < 8; w++) sum += s_red[w];
    float inv = 1.0f / sum;
    for (int i = tid; i < NV4; i += 256) {
        float4 v = dst[i];
        v.x *= inv; v.y *= inv; v.z *= inv; v.w *= inv;
        dst[i] = v;
    }
}

// ---------------- launcher ---------------------------------------------------------
extern "C" void kernel_launch(void* const* d_in, const int* in_sizes, int n_in,
                              void* d_out, int out_size) {
    const float* enc      = (const float*)d_in[0];
    const int*   seqs     = (const int*)  d_in[1];
    const int*   lens     = (const int*)  d_in[2];
    const float* emb_tab  = (const float*)d_in[3];
    const float* W_ae     = (const float*)d_in[4];
    const float* b_ae     = (const float*)d_in[5];
    const float* W_ag     = (const float*)d_in[6];
    const float* b_ag     = (const float*)d_in[7];
    const float* W_af     = (const float*)d_in[8];
    const float* b_af     = (const float*)d_in[9];
    const float* W_x      = (const float*)d_in[10];
    const float* W_h      = (const float*)d_in[11];
    const float* b_lstm   = (const float*)d_in[12];
    const float* W_im     = (const float*)d_in[13];
    const float* b_im     = (const float*)d_in[14];
    const float* W_ic     = (const float*)d_in[15];
    const float* b_ic     = (const float*)d_in[16];
    const float* W_beta   = (const float*)d_in[17];
    const float* b_beta   = (const float*)d_in[18];
    const float* W_out    = (const float*)d_in[19];
    const float* b_out    = (const float*)d_in[20];

    float* out       = (float*)d_out;
    float* out_pred  = out;                                   // [B,T,V]
    float* out_alpha = out_pred + (size_t)Bc * Tc * Vc;       // [B,T,P]
    float* out_seqs  = out_alpha + (size_t)Bc * Tc * Pc;      // [B,S]
    float* out_ilen  = out_seqs + (size_t)Bc * Sc;            // [B]
    float* out_order = out_ilen + Bc;                         // [B]

    float *p_enc, *p_att1, *p_Wxh, *p_Wcb, *p_mean, *p_c, *p_xh, *p_zpart, *p_cbpart, *p_logits;
    cudaGetSymbolAddress((void**)&p_enc, g_enc);
    cudaGetSymbolAddress((void**)&p_att1, g_att1);
    cudaGetSymbolAddress((void**)&p_Wxh, g_Wxh);
    cudaGetSymbolAddress((void**)&p_Wcb, g_Wcb);
    cudaGetSymbolAddress((void**)&p_mean, g_mean);
    cudaGetSymbolAddress((void**)&p_c, g_c);
    cudaGetSymbolAddress((void**)&p_xh, g_xh);
    cudaGetSymbolAddress((void**)&p_zpart, g_zpart);
    cudaGetSymbolAddress((void**)&p_cbpart, g_cbpart);
    cudaGetSymbolAddress((void**)&p_logits, g_logits);

    // ---- setup ----
    sort_kernel<<<1, Bc>>>(lens, seqs, out_seqs, out_ilen, out_order);
    permute_kernel<<<dim3(Bc, Pc), 256>>>(enc);
    wxh_kernel<<<(int)(((size_t)KXH * N4U + 255) / 256), 256>>>(W_x, W_h);
    wcb_kernel<<<(int)(((size_t)Uc * CBN + 255) / 256), 256>>>(W_ag, W_beta);
    emb_all_kernel<<<dim3(Bc, Tc), 128>>>(emb_tab);
    mean_kernel<<<dim3(Bc, 2), 256>>>();
    // h0/c0 partials (K=2048, ksplit=8)
    gemm_k<<<dim3(Uc / 64, 1, 8), 256>>>(p_mean, ENCc, W_im, p_zpart, ENCc, Uc, (size_t)Bc * Uc);
    gemm_k<<<dim3(Uc / 64, 1, 8), 256>>>(p_mean, ENCc, W_ic, p_zpart + (size_t)8 * Bc * Uc, ENCc, Uc, (size_t)Bc * Uc);
    init_hc_kernel<<<Bc, Uc>>>(b_im, b_ic);
    // att1 = enc_sorted @ W_att_enc + b   — TF32 tensor cores (12544x512, K=2048)
    tf32_gemm<128, 256><<<dim3(Ac / 64, (Bc * Pc) / 128), 256>>>(p_enc, W_ae, b_ae, p_att1, ENCc, Ac);

    // ---- time steps ----
    for (int t = 0; t < Tc; t++) {
        // [att2 | beta] = c @ [W_att_gen | W_beta]   (fp32, K=512, ksplit=4)
        gemm_k<<<dim3(CBN / 64, 1, 4), 256>>>(p_c, Uc, p_Wcb, p_cbpart, Uc, CBN, (size_t)Bc * CBN);
        attn_awe_kernel<<<Bc, 512>>>(b_ag, W_af, b_af, b_beta, out_alpha, t);
        // z = xh @ Wxh  (fp32, K=3072, ksplit=8)
        gemm_k<<<dim3(N4U / 64, 1, 8), 256>>>(p_xh, KXH, p_Wxh, p_zpart, KXH, N4U, (size_t)Bc * N4U);
        gates_kernel<<<Bc, Uc>>>(b_lstm, t);
        // logits = c2 @ W_out + b_out  — TF32 tensor cores (64x10000, K=512)
        tf32_gemm<64, 128><<<dim3((Vc + 63) / 64, 1), 128>>>(p_c, W_out, b_out, p_logits, Uc, Vc);
        pred_softmax_kernel<<<Bc, 256>>>(out_pred, t);
    }
}

// round 4
// speedup vs baseline: 1.2921x; 1.0025x over previous
#include <cuda_runtime.h>
#include <math.h>
#include <stdint.h>

// Problem dims
#define Bc   64
#define Pc   196
#define Sc   22
#define Tc   21
#define Vc   10000
#define Ec   512
#define Ac   512
#define Uc   512
#define ENCc 2048
#define N4U  2048   // 4*U
#define CBN  2560   // A + ENC (att2 | beta combined)

// ---------------- scratch (static __device__ arrays; no allocation) -------------
__device__ float g_enc[Bc * Pc * ENCc];      // sorted encoder output  (102.8 MB)
__device__ float g_att1[Bc * Pc * Ac];       // enc @ W_att_enc + b_ae (25.7 MB)
__device__ float g_mean[Bc * ENCc];
__device__ float g_h[Bc * Uc];
__device__ float g_c[Bc * Uc];
__device__ float g_alpha[Bc * Pc];
__device__ float g_cb[Bc * CBN];             // [att2 | beta-logits] (no bias)
__device__ float g_awe[Bc * ENCc];           // gated context
__device__ float g_zp[4 * Bc * N4U];         // z partials: emb, h, awe0, awe1 (init reuses)
__device__ float g_logits[Bc * Vc];          // logits (no bias)
__device__ float g_embAll[Tc * Bc * Ec];     // embeddings for all steps
__device__ int   g_order[Bc];
__device__ int   g_ilen[Bc];
__device__ int   g_seqs[Bc * Sc];

// ---------------- sort: stable argsort(-lens) ------------------------------------
__global__ void sort_kernel(const int* __restrict__ lens,
                            const int* __restrict__ seqs,
                            float* __restrict__ out_seqs,
                            float* __restrict__ out_ilen,
                            float* __restrict__ out_order) {
    int tid = threadIdx.x;  // 64 threads
    __shared__ int s_len[Bc];
    s_len[tid] = lens[tid];
    __syncthreads();
    int myL = s_len[tid];
    int rank = 0;
    for (int j = 0; j < Bc; j++) {
        int lj = s_len[j];
        rank += (lj > myL) || (lj == myL && j < tid);
    }
    g_order[rank] = tid;
    __syncthreads();
    int src = g_order[tid];
    int il = s_len[src] - 1;
    g_ilen[tid] = il;
    out_ilen[tid] = (float)il;
    out_order[tid] = (float)src;
    for (int s = 0; s < Sc; s++) {
        int v = seqs[src * Sc + s];
        g_seqs[tid * Sc + s] = v;
        out_seqs[tid * Sc + s] = (float)v;
    }
}

// ---------------- permute encoder rows into sorted order ------------------------
__global__ void permute_kernel(const float* __restrict__ enc) {
    int b = blockIdx.x, p = blockIdx.y;
    int src = g_order[b];
    const float4* s = (const float4*)&enc[((size_t)src * Pc + p) * ENCc];
    float4* d = (float4*)&g_enc[((size_t)b * Pc + p) * ENCc];
    for (int i = threadIdx.x; i < ENCc / 4; i += 256) d[i] = s[i];
}

// ---------------- precompute embeddings for all timesteps ------------------------
__global__ void emb_all_kernel(const float* __restrict__ emb_table) {
    int b = blockIdx.x, t = blockIdx.y;  // 128 threads, float4
    int tok = g_seqs[b * Sc + t];
    float4 v = ((const float4*)(emb_table + (size_t)tok * Ec))[threadIdx.x];
    ((float4*)(g_embAll + ((size_t)t * Bc + b) * Ec))[threadIdx.x] = v;
}

// ---------------- mean over pixels (vectorized) -----------------------------------
__global__ void mean_kernel() {
    int b = blockIdx.x;
    int e0 = blockIdx.y * 1024 + threadIdx.x * 4;
    const float4* encb = (const float4*)(g_enc + (size_t)b * Pc * ENCc + e0);
    const int str = ENCc / 4;
    float4 a0 = {0,0,0,0}, a1 = {0,0,0,0}, a2 = {0,0,0,0}, a3 = {0,0,0,0};
#pragma unroll 2
    for (int p = 0; p < Pc; p += 4) {
        float4 v0 = encb[(size_t)(p + 0) * str];
        float4 v1 = encb[(size_t)(p + 1) * str];
        float4 v2 = encb[(size_t)(p + 2) * str];
        float4 v3 = encb[(size_t)(p + 3) * str];
        a0.x += v0.x; a0.y += v0.y; a0.z += v0.z; a0.w += v0.w;
        a1.x += v1.x; a1.y += v1.y; a1.z += v1.z; a1.w += v1.w;
        a2.x += v2.x; a2.y += v2.y; a2.z += v2.z; a2.w += v2.w;
        a3.x += v3.x; a3.y += v3.y; a3.z += v3.z; a3.w += v3.w;
    }
    float4 r;
    r.x = (a0.x + a1.x + a2.x + a3.x) * (1.0f / Pc);
    r.y = (a0.y + a1.y + a2.y + a3.y) * (1.0f / Pc);
    r.z = (a0.z + a1.z + a2.z + a3.z) * (1.0f / Pc);
    r.w = (a0.w + a1.w + a2.w + a3.w) * (1.0f / Pc);
    *(float4*)(g_mean + (size_t)b * ENCc + e0) = r;
}

// ---------------- TF32 helpers -----------------------------------------------------
__device__ __forceinline__ float to_tf32(float x) {
    uint32_t r;
    asm("cvt.rna.tf32.f32 %0, %1;" : "=r"(r) : "f"(x));
    return __uint_as_float(r);
}
__device__ __forceinline__ void mma_tf32(float* c, const uint32_t* a, const uint32_t* b) {
    asm volatile(
        "mma.sync.aligned.m16n8k8.row.col.f32.tf32.tf32.f32 "
        "{%0,%1,%2,%3}, {%4,%5,%6,%7}, {%8,%9}, {%0,%1,%2,%3};"
        : "+f"(c[0]), "+f"(c[1]), "+f"(c[2]), "+f"(c[3])
        : "r"(a[0]), "r"(a[1]), "r"(a[2]), "r"(b[0]), "r"(b[1]), "r"(a[3])
        : );
}
// NOTE: careful operand order — use explicit correct version below.
__device__ __forceinline__ void mma_tf32v(float* c, const uint32_t* a, const uint32_t* b) {
    asm volatile(
        "mma.sync.aligned.m16n8k8.row.col.f32.tf32.tf32.f32 "
        "{%0,%1,%2,%3}, {%4,%5,%6,%7}, {%8,%9}, {%0,%1,%2,%3};"
        : "+f"(c[0]), "+f"(c[1]), "+f"(c[2]), "+f"(c[3])
        : "r"(a[0]), "r"(a[1]), "r"(a[2]), "r"(a[3]), "r"(b[0]), "r"(b[1]));
}

// ---- 64x128-tile TF32 block GEMM device function (256 threads, 8 warps) ----------
// C[64, nguard] = A[64, K] @ W[K, nguard<=128].  A: row stride lda; W: row stride ldw;
// C: row stride ldc. No bias. K % 32 == 0. Pointers pre-offset to tile origin.
__device__ void tf32_block(const float* __restrict__ A, int lda,
                           const float* __restrict__ W, int ldw,
                           float* __restrict__ C, int ldc,
                           int K, int nguard) {
    __shared__ float As[64][36];
    __shared__ float Ws[32][132];
    const int tid = threadIdx.x;
    const int warp = tid >> 5, lane = tid & 31;
    const int wm = (warp & 1) << 5;
    const int wn = (warp >> 1) << 5;

    float acc[2][4][4];
#pragma unroll
    for (int i = 0; i < 2; i++)
#pragma unroll
        for (int j = 0; j < 4; j++)
#pragma unroll
            for (int q = 0; q < 4; q++) acc[i][j][q] = 0.f;

    for (int k0 = 0; k0 < K; k0 += 32) {
        __syncthreads();
        // A tile 64x32: 2 float4 per thread
#pragma unroll
        for (int j = 0; j < 2; j++) {
            int idx = tid + j * 256;
            int r = idx >> 3, kq = (idx & 7) << 2;
            float4 v = *(const float4*)(A + (size_t)r * lda + k0 + kq);
            float4 cv;
            cv.x = to_tf32(v.x); cv.y = to_tf32(v.y);
            cv.z = to_tf32(v.z); cv.w = to_tf32(v.w);
            *(float4*)&As[r][kq] = cv;
        }
        // W tile 32x128: 4 float4 per thread
#pragma unroll
        for (int j = 0; j < 4; j++) {
            int idx = tid + j * 256;
            int kr = idx >> 5, nq = (idx & 31) << 2;
            const float* wp = W + (size_t)(k0 + kr) * ldw + nq;
            float4 v;
            if (nq + 3 < nguard) v = *(const float4*)wp;
            else {
                v.x = (nq + 0 < nguard) ? wp[0] : 0.f;
                v.y = (nq + 1 < nguard) ? wp[1] : 0.f;
                v.z = (nq + 2 < nguard) ? wp[2] : 0.f;
                v.w = (nq + 3 < nguard) ? wp[3] : 0.f;
            }
            float4 cv;
            cv.x = to_tf32(v.x); cv.y = to_tf32(v.y);
            cv.z = to_tf32(v.z); cv.w = to_tf32(v.w);
            *(float4*)&Ws[kr][nq] = cv;
        }
        __syncthreads();
#pragma unroll
        for (int ks = 0; ks < 32; ks += 8) {
            uint32_t af[2][4];
            const int r = lane >> 2, c = ks + (lane & 3);
#pragma unroll
            for (int mi = 0; mi < 2; mi++) {
                int rr = wm + mi * 16 + r;
                af[mi][0] = __float_as_uint(As[rr][c]);
                af[mi][1] = __float_as_uint(As[rr + 8][c]);
                af[mi][2] = __float_as_uint(As[rr][c + 4]);
                af[mi][3] = __float_as_uint(As[rr + 8][c + 4]);
            }
            uint32_t bfr[4][2];
            const int bk = ks + (lane & 3), bn = lane >> 2;
#pragma unroll
            for (int nj = 0; nj < 4; nj++) {
                bfr[nj][0] = __float_as_uint(Ws[bk][wn + nj * 8 + bn]);
                bfr[nj][1] = __float_as_uint(Ws[bk + 4][wn + nj * 8 + bn]);
            }
#pragma unroll
            for (int mi = 0; mi < 2; mi++)
#pragma unroll
                for (int nj = 0; nj < 4; nj++)
                    mma_tf32v(acc[mi][nj], af[mi], bfr[nj]);
        }
    }
    const int r = lane >> 2, cc = (lane & 3) << 1;
#pragma unroll
    for (int mi = 0; mi < 2; mi++) {
#pragma unroll
        for (int nj = 0; nj < 4; nj++) {
            int row = wm + mi * 16 + r;
            int col = wn + nj * 8 + cc;
            if (col + 1 < nguard) {
                float2 o0 = {acc[mi][nj][0], acc[mi][nj][1]};
                float2 o1 = {acc[mi][nj][2], acc[mi][nj][3]};
                *(float2*)&C[(size_t)row * ldc + col] = o0;
                *(float2*)&C[(size_t)(row + 8) * ldc + col] = o1;
            }
        }
    }
}

// ---------------- old TF32 GEMM with bias (att1, 128x64 tiles) --------------------
template <int BM, int THREADS>
__global__ __launch_bounds__(256) void tf32_gemm(
    const float* __restrict__ A, const float* __restrict__ W,
    const float* __restrict__ bias, float* __restrict__ C,
    int K, int N) {
    __shared__ float As[BM][36];
    __shared__ float Ws[32][72];
    const int tid = threadIdx.x;
    const int warp = tid >> 5, lane = tid & 31;
    const int WGM = BM / 32;
    const int wm = (warp % WGM) << 5;
    const int wn = (warp / WGM) << 5;
    const int m0 = blockIdx.y * BM;
    const int n0 = blockIdx.x * 64;
    const float* Ab = A + (size_t)m0 * K;

    float acc[2][4][4];
#pragma unroll
    for (int i = 0; i < 2; i++)
#pragma unroll
        for (int j = 0; j < 4; j++)
#pragma unroll
            for (int q = 0; q < 4; q++) acc[i][j][q] = 0.f;

    for (int k0 = 0; k0 < K; k0 += 32) {
        __syncthreads();
#pragma unroll
        for (int j = 0; j < (BM * 8) / THREADS; j++) {
            int idx = tid + j * THREADS;
            int r = idx >> 3, kq = (idx & 7) << 2;
            float4 v = *(const float4*)(Ab + (size_t)r * K + k0 + kq);
            float4 cv;
            cv.x = to_tf32(v.x); cv.y = to_tf32(v.y);
            cv.z = to_tf32(v.z); cv.w = to_tf32(v.w);
            *(float4*)&As[r][kq] = cv;
        }
#pragma unroll
        for (int j = 0; j < 512 / THREADS; j++) {
            int idx = tid + j * THREADS;
            int kr = idx >> 4, nq = (idx & 15) << 2;
            const float* wp = W + (size_t)(k0 + kr) * N + n0 + nq;
            float4 v = *(const float4*)wp;
            float4 cv;
            cv.x = to_tf32(v.x); cv.y = to_tf32(v.y);
            cv.z = to_tf32(v.z); cv.w = to_tf32(v.w);
            *(float4*)&Ws[kr][nq] = cv;
        }
        __syncthreads();
#pragma unroll
        for (int ks = 0; ks < 32; ks += 8) {
            uint32_t af[2][4];
            const int r = lane >> 2, c = ks + (lane & 3);
#pragma unroll
            for (int mi = 0; mi < 2; mi++) {
                int rr = wm + mi * 16 + r;
                af[mi][0] = __float_as_uint(As[rr][c]);
                af[mi][1] = __float_as_uint(As[rr + 8][c]);
                af[mi][2] = __float_as_uint(As[rr][c + 4]);
                af[mi][3] = __float_as_uint(As[rr + 8][c + 4]);
            }
            uint32_t bfr[4][2];
            const int bk = ks + (lane & 3), bn = lane >> 2;
#pragma unroll
            for (int nj = 0; nj < 4; nj++) {
                bfr[nj][0] = __float_as_uint(Ws[bk][wn + nj * 8 + bn]);
                bfr[nj][1] = __float_as_uint(Ws[bk + 4][wn + nj * 8 + bn]);
            }
#pragma unroll
            for (int mi = 0; mi < 2; mi++)
#pragma unroll
                for (int nj = 0; nj < 4; nj++)
                    mma_tf32v(acc[mi][nj], af[mi], bfr[nj]);
        }
    }
    const int r = lane >> 2, cc = (lane & 3) << 1;
#pragma unroll
    for (int mi = 0; mi < 2; mi++) {
#pragma unroll
        for (int nj = 0; nj < 4; nj++) {
            int row = m0 + wm + mi * 16 + r;
            int col = n0 + wn + nj * 8 + cc;
            float b0 = bias[col], b1 = bias[col + 1];
            float2 o0 = {acc[mi][nj][0] + b0, acc[mi][nj][1] + b1};
            float2 o1 = {acc[mi][nj][2] + b0, acc[mi][nj][3] + b1};
            *(float2*)&C[(size_t)row * N + col] = o0;
            *(float2*)&C[(size_t)(row + 8) * N + col] = o1;
        }
    }
}

// ---------------- fp32 GEMM for h0/c0 init (partials) -----------------------------
__global__ __launch_bounds__(256) void gemm_k(
    const float* __restrict__ A, int lda,
    const float* __restrict__ W,
    float* __restrict__ out,
    int K, int N, size_t part_stride) {
    __shared__ float As[16][68];
    __shared__ float Ws[16][68];
    const int tid = threadIdx.x;
    const int tx = tid & 15, ty = tid >> 4;
    const int n0 = blockIdx.x * 64;
    const int kchunk = K / gridDim.z;
    const int kbeg = blockIdx.z * kchunk;
    float* ob = out + (size_t)blockIdx.z * part_stride;

    const int lm = tid >> 2;
    const int lq = (tid & 3) << 2;
    const int wk = tid >> 4;
    const int wn = (tid & 15) << 2;

    float acc[4][4] = {};

    for (int k0 = kbeg; k0 < kbeg + kchunk; k0 += 16) {
        float4 av = *(const float4*)(A + (size_t)lm * lda + k0 + lq);
        float4 wv = *(const float4*)(W + (size_t)(k0 + wk) * N + n0 + wn);
        __syncthreads();
        As[lq + 0][lm] = av.x; As[lq + 1][lm] = av.y;
        As[lq + 2][lm] = av.z; As[lq + 3][lm] = av.w;
        *(float4*)&Ws[wk][wn] = wv;
        __syncthreads();
#pragma unroll
        for (int kk = 0; kk < 16; kk++) {
            float4 a = *(const float4*)&As[kk][ty << 2];
            float4 w = *(const float4*)&Ws[kk][tx << 2];
            acc[0][0] = fmaf(a.x, w.x, acc[0][0]); acc[0][1] = fmaf(a.x, w.y, acc[0][1]);
            acc[0][2] = fmaf(a.x, w.z, acc[0][2]); acc[0][3] = fmaf(a.x, w.w, acc[0][3]);
            acc[1][0] = fmaf(a.y, w.x, acc[1][0]); acc[1][1] = fmaf(a.y, w.y, acc[1][1]);
            acc[1][2] = fmaf(a.y, w.z, acc[1][2]); acc[1][3] = fmaf(a.y, w.w, acc[1][3]);
            acc[2][0] = fmaf(a.z, w.x, acc[2][0]); acc[2][1] = fmaf(a.z, w.y, acc[2][1]);
            acc[2][2] = fmaf(a.z, w.z, acc[2][2]); acc[2][3] = fmaf(a.z, w.w, acc[2][3]);
            acc[3][0] = fmaf(a.w, w.x, acc[3][0]); acc[3][1] = fmaf(a.w, w.y, acc[3][1]);
            acc[3][2] = fmaf(a.w, w.z, acc[3][2]); acc[3][3] = fmaf(a.w, w.w, acc[3][3]);
        }
    }
    const int c0 = n0 + (tx << 2);
#pragma unroll
    for (int i = 0; i < 4; i++) {
        int r = (ty << 2) + i;
        float4 o = {acc[i][0], acc[i][1], acc[i][2], acc[i][3]};
        *(float4*)&ob[(size_t)r * N + c0] = o;
    }
}

// ---------------- init h0/c0 from split-K partials + bias ------------------------
__global__ void init_hc_kernel(const float* __restrict__ bm, const float* __restrict__ bc) {
    int b = blockIdx.x, n = threadIdx.x;  // 512
    float h = bm[n], c = bc[n];
#pragma unroll
    for (int s = 0; s < 8; s++) {
        h += g_zp[((size_t)s * Bc + b) * Uc + n];
        c += g_zp[((size_t)(8 + s) * Bc + b) * Uc + n];
    }
    g_h[b * Uc + n] = h;
    g_c[b * Uc + n] = c;
}

// ============ Mega-A: cb(t) | logits(t-1) | z_emb(t) | z_h(t)  (131 blocks) ======
__global__ __launch_bounds__(256) void megaA_kernel(
    const float* __restrict__ Wag, const float* __restrict__ Wbeta,
    const float* __restrict__ Wout, const float* __restrict__ Wx,
    const float* __restrict__ Wh, int t, int do_rest, int do_logits) {
    int r = blockIdx.x;
    if (r < 20) {
        if (!do_rest) return;
        // cb: [att2|beta] = c @ [Wag|Wbeta], N=2560 concat
        const float* W;
        int ldw;
        if (r < 4) { W = Wag + r * 128; ldw = Ac; }
        else       { W = Wbeta + (r - 4) * 128; ldw = ENCc; }
        tf32_block(g_c, Uc, W, ldw, g_cb + r * 128, CBN, Uc, 128);
    } else if (r < 99) {
        if (!do_logits) return;
        int n0 = (r - 20) * 128;
        int ng = Vc - n0; if (ng > 128) ng = 128;
        tf32_block(g_c, Uc, Wout + n0, Vc, g_logits + n0, Vc, Uc, ng);
    } else if (r < 115) {
        if (!do_rest) return;
        int n0 = (r - 99) * 128;
        tf32_block(g_embAll + (size_t)t * Bc * Ec, Ec, Wx + n0, N4U,
                   g_zp + 0 * (size_t)Bc * N4U + n0, N4U, Ec, 128);
    } else {
        if (!do_rest) return;
        int n0 = (r - 115) * 128;
        tf32_block(g_h, Uc, Wh + n0, N4U,
                   g_zp + 1 * (size_t)Bc * N4U + n0, N4U, Uc, 128);
    }
}

// ============ z_awe: two K-halves x 16 N-blocks (32 blocks) ======================
__global__ __launch_bounds__(256) void zawe_kernel(const float* __restrict__ Wx) {
    int r = blockIdx.x;
    int half = r >> 4, n0 = (r & 15) * 128;
    tf32_block(g_awe + half * 1024, ENCc,
               Wx + (size_t)(Ec + half * 1024) * N4U + n0, N4U,
               g_zp + (size_t)(2 + half) * Bc * N4U + n0, N4U, 1024, 128);
}

// ============ Mega-B: attn(t) | vocab softmax(t-1)  (128 blocks, 256 thr) ========
__device__ void attn_dev(int b, const float* __restrict__ bag,
                         const float* __restrict__ wf, const float* __restrict__ bf,
                         float* __restrict__ out_alpha, int t) {
    int tid = threadIdx.x;  // 256
    if (t >= g_ilen[b]) {
        if (tid < Pc) out_alpha[((size_t)b * Tc + t) * Pc + tid] = 0.f;
        return;
    }
    __shared__ float s_att2[Ac];
    __shared__ float s_wf[Ac];
    __shared__ float s_e[Pc];
    __shared__ float s_red[8];
    for (int a = tid; a < Ac; a += 256) {
        s_att2[a] = g_cb[(size_t)b * CBN + a] + bag[a];
        s_wf[a] = wf[a];
    }
    __syncthreads();
    int warp = tid >> 5, lane = tid & 31;
    const float* att1b = g_att1 + (size_t)b * Pc * Ac;
    float bfull = bf[0];
    for (int p = warp; p < Pc; p += 8) {
        const float4* row = (const float4*)(att1b + (size_t)p * Ac);
        float s = 0.f;
#pragma unroll
        for (int i = 0; i < 4; i++) {
            int a = lane + i * 32;
            float4 v = row[a];
            float4 t2 = *(const float4*)&s_att2[a * 4];
            float4 wv = *(const float4*)&s_wf[a * 4];
            float x;
            x = v.x + t2.x; if (x > 0.f) s = fmaf(x, wv.x, s);
            x = v.y + t2.y; if (x > 0.f) s = fmaf(x, wv.y, s);
            x = v.z + t2.z; if (x > 0.f) s = fmaf(x, wv.z, s);
            x = v.w + t2.w; if (x > 0.f) s = fmaf(x, wv.w, s);
        }
#pragma unroll
        for (int o = 16; o; o >>= 1) s += __shfl_xor_sync(0xffffffff, s, o);
        if (lane == 0) s_e[p] = s + bfull;
    }
    __syncthreads();
    float e = (tid < Pc) ? s_e[tid] : -1e30f;
    float m = e;
#pragma unroll
    for (int o = 16; o; o >>= 1) m = fmaxf(m, __shfl_xor_sync(0xffffffff, m, o));
    if (lane == 0) s_red[warp] = m;
    __syncthreads();
    m = s_red[0];
#pragma unroll
    for (int w = 1; w < 8; w++) m = fmaxf(m, s_red[w]);
    float ex = (tid < Pc) ? expf(e - m) : 0.f;
    float sm = ex;
#pragma unroll
    for (int o = 16; o; o >>= 1) sm += __shfl_xor_sync(0xffffffff, sm, o);
    __syncthreads();
    if (lane == 0) s_red[warp] = sm;
    __syncthreads();
    sm = 0.f;
#pragma unroll
    for (int w = 0; w < 8; w++) sm += s_red[w];
    float inv = 1.0f / sm;
    if (tid < Pc) {
        float al = ex * inv;
        g_alpha[b * Pc + tid] = al;
        out_alpha[((size_t)b * Tc + t) * Pc + tid] = al;
    }
}

__device__ void softmax_dev(int b, const float* __restrict__ bo,
                            float* __restrict__ out_pred, int tsoft) {
    int tid = threadIdx.x;  // 256
    float4* dst = (float4*)(out_pred + ((size_t)b * Tc + tsoft) * Vc);
    const int NV4 = Vc / 4;
    if (tsoft >= g_ilen[b]) {
        float4 z = {0, 0, 0, 0};
        for (int i = tid; i < NV4; i += 256) dst[i] = z;
        return;
    }
    const float4* lg = (const float4*)(g_logits + (size_t)b * Vc);
    const float4* bo4 = (const float4*)bo;
    __shared__ float s_red2[8];
    int warp = tid >> 5, lane = tid & 31;
    float m = -1e30f;
    for (int i = tid; i < NV4; i += 256) {
        float4 a = lg[i], bb = bo4[i];
        float4 v = {a.x + bb.x, a.y + bb.y, a.z + bb.z, a.w + bb.w};
        dst[i] = v;
        m = fmaxf(m, fmaxf(fmaxf(v.x, v.y), fmaxf(v.z, v.w)));
    }
#pragma unroll
    for (int o = 16; o; o >>= 1) m = fmaxf(m, __shfl_xor_sync(0xffffffff, m, o));
    if (lane == 0) s_red2[warp] = m;
    __syncthreads();
    m = s_red2[0];
#pragma unroll
    for (int w = 1; w < 8; w++) m = fmaxf(m, s_red2[w]);
    float sum = 0.f;
    for (int i = tid; i < NV4; i += 256) {
        float4 v = dst[i];
        v.x = expf(v.x - m); v.y = expf(v.y - m);
        v.z = expf(v.z - m); v.w = expf(v.w - m);
        dst[i] = v;
        sum += v.x + v.y + v.z + v.w;
    }
#pragma unroll
    for (int o = 16; o; o >>= 1) sum += __shfl_xor_sync(0xffffffff, sum, o);
    __syncthreads();
    if (lane == 0) s_red2[warp] = sum;
    __syncthreads();
    sum = 0.f;
#pragma unroll
    for (int w = 0; w < 8; w++) sum += s_red2[w];
    float inv = 1.0f / sum;
    for (int i = tid; i < NV4; i += 256) {
        float4 v = dst[i];
        v.x *= inv; v.y *= inv; v.z *= inv; v.w *= inv;
        dst[i] = v;
    }
}

__global__ __launch_bounds__(256) void megaB_kernel(
    const float* __restrict__ bag, const float* __restrict__ wf,
    const float* __restrict__ bf, const float* __restrict__ bo,
    float* __restrict__ out_alpha, float* __restrict__ out_pred,
    int t, int do_attn, int do_soft, int tsoft) {
    if (blockIdx.x < 64) {
        if (do_attn) attn_dev(blockIdx.x, bag, wf, bf, out_alpha, t);
    } else {
        if (do_soft) softmax_dev(blockIdx.x - 64, bo, out_pred, tsoft);
    }
}

// ---------------- awe = (alpha . enc) * sigmoid(beta)  grid (64,4) ----------------
__global__ __launch_bounds__(256) void awe_kernel(const float* __restrict__ bbeta, int t) {
    int b = blockIdx.x, tid = threadIdx.x;
    if (t >= g_ilen[b]) return;  // stale g_awe unused (masked)
    __shared__ float s_al[Pc];
    if (tid < Pc) s_al[tid] = g_alpha[b * Pc + tid];
    __syncthreads();
    int e = blockIdx.y * 512 + tid * 2;
    const float2* encb = (const float2*)(g_enc + (size_t)b * Pc * ENCc + e);
    const int str = ENCc / 2;
    float2 a0 = {0,0}, a1 = {0,0}, a2 = {0,0}, a3 = {0,0};
#pragma unroll 2
    for (int p = 0; p < Pc; p += 4) {
        float l0 = s_al[p + 0], l1 = s_al[p + 1], l2 = s_al[p + 2], l3 = s_al[p + 3];
        float2 v0 = encb[(size_t)(p + 0) * str];
        float2 v1 = encb[(size_t)(p + 1) * str];
        float2 v2 = encb[(size_t)(p + 2) * str];
        float2 v3 = encb[(size_t)(p + 3) * str];
        a0.x = fmaf(l0, v0.x, a0.x); a0.y = fmaf(l0, v0.y, a0.y);
        a1.x = fmaf(l1, v1.x, a1.x); a1.y = fmaf(l1, v1.y, a1.y);
        a2.x = fmaf(l2, v2.x, a2.x); a2.y = fmaf(l2, v2.y, a2.y);
        a3.x = fmaf(l3, v3.x, a3.x); a3.y = fmaf(l3, v3.y, a3.y);
    }
    float2 s = {a0.x + a1.x + a2.x + a3.x, a0.y + a1.y + a2.y + a3.y};
    float2 bl = *(const float2*)&bbeta[e];
    float2 cbv = *(const float2*)&g_cb[(size_t)b * CBN + Ac + e];
    bl.x += cbv.x; bl.y += cbv.y;
    float2 o;
    o.x = s.x / (1.0f + expf(-bl.x));
    o.y = s.y / (1.0f + expf(-bl.y));
    *(float2*)&g_awe[(size_t)b * ENCc + e] = o;
}

// ---------------- LSTM gates from 4 partials + masked state update ---------------
__global__ void gates_kernel(const float* __restrict__ bl, int t) {
    int b = blockIdx.x, n = threadIdx.x;  // 512
    float zi = bl[n], zf = bl[Uc + n], zg = bl[2 * Uc + n], zo = bl[3 * Uc + n];
#pragma unroll
    for (int s = 0; s < 4; s++) {
        const float* zp = g_zp + ((size_t)s * Bc + b) * N4U;
        zi += zp[n];
        zf += zp[Uc + n];
        zg += zp[2 * Uc + n];
        zo += zp[3 * Uc + n];
    }
    float c_old = g_c[b * Uc + n], h_old = g_h[b * Uc + n];
    float si = 1.0f / (1.0f + expf(-zi));
    float sf = 1.0f / (1.0f + expf(-zf));
    float so = 1.0f / (1.0f + expf(-zo));
    float c_new = sf * c_old + si * tanhf(zg);
    float h_new = so * tanhf(c_new);
    bool mask = t < g_ilen[b];
    g_c[b * Uc + n] = mask ? c_new : c_old;
    g_h[b * Uc + n] = mask ? h_new : h_old;
}

// ---------------- launcher ---------------------------------------------------------
extern "C" void kernel_launch(void* const* d_in, const int* in_sizes, int n_in,
                              void* d_out, int out_size) {
    const float* enc      = (const float*)d_in[0];
    const int*   seqs     = (const int*)  d_in[1];
    const int*   lens     = (const int*)  d_in[2];
    const float* emb_tab  = (const float*)d_in[3];
    const float* W_ae     = (const float*)d_in[4];
    const float* b_ae     = (const float*)d_in[5];
    const float* W_ag     = (const float*)d_in[6];
    const float* b_ag     = (const float*)d_in[7];
    const float* W_af     = (const float*)d_in[8];
    const float* b_af     = (const float*)d_in[9];
    const float* W_x      = (const float*)d_in[10];
    const float* W_h      = (const float*)d_in[11];
    const float* b_lstm   = (const float*)d_in[12];
    const float* W_im     = (const float*)d_in[13];
    const float* b_im     = (const float*)d_in[14];
    const float* W_ic     = (const float*)d_in[15];
    const float* b_ic     = (const float*)d_in[16];
    const float* W_beta   = (const float*)d_in[17];
    const float* b_beta   = (const float*)d_in[18];
    const float* W_out    = (const float*)d_in[19];
    const float* b_out    = (const float*)d_in[20];

    float* out       = (float*)d_out;
    float* out_pred  = out;                                   // [B,T,V]
    float* out_alpha = out_pred + (size_t)Bc * Tc * Vc;       // [B,T,P]
    float* out_seqs  = out_alpha + (size_t)Bc * Tc * Pc;      // [B,S]
    float* out_ilen  = out_seqs + (size_t)Bc * Sc;            // [B]
    float* out_order = out_ilen + Bc;                         // [B]

    float *p_enc, *p_att1, *p_mean, *p_zp;
    cudaGetSymbolAddress((void**)&p_enc, g_enc);
    cudaGetSymbolAddress((void**)&p_att1, g_att1);
    cudaGetSymbolAddress((void**)&p_mean, g_mean);
    cudaGetSymbolAddress((void**)&p_zp, g_zp);

    // ---- setup ----
    sort_kernel<<<1, Bc>>>(lens, seqs, out_seqs, out_ilen, out_order);
    permute_kernel<<<dim3(Bc, Pc), 256>>>(enc);
    emb_all_kernel<<<dim3(Bc, Tc), 128>>>(emb_tab);
    mean_kernel<<<dim3(Bc, 2), 256>>>();
    // h0/c0 partials into g_zp slices 0..7 / 8..15 (stride Bc*Uc)
    gemm_k<<<dim3(Uc / 64, 1, 8), 256>>>(p_mean, ENCc, W_im, p_zp, ENCc, Uc, (size_t)Bc * Uc);
    gemm_k<<<dim3(Uc / 64, 1, 8), 256>>>(p_mean, ENCc, W_ic, p_zp + (size_t)8 * Bc * Uc, ENCc, Uc, (size_t)Bc * Uc);
    init_hc_kernel<<<Bc, Uc>>>(b_im, b_ic);
    // att1 = enc_sorted @ W_att_enc + b_ae (TF32 tensor cores)
    tf32_gemm<128, 256><<<dim3(Ac / 64, (Bc * Pc) / 128), 256>>>(p_enc, W_ae, b_ae, p_att1, ENCc, Ac);

    // ---- time steps ----
    for (int t = 0; t < Tc; t++) {
        int haveprev = (t > 0) ? 1 : 0;
        megaA_kernel<<<131, 256>>>(W_ag, W_beta, W_out, W_x, W_h, t, 1, haveprev);
        megaB_kernel<<<128, 256>>>(b_ag, W_af, b_af, b_out, out_alpha, out_pred,
                                   t, 1, haveprev, t - 1);
        awe_kernel<<<dim3(Bc, 4), 256>>>(b_beta, t);
        zawe_kernel<<<32, 256>>>(W_x);
        gates_kernel<<<Bc, Uc>>>(b_lstm, t);
    }
    // tail: logits + softmax for final step
    megaA_kernel<<<131, 256>>>(W_ag, W_beta, W_out, W_x, W_h, 0, 0, 1);
    megaB_kernel<<<128, 256>>>(b_ag, W_af, b_af, b_out, out_alpha, out_pred,
                               0, 0, 1, Tc - 1);
}

// round 5
// speedup vs baseline: 2.2862x; 1.7693x over previous
#include <cuda_runtime.h>
#include <cuda_fp16.h>
#include <math.h>
#include <stdint.h>

// Problem dims
#define Bc   64
#define Pc   196
#define Sc   22
#define Tc   21
#define Vc   10000
#define Ec   512
#define Ac   512
#define Uc   512
#define ENCc 2048
#define N4U  2048   // 4*U
#define CBN  2560   // A + ENC (att2 | beta combined)
#define KX   2560   // E + ENC (W_x K dim)

// ---------------- scratch (static __device__ arrays; no allocation) -------------
__device__ float  g_enc[Bc * Pc * ENCc];      // sorted encoder fp32 (mean + att1)
__device__ __half g_ench[Bc * Pc * ENCc];     // sorted encoder fp16 (awe)
__device__ __half g_att1h[Bc * Pc * Ac];      // att1 fp16 (attn)
__device__ __half g_Waet[Ac * ENCc];          // W_att_enc^T  [A][ENC]
__device__ __half g_Wcbt[CBN * Uc];           // [Wag|Wbeta]^T [CBN][U]
__device__ __half g_Woutt[Vc * Uc];           // W_out^T [V][U]
__device__ __half g_Wxt[N4U * KX];            // W_x^T [4U][E+ENC]
__device__ __half g_Wht[N4U * Uc];            // W_h^T [4U][U]
__device__ float g_mean[Bc * ENCc];
__device__ float g_h[Bc * Uc];
__device__ float g_c[Bc * Uc];
__device__ float g_alpha[Bc * Pc];
__device__ float g_cb[Bc * CBN];              // [att2 | beta-logits] (no bias)
__device__ float g_awe[Bc * ENCc];            // gated context
__device__ float g_zp[6 * Bc * N4U];          // z partials (init h0/c0 reuses)
__device__ float g_logits[Bc * Vc];           // logits (no bias)
__device__ float g_embAll[Tc * Bc * Ec];      // embeddings for all steps
__device__ int   g_order[Bc];
__device__ int   g_ilen[Bc];
__device__ int   g_seqs[Bc * Sc];

// ---------------- sort: stable argsort(-lens) ------------------------------------
__global__ void sort_kernel(const int* __restrict__ lens,
                            const int* __restrict__ seqs,
                            float* __restrict__ out_seqs,
                            float* __restrict__ out_ilen,
                            float* __restrict__ out_order) {
    int tid = threadIdx.x;  // 64 threads
    __shared__ int s_len[Bc];
    s_len[tid] = lens[tid];
    __syncthreads();
    int myL = s_len[tid];
    int rank = 0;
    for (int j = 0; j < Bc; j++) {
        int lj = s_len[j];
        rank += (lj > myL) || (lj == myL && j < tid);
    }
    g_order[rank] = tid;
    __syncthreads();
    int src = g_order[tid];
    int il = s_len[src] - 1;
    g_ilen[tid] = il;
    out_ilen[tid] = (float)il;
    out_order[tid] = (float)src;
    for (int s = 0; s < Sc; s++) {
        int v = seqs[src * Sc + s];
        g_seqs[tid * Sc + s] = v;
        out_seqs[tid * Sc + s] = (float)v;
    }
}

// ---------------- permute encoder rows into sorted order (fp32 + fp16) ----------
__global__ void permute_kernel(const float* __restrict__ enc) {
    int b = blockIdx.x, p = blockIdx.y;
    int src = g_order[b];
    const float4* s = (const float4*)&enc[((size_t)src * Pc + p) * ENCc];
    float4* d = (float4*)&g_enc[((size_t)b * Pc + p) * ENCc];
    __half2* dh = (__half2*)&g_ench[((size_t)b * Pc + p) * ENCc];
    for (int i = threadIdx.x; i < ENCc / 4; i += 256) {
        float4 v = s[i];
        d[i] = v;
        dh[i * 2 + 0] = __floats2half2_rn(v.x, v.y);
        dh[i * 2 + 1] = __floats2half2_rn(v.z, v.w);
    }
}

// ---------------- transpose-convert weight fp32[K,N] -> fp16[N,K] ----------------
__global__ void convT_kernel(const float* __restrict__ in, __half* __restrict__ out,
                             int K, int N) {
    __shared__ float tile[32][33];
    int n0 = blockIdx.x * 32, k0 = blockIdx.y * 32;
    int tx = threadIdx.x & 31, ty = threadIdx.x >> 5;  // 256 thr
#pragma unroll
    for (int i = 0; i < 32; i += 8) {
        int k = k0 + ty + i, n = n0 + tx;
        tile[ty + i][tx] = (n < N) ? in[(size_t)k * N + n] : 0.f;
    }
    __syncthreads();
#pragma unroll
    for (int i = 0; i < 32; i += 8) {
        int n = n0 + ty + i;
        if (n < N) out[(size_t)n * K + k0 + tx] = __float2half(tile[tx][ty + i]);
    }
}

// ---------------- precompute embeddings for all timesteps ------------------------
__global__ void emb_all_kernel(const float* __restrict__ emb_table) {
    int b = blockIdx.x, t = blockIdx.y;  // 128 threads, float4
    int tok = g_seqs[b * Sc + t];
    float4 v = ((const float4*)(emb_table + (size_t)tok * Ec))[threadIdx.x];
    ((float4*)(g_embAll + ((size_t)t * Bc + b) * Ec))[threadIdx.x] = v;
}

// ---------------- mean over pixels ------------------------------------------------
__global__ void mean_kernel() {
    int b = blockIdx.x;
    int e0 = blockIdx.y * 1024 + threadIdx.x * 4;
    const float4* encb = (const float4*)(g_enc + (size_t)b * Pc * ENCc + e0);
    const int str = ENCc / 4;
    float4 a0 = {0,0,0,0}, a1 = {0,0,0,0}, a2 = {0,0,0,0}, a3 = {0,0,0,0};
#pragma unroll 2
    for (int p = 0; p < Pc; p += 4) {
        float4 v0 = encb[(size_t)(p + 0) * str];
        float4 v1 = encb[(size_t)(p + 1) * str];
        float4 v2 = encb[(size_t)(p + 2) * str];
        float4 v3 = encb[(size_t)(p + 3) * str];
        a0.x += v0.x; a0.y += v0.y; a0.z += v0.z; a0.w += v0.w;
        a1.x += v1.x; a1.y += v1.y; a1.z += v1.z; a1.w += v1.w;
        a2.x += v2.x; a2.y += v2.y; a2.z += v2.z; a2.w += v2.w;
        a3.x += v3.x; a3.y += v3.y; a3.z += v3.z; a3.w += v3.w;
    }
    float4 r;
    r.x = (a0.x + a1.x + a2.x + a3.x) * (1.0f / Pc);
    r.y = (a0.y + a1.y + a2.y + a3.y) * (1.0f / Pc);
    r.z = (a0.z + a1.z + a2.z + a3.z) * (1.0f / Pc);
    r.w = (a0.w + a1.w + a2.w + a3.w) * (1.0f / Pc);
    *(float4*)(g_mean + (size_t)b * ENCc + e0) = r;
}

// ---------------- fp16 MMA helper --------------------------------------------------
__device__ __forceinline__ void mma_fp16(float* c, const uint32_t* a, const uint32_t* b) {
    asm volatile(
        "mma.sync.aligned.m16n8k16.row.col.f32.f16.f16.f32 "
        "{%0,%1,%2,%3}, {%4,%5,%6,%7}, {%8,%9}, {%0,%1,%2,%3};"
        : "+f"(c[0]), "+f"(c[1]), "+f"(c[2]), "+f"(c[3])
        : "r"(a[0]), "r"(a[1]), "r"(a[2]), "r"(a[3]), "r"(b[0]), "r"(b[1]));
}

// ---- 64x128-tile fp16 block GEMM (256 threads, 8 warps, warp tile 32x32) ---------
// C[64, nguard] = A[64,K](fp32) @ Wt[n][k](fp16, row stride ldk).
// HOUT: add bias and store fp16; else store fp32, bias ignored.
template <bool HOUT>
__device__ void fp16_block(const float* __restrict__ A, int lda,
                           const __half* __restrict__ Wt, int ldk,
                           void* __restrict__ Cv, int ldc,
                           int K, int nguard, const float* __restrict__ bias) {
    __shared__ __half As[64][40];
    __shared__ __half Ws[128][40];
    const int tid = threadIdx.x;
    const int warp = tid >> 5, lane = tid & 31;
    const int wm = (warp & 1) << 5;
    const int wn = (warp >> 1) << 5;

    float acc[2][4][4];
#pragma unroll
    for (int i = 0; i < 2; i++)
#pragma unroll
        for (int j = 0; j < 4; j++)
#pragma unroll
            for (int q = 0; q < 4; q++) acc[i][j][q] = 0.f;

    const int nr = tid >> 1, koff = (tid & 1) << 4;
    const bool wok = nr < nguard;

    for (int k0 = 0; k0 < K; k0 += 32) {
        __syncthreads();
        // A tile 64x32 fp32 -> fp16
#pragma unroll
        for (int j = 0; j < 2; j++) {
            int idx = tid + j * 256;
            int r = idx >> 3, kq = (idx & 7) << 2;
            float4 v = *(const float4*)(A + (size_t)r * lda + k0 + kq);
            *(__half2*)&As[r][kq]     = __floats2half2_rn(v.x, v.y);
            *(__half2*)&As[r][kq + 2] = __floats2half2_rn(v.z, v.w);
        }
        // W tile 128x32 fp16 (transposed layout [n][k])
        if (wok) {
            const __half* wp = Wt + (size_t)nr * ldk + k0 + koff;
            *(uint4*)&Ws[nr][koff]     = *(const uint4*)wp;
            *(uint4*)&Ws[nr][koff + 8] = *(const uint4*)(wp + 8);
        } else {
            uint4 z = {0, 0, 0, 0};
            *(uint4*)&Ws[nr][koff] = z;
            *(uint4*)&Ws[nr][koff + 8] = z;
        }
        __syncthreads();
#pragma unroll
        for (int ks = 0; ks < 32; ks += 16) {
            const int gr = lane >> 2, gc = (lane & 3) << 1;
            uint32_t a[2][4], bb[4][2];
#pragma unroll
            for (int mi = 0; mi < 2; mi++) {
                int row = wm + mi * 16 + gr;
                a[mi][0] = *(const uint32_t*)&As[row][ks + gc];
                a[mi][1] = *(const uint32_t*)&As[row + 8][ks + gc];
                a[mi][2] = *(const uint32_t*)&As[row][ks + gc + 8];
                a[mi][3] = *(const uint32_t*)&As[row + 8][ks + gc + 8];
            }
#pragma unroll
            for (int nj = 0; nj < 4; nj++) {
                int n = wn + nj * 8 + gr;
                bb[nj][0] = *(const uint32_t*)&Ws[n][ks + gc];
                bb[nj][1] = *(const uint32_t*)&Ws[n][ks + gc + 8];
            }
#pragma unroll
            for (int mi = 0; mi < 2; mi++)
#pragma unroll
                for (int nj = 0; nj < 4; nj++)
                    mma_fp16(acc[mi][nj], a[mi], bb[nj]);
        }
    }
    const int gr = lane >> 2, cc = (lane & 3) << 1;
#pragma unroll
    for (int mi = 0; mi < 2; mi++) {
#pragma unroll
        for (int nj = 0; nj < 4; nj++) {
            int row = wm + mi * 16 + gr;
            int col = wn + nj * 8 + cc;
            if (col + 1 < nguard || col + 1 == nguard - 0) {}  // no-op; guard below
            if (col + 1 < nguard + 1 && col < nguard - 1 + 1) {}  // no-op
            if (col + 1 <= nguard - 1) {
                if (HOUT) {
                    float b0 = bias[col], b1 = bias[col + 1];
                    __half* Ch = (__half*)Cv;
                    *(__half2*)&Ch[(size_t)row * ldc + col] =
                        __floats2half2_rn(acc[mi][nj][0] + b0, acc[mi][nj][1] + b1);
                    *(__half2*)&Ch[(size_t)(row + 8) * ldc + col] =
                        __floats2half2_rn(acc[mi][nj][2] + b0, acc[mi][nj][3] + b1);
                } else {
                    float* C = (float*)Cv;
                    float2 o0 = {acc[mi][nj][0], acc[mi][nj][1]};
                    float2 o1 = {acc[mi][nj][2], acc[mi][nj][3]};
                    *(float2*)&C[(size_t)row * ldc + col] = o0;
                    *(float2*)&C[(size_t)(row + 8) * ldc + col] = o1;
                }
            }
        }
    }
}

// ---------------- att1 = enc @ W_ae + b_ae  -> fp16 (grid (4, 196)) ---------------
__global__ __launch_bounds__(256) void att1h_kernel(const float* __restrict__ bae) {
    int n0 = blockIdx.x * 128;
    int m0 = blockIdx.y * 64;
    fp16_block<true>(g_enc + (size_t)m0 * ENCc, ENCc,
                     g_Waet + (size_t)n0 * ENCc, ENCc,
                     g_att1h + (size_t)m0 * Ac + n0, Ac, ENCc, 128, bae + n0);
}

// ---------------- fp32 GEMM for h0/c0 init (partials) -----------------------------
__global__ __launch_bounds__(256) void gemm_k(
    const float* __restrict__ A, int lda,
    const float* __restrict__ W,
    float* __restrict__ out,
    int K, int N, size_t part_stride) {
    __shared__ float As[16][68];
    __shared__ float Ws[16][68];
    const int tid = threadIdx.x;
    const int tx = tid & 15, ty = tid >> 4;
    const int n0 = blockIdx.x * 64;
    const int kchunk = K / gridDim.z;
    const int kbeg = blockIdx.z * kchunk;
    float* ob = out + (size_t)blockIdx.z * part_stride;

    const int lm = tid >> 2;
    const int lq = (tid & 3) << 2;
    const int wk = tid >> 4;
    const int wn = (tid & 15) << 2;

    float acc[4][4] = {};

    for (int k0 = kbeg; k0 < kbeg + kchunk; k0 += 16) {
        float4 av = *(const float4*)(A + (size_t)lm * lda + k0 + lq);
        float4 wv = *(const float4*)(W + (size_t)(k0 + wk) * N + n0 + wn);
        __syncthreads();
        As[lq + 0][lm] = av.x; As[lq + 1][lm] = av.y;
        As[lq + 2][lm] = av.z; As[lq + 3][lm] = av.w;
        *(float4*)&Ws[wk][wn] = wv;
        __syncthreads();
#pragma unroll
        for (int kk = 0; kk < 16; kk++) {
            float4 a = *(const float4*)&As[kk][ty << 2];
            float4 w = *(const float4*)&Ws[kk][tx << 2];
            acc[0][0] = fmaf(a.x, w.x, acc[0][0]); acc[0][1] = fmaf(a.x, w.y, acc[0][1]);
            acc[0][2] = fmaf(a.x, w.z, acc[0][2]); acc[0][3] = fmaf(a.x, w.w, acc[0][3]);
            acc[1][0] = fmaf(a.y, w.x, acc[1][0]); acc[1][1] = fmaf(a.y, w.y, acc[1][1]);
            acc[1][2] = fmaf(a.y, w.z, acc[1][2]); acc[1][3] = fmaf(a.y, w.w, acc[1][3]);
            acc[2][0] = fmaf(a.z, w.x, acc[2][0]); acc[2][1] = fmaf(a.z, w.y, acc[2][1]);
            acc[2][2] = fmaf(a.z, w.z, acc[2][2]); acc[2][3] = fmaf(a.z, w.w, acc[2][3]);
            acc[3][0] = fmaf(a.w, w.x, acc[3][0]); acc[3][1] = fmaf(a.w, w.y, acc[3][1]);
            acc[3][2] = fmaf(a.w, w.z, acc[3][2]); acc[3][3] = fmaf(a.w, w.w, acc[3][3]);
        }
    }
    const int c0 = n0 + (tx << 2);
#pragma unroll
    for (int i = 0; i < 4; i++) {
        int r = (ty << 2) + i;
        float4 o = {acc[i][0], acc[i][1], acc[i][2], acc[i][3]};
        *(float4*)&ob[(size_t)r * N + c0] = o;
    }
}

// ---------------- init h0/c0 from split-K partials + bias ------------------------
__global__ void init_hc_kernel(const float* __restrict__ bm, const float* __restrict__ bc) {
    int b = blockIdx.x, n = threadIdx.x;  // 512
    float h = bm[n], c = bc[n];
#pragma unroll
    for (int s = 0; s < 8; s++) {
        h += g_zp[((size_t)s * Bc + b) * Uc + n];
        c += g_zp[((size_t)(8 + s) * Bc + b) * Uc + n];
    }
    g_h[b * Uc + n] = h;
    g_c[b * Uc + n] = c;
}

// ============ Mega-A: cb(t) | logits(t-1) | z_emb(t) | z_h(t)  (131 blocks) ======
__global__ __launch_bounds__(256) void megaA_kernel(int t, int do_rest, int do_logits) {
    int r = blockIdx.x;
    if (r < 20) {
        if (!do_rest) return;
        int n0 = r * 128;
        fp16_block<false>(g_c, Uc, g_Wcbt + (size_t)n0 * Uc, Uc,
                          g_cb + n0, CBN, Uc, 128, nullptr);
    } else if (r < 99) {
        if (!do_logits) return;
        int n0 = (r - 20) * 128;
        int ng = Vc - n0; if (ng > 128) ng = 128;
        fp16_block<false>(g_c, Uc, g_Woutt + (size_t)n0 * Uc, Uc,
                          g_logits + n0, Vc, Uc, ng, nullptr);
    } else if (r < 115) {
        if (!do_rest) return;
        int n0 = (r - 99) * 128;
        fp16_block<false>(g_embAll + (size_t)t * Bc * Ec, Ec,
                          g_Wxt + (size_t)n0 * KX, KX,
                          g_zp + 0 * (size_t)Bc * N4U + n0, N4U, Ec, 128, nullptr);
    } else {
        if (!do_rest) return;
        int n0 = (r - 115) * 128;
        fp16_block<false>(g_h, Uc, g_Wht + (size_t)n0 * Uc, Uc,
                          g_zp + 1 * (size_t)Bc * N4U + n0, N4U, Uc, 128, nullptr);
    }
}

// ============ z_awe: 4 K-splits x 16 N-blocks (64 blocks) ========================
__global__ __launch_bounds__(256) void zawe_kernel() {
    int r = blockIdx.x;
    int sp = r >> 4, n0 = (r & 15) * 128;
    fp16_block<false>(g_awe + sp * 512, ENCc,
                      g_Wxt + (size_t)n0 * KX + Ec + sp * 512, KX,
                      g_zp + (size_t)(2 + sp) * Bc * N4U + n0, N4U, 512, 128, nullptr);
}

// ============ Mega-B: attn(t) | vocab softmax(t-1)  (128 blocks, 256 thr) ========
__device__ void attn_dev(int b, const float* __restrict__ bag,
                         const float* __restrict__ wf, const float* __restrict__ bf,
                         float* __restrict__ out_alpha, int t) {
    int tid = threadIdx.x;  // 256
    if (t >= g_ilen[b]) {
        if (tid < Pc) out_alpha[((size_t)b * Tc + t) * Pc + tid] = 0.f;
        return;
    }
    __shared__ float s_att2[Ac];
    __shared__ float s_wf[Ac];
    __shared__ float s_e[Pc];
    __shared__ float s_red[8];
    for (int a = tid; a < Ac; a += 256) {
        s_att2[a] = g_cb[(size_t)b * CBN + a] + bag[a];
        s_wf[a] = wf[a];
    }
    __syncthreads();
    int warp = tid >> 5, lane = tid & 31;
    float bfull = bf[0];
    for (int p = warp; p < Pc; p += 8) {
        const __half* rowp = g_att1h + ((size_t)b * Pc + p) * Ac;
        float s = 0.f;
#pragma unroll
        for (int i = 0; i < 2; i++) {
            int q = lane + i * 32;          // uint4 index (8 halves each)
            uint4 v = *(const uint4*)(rowp + q * 8);
            const __half2* hp = (const __half2*)&v;
            int a = q * 8;
#pragma unroll
            for (int j = 0; j < 4; j++) {
                float2 f = __half22float2(hp[j]);
                float x0 = f.x + s_att2[a + j * 2];
                float x1 = f.y + s_att2[a + j * 2 + 1];
                if (x0 > 0.f) s = fmaf(x0, s_wf[a + j * 2], s);
                if (x1 > 0.f) s = fmaf(x1, s_wf[a + j * 2 + 1], s);
            }
        }
#pragma unroll
        for (int o = 16; o; o >>= 1) s += __shfl_xor_sync(0xffffffff, s, o);
        if (lane == 0) s_e[p] = s + bfull;
    }
    __syncthreads();
    float e = (tid < Pc) ? s_e[tid] : -1e30f;
    float m = e;
#pragma unroll
    for (int o = 16; o; o >>= 1) m = fmaxf(m, __shfl_xor_sync(0xffffffff, m, o));
    if (lane == 0) s_red[warp] = m;
    __syncthreads();
    m = s_red[0];
#pragma unroll
    for (int w = 1; w < 8; w++) m = fmaxf(m, s_red[w]);
    float ex = (tid < Pc) ? expf(e - m) : 0.f;
    float sm = ex;
#pragma unroll
    for (int o = 16; o; o >>= 1) sm += __shfl_xor_sync(0xffffffff, sm, o);
    __syncthreads();
    if (lane == 0) s_red[warp] = sm;
    __syncthreads();
    sm = 0.f;
#pragma unroll
    for (int w = 0; w < 8; w++) sm += s_red[w];
    float inv = 1.0f / sm;
    if (tid < Pc) {
        float al = ex * inv;
        g_alpha[b * Pc + tid] = al;
        out_alpha[((size_t)b * Tc + t) * Pc + tid] = al;
    }
}

__device__ void softmax_dev(int b, const float* __restrict__ bo,
                            float* __restrict__ out_pred, int tsoft) {
    int tid = threadIdx.x;  // 256
    float4* dst = (float4*)(out_pred + ((size_t)b * Tc + tsoft) * Vc);
    const int NV4 = Vc / 4;
    if (tsoft >= g_ilen[b]) {
        float4 z = {0, 0, 0, 0};
        for (int i = tid; i < NV4; i += 256) dst[i] = z;
        return;
    }
    const float4* lg = (const float4*)(g_logits + (size_t)b * Vc);
    const float4* bo4 = (const float4*)bo;
    __shared__ float s_red2[8];
    int warp = tid >> 5, lane = tid & 31;
    float m = -1e30f;
    for (int i = tid; i < NV4; i += 256) {
        float4 a = lg[i], bb = bo4[i];
        float4 v = {a.x + bb.x, a.y + bb.y, a.z + bb.z, a.w + bb.w};
        dst[i] = v;
        m = fmaxf(m, fmaxf(fmaxf(v.x, v.y), fmaxf(v.z, v.w)));
    }
#pragma unroll
    for (int o = 16; o; o >>= 1) m = fmaxf(m, __shfl_xor_sync(0xffffffff, m, o));
    if (lane == 0) s_red2[warp] = m;
    __syncthreads();
    m = s_red2[0];
#pragma unroll
    for (int w = 1; w < 8; w++) m = fmaxf(m, s_red2[w]);
    float sum = 0.f;
    for (int i = tid; i < NV4; i += 256) {
        float4 v = dst[i];
        v.x = expf(v.x - m); v.y = expf(v.y - m);
        v.z = expf(v.z - m); v.w = expf(v.w - m);
        dst[i] = v;
        sum += v.x + v.y + v.z + v.w;
    }
#pragma unroll
    for (int o = 16; o; o >>= 1) sum += __shfl_xor_sync(0xffffffff, sum, o);
    __syncthreads();
    if (lane == 0) s_red2[warp] = sum;
    __syncthreads();
    sum = 0.f;
#pragma unroll
    for (int w = 0; w < 8; w++) sum += s_red2[w];
    float inv = 1.0f / sum;
    for (int i = tid; i < NV4; i += 256) {
        float4 v = dst[i];
        v.x *= inv; v.y *= inv; v.z *= inv; v.w *= inv;
        dst[i] = v;
    }
}

__global__ __launch_bounds__(256) void megaB_kernel(
    const float* __restrict__ bag, const float* __restrict__ wf,
    const float* __restrict__ bf, const float* __restrict__ bo,
    float* __restrict__ out_alpha, float* __restrict__ out_pred,
    int t, int do_attn, int do_soft, int tsoft) {
    if (blockIdx.x < 64) {
        if (do_attn) attn_dev(blockIdx.x, bag, wf, bf, out_alpha, t);
    } else {
        if (do_soft) softmax_dev(blockIdx.x - 64, bo, out_pred, tsoft);
    }
}

// ---------------- awe = (alpha . enc_fp16) * sigmoid(beta)  grid (64,2) -----------
__global__ __launch_bounds__(256) void awe_kernel(const float* __restrict__ bbeta, int t) {
    int b = blockIdx.x, tid = threadIdx.x;
    if (t >= g_ilen[b]) return;  // stale g_awe unused (masked in gates)
    __shared__ float s_al[Pc];
    if (tid < Pc) s_al[tid] = g_alpha[b * Pc + tid];
    __syncthreads();
    int e0 = blockIdx.y * 1024 + tid * 4;
    const __half* encb = g_ench + (size_t)b * Pc * ENCc + e0;
    float4 a0 = {0,0,0,0}, a1 = {0,0,0,0}, a2 = {0,0,0,0}, a3 = {0,0,0,0};
#pragma unroll 2
    for (int p = 0; p < Pc; p += 4) {
        float l0 = s_al[p + 0], l1 = s_al[p + 1], l2 = s_al[p + 2], l3 = s_al[p + 3];
        uint2 r0 = *(const uint2*)(encb + (size_t)(p + 0) * ENCc);
        uint2 r1 = *(const uint2*)(encb + (size_t)(p + 1) * ENCc);
        uint2 r2 = *(const uint2*)(encb + (size_t)(p + 2) * ENCc);
        uint2 r3 = *(const uint2*)(encb + (size_t)(p + 3) * ENCc);
        float2 f;
        f = __half22float2(*(__half2*)&r0.x); a0.x = fmaf(l0, f.x, a0.x); a0.y = fmaf(l0, f.y, a0.y);
        f = __half22float2(*(__half2*)&r0.y); a0.z = fmaf(l0, f.x, a0.z); a0.w = fmaf(l0, f.y, a0.w);
        f = __half22float2(*(__half2*)&r1.x); a1.x = fmaf(l1, f.x, a1.x); a1.y = fmaf(l1, f.y, a1.y);
        f = __half22float2(*(__half2*)&r1.y); a1.z = fmaf(l1, f.x, a1.z); a1.w = fmaf(l1, f.y, a1.w);
        f = __half22float2(*(__half2*)&r2.x); a2.x = fmaf(l2, f.x, a2.x); a2.y = fmaf(l2, f.y, a2.y);
        f = __half22float2(*(__half2*)&r2.y); a2.z = fmaf(l2, f.x, a2.z); a2.w = fmaf(l2, f.y, a2.w);
        f = __half22float2(*(__half2*)&r3.x); a3.x = fmaf(l3, f.x, a3.x); a3.y = fmaf(l3, f.y, a3.y);
        f = __half22float2(*(__half2*)&r3.y); a3.z = fmaf(l3, f.x, a3.z); a3.w = fmaf(l3, f.y, a3.w);
    }
    float4 s;
    s.x = a0.x + a1.x + a2.x + a3.x;
    s.y = a0.y + a1.y + a2.y + a3.y;
    s.z = a0.z + a1.z + a2.z + a3.z;
    s.w = a0.w + a1.w + a2.w + a3.w;
    float4 bl = *(const float4*)&bbeta[e0];
    float4 cbv = *(const float4*)&g_cb[(size_t)b * CBN + Ac + e0];
    bl.x += cbv.x; bl.y += cbv.y; bl.z += cbv.z; bl.w += cbv.w;
    float4 o;
    o.x = s.x / (1.0f + expf(-bl.x));
    o.y = s.y / (1.0f + expf(-bl.y));
    o.z = s.z / (1.0f + expf(-bl.z));
    o.w = s.w / (1.0f + expf(-bl.w));
    *(float4*)&g_awe[(size_t)b * ENCc + e0] = o;
}

// ---------------- LSTM gates from 6 partials + masked state update ---------------
__global__ void gates_kernel(const float* __restrict__ bl, int t) {
    int b = blockIdx.x, n = threadIdx.x;  // 512
    float zi = bl[n], zf = bl[Uc + n], zg = bl[2 * Uc + n], zo = bl[3 * Uc + n];
#pragma unroll
    for (int s = 0; s < 6; s++) {
        const float* zp = g_zp + ((size_t)s * Bc + b) * N4U;
        zi += zp[n];
        zf += zp[Uc + n];
        zg += zp[2 * Uc + n];
        zo += zp[3 * Uc + n];
    }
    float c_old = g_c[b * Uc + n], h_old = g_h[b * Uc + n];
    float si = 1.0f / (1.0f + expf(-zi));
    float sf = 1.0f / (1.0f + expf(-zf));
    float so = 1.0f / (1.0f + expf(-zo));
    float c_new = sf * c_old + si * tanhf(zg);
    float h_new = so * tanhf(c_new);
    bool mask = t < g_ilen[b];
    g_c[b * Uc + n] = mask ? c_new : c_old;
    g_h[b * Uc + n] = mask ? h_new : h_old;
}

// ---------------- launcher ---------------------------------------------------------
extern "C" void kernel_launch(void* const* d_in, const int* in_sizes, int n_in,
                              void* d_out, int out_size) {
    const float* enc      = (const float*)d_in[0];
    const int*   seqs     = (const int*)  d_in[1];
    const int*   lens     = (const int*)  d_in[2];
    const float* emb_tab  = (const float*)d_in[3];
    const float* W_ae     = (const float*)d_in[4];
    const float* b_ae     = (const float*)d_in[5];
    const float* W_ag     = (const float*)d_in[6];
    const float* b_ag     = (const float*)d_in[7];
    const float* W_af     = (const float*)d_in[8];
    const float* b_af     = (const float*)d_in[9];
    const float* W_x      = (const float*)d_in[10];
    const float* W_h      = (const float*)d_in[11];
    const float* b_lstm   = (const float*)d_in[12];
    const float* W_im     = (const float*)d_in[13];
    const float* b_im     = (const float*)d_in[14];
    const float* W_ic     = (const float*)d_in[15];
    const float* b_ic     = (const float*)d_in[16];
    const float* W_beta   = (const float*)d_in[17];
    const float* b_beta   = (const float*)d_in[18];
    const float* W_out    = (const float*)d_in[19];
    const float* b_out    = (const float*)d_in[20];

    float* out       = (float*)d_out;
    float* out_pred  = out;                                   // [B,T,V]
    float* out_alpha = out_pred + (size_t)Bc * Tc * Vc;       // [B,T,P]
    float* out_seqs  = out_alpha + (size_t)Bc * Tc * Pc;      // [B,S]
    float* out_ilen  = out_seqs + (size_t)Bc * Sc;            // [B]
    float* out_order = out_ilen + Bc;                         // [B]

    float *p_mean, *p_zp;
    __half *p_Waet, *p_Wcbt, *p_Woutt, *p_Wxt, *p_Wht;
    cudaGetSymbolAddress((void**)&p_mean, g_mean);
    cudaGetSymbolAddress((void**)&p_zp, g_zp);
    cudaGetSymbolAddress((void**)&p_Waet, g_Waet);
    cudaGetSymbolAddress((void**)&p_Wcbt, g_Wcbt);
    cudaGetSymbolAddress((void**)&p_Woutt, g_Woutt);
    cudaGetSymbolAddress((void**)&p_Wxt, g_Wxt);
    cudaGetSymbolAddress((void**)&p_Wht, g_Wht);

    // ---- setup ----
    sort_kernel<<<1, Bc>>>(lens, seqs, out_seqs, out_ilen, out_order);
    permute_kernel<<<dim3(Bc, Pc), 256>>>(enc);
    emb_all_kernel<<<dim3(Bc, Tc), 128>>>(emb_tab);
    mean_kernel<<<dim3(Bc, 2), 256>>>();
    // weight conversions (independent)
    convT_kernel<<<dim3(16, 64), 256>>>(W_ae, p_Waet, ENCc, Ac);
    convT_kernel<<<dim3(16, 16), 256>>>(W_ag, p_Wcbt, Uc, Ac);
    convT_kernel<<<dim3(64, 16), 256>>>(W_beta, p_Wcbt + (size_t)Ac * Uc, Uc, ENCc);
    convT_kernel<<<dim3(313, 16), 256>>>(W_out, p_Woutt, Uc, Vc);
    convT_kernel<<<dim3(64, 80), 256>>>(W_x, p_Wxt, KX, N4U);
    convT_kernel<<<dim3(64, 16), 256>>>(W_h, p_Wht, Uc, N4U);
    // h0/c0 partials into g_zp slices (stride Bc*Uc)
    gemm_k<<<dim3(Uc / 64, 1, 8), 256>>>(p_mean, ENCc, W_im, p_zp, ENCc, Uc, (size_t)Bc * Uc);
    gemm_k<<<dim3(Uc / 64, 1, 8), 256>>>(p_mean, ENCc, W_ic, p_zp + (size_t)8 * Bc * Uc, ENCc, Uc, (size_t)Bc * Uc);
    init_hc_kernel<<<Bc, Uc>>>(b_im, b_ic);
    // att1 (fp16 mma, fp16 output)
    att1h_kernel<<<dim3(Ac / 128, (Bc * Pc) / 64), 256>>>(b_ae);

    // ---- time steps ----
    for (int t = 0; t < Tc; t++) {
        int haveprev = (t > 0) ? 1 : 0;
        megaA_kernel<<<131, 256>>>(t, 1, haveprev);
        megaB_kernel<<<128, 256>>>(b_ag, W_af, b_af, b_out, out_alpha, out_pred,
                                   t, 1, haveprev, t - 1);
        awe_kernel<<<dim3(Bc, 2), 256>>>(b_beta, t);
        zawe_kernel<<<64, 256>>>();
        gates_kernel<<<Bc, Uc>>>(b_lstm, t);
    }
    // tail: logits + softmax for final step
    megaA_kernel<<<131, 256>>>(0, 0, 1);
    megaB_kernel<<<128, 256>>>(b_ag, W_af, b_af, b_out, out_alpha, out_pred,
                               0, 0, 1, Tc - 1);
}

// round 6
// speedup vs baseline: 2.3459x; 1.0261x over previous
#include <cuda_runtime.h>
#include <cuda_fp16.h>
#include <math.h>
#include <stdint.h>

// Problem dims
#define Bc   64
#define Pc   196
#define Sc   22
#define Tc   21
#define Vc   10000
#define Ec   512
#define Ac   512
#define Uc   512
#define ENCc 2048
#define N4U  2048   // 4*U
#define CBN  2560   // A + ENC (att2 | beta combined)
#define KX   2560   // E + ENC (W_x K dim)
#define NB   131    // persistent grid size (single wave on 148 SMs)

// ---------------- scratch (static __device__ arrays; no allocation) -------------
__device__ __half g_ench[Bc * Pc * ENCc];     // sorted encoder fp16 (51.4 MB)
__device__ __half g_att1h[Bc * Pc * Ac];      // att1 fp16 (12.8 MB)
__device__ __half g_Waet[Ac * ENCc];          // W_att_enc^T
__device__ __half g_Wcbt[CBN * Uc];           // [Wag|Wbeta]^T
__device__ __half g_Woutt[Vc * Uc];           // W_out^T
__device__ __half g_Wxt[N4U * KX];            // W_x^T
__device__ __half g_Wht[N4U * Uc];            // W_h^T
__device__ float g_mean[Bc * ENCc];
__device__ float g_h[Bc * Uc];
__device__ float g_c[Bc * Uc];
__device__ float g_cb[Bc * CBN];              // [att2 | beta-logits] (no bias)
__device__ float g_awe[Bc * ENCc];            // gated context
__device__ float g_zp[16 * Bc * Uc > 10 * Bc * N4U ? 16 * Bc * Uc : 10 * Bc * N4U];
__device__ float g_logits[Bc * Vc];           // logits (no bias)
__device__ float g_embAll[Tc * Bc * Ec];      // embeddings for all steps
__device__ int   g_order[Bc];
__device__ int   g_ilen[Bc];
__device__ int   g_seqs[Bc * Sc];

// ---------------- software grid barrier -------------------------------------------
__device__ int          g_bar_cnt = 0;
__device__ volatile int g_bar_gen = 0;

__device__ __forceinline__ void grid_bar() {
    __syncthreads();
    if (threadIdx.x == 0) {
        __threadfence();
        int gen = g_bar_gen;
        if (atomicAdd(&g_bar_cnt, 1) == NB - 1) {
            g_bar_cnt = 0;
            __threadfence();
            g_bar_gen = gen + 1;
        } else {
            while (g_bar_gen == gen) __nanosleep(32);
        }
        __threadfence();
    }
    __syncthreads();
}

// ---------------- sort: stable argsort(-lens) ------------------------------------
__global__ void sort_kernel(const int* __restrict__ lens,
                            const int* __restrict__ seqs,
                            float* __restrict__ out_seqs,
                            float* __restrict__ out_ilen,
                            float* __restrict__ out_order) {
    int tid = threadIdx.x;  // 64 threads
    __shared__ int s_len[Bc];
    s_len[tid] = lens[tid];
    __syncthreads();
    int myL = s_len[tid];
    int rank = 0;
    for (int j = 0; j < Bc; j++) {
        int lj = s_len[j];
        rank += (lj > myL) || (lj == myL && j < tid);
    }
    g_order[rank] = tid;
    __syncthreads();
    int src = g_order[tid];
    int il = s_len[src] - 1;
    g_ilen[tid] = il;
    out_ilen[tid] = (float)il;
    out_order[tid] = (float)src;
    for (int s = 0; s < Sc; s++) {
        int v = seqs[src * Sc + s];
        g_seqs[tid * Sc + s] = v;
        out_seqs[tid * Sc + s] = (float)v;
    }
}

// ---------------- permute encoder rows -> fp16 sorted copy ------------------------
__global__ void permute_kernel(const float* __restrict__ enc) {
    int b = blockIdx.x, p = blockIdx.y;
    int src = g_order[b];
    const float4* s = (const float4*)&enc[((size_t)src * Pc + p) * ENCc];
    __half2* dh = (__half2*)&g_ench[((size_t)b * Pc + p) * ENCc];
    for (int i = threadIdx.x; i < ENCc / 4; i += 256) {
        float4 v = s[i];
        dh[i * 2 + 0] = __floats2half2_rn(v.x, v.y);
        dh[i * 2 + 1] = __floats2half2_rn(v.z, v.w);
    }
}

// ---------------- transpose-convert weight fp32[K,N] -> fp16[N,K] ----------------
__global__ void convT_kernel(const float* __restrict__ in, __half* __restrict__ out,
                             int K, int N) {
    __shared__ float tile[32][33];
    int n0 = blockIdx.x * 32, k0 = blockIdx.y * 32;
    int tx = threadIdx.x & 31, ty = threadIdx.x >> 5;  // 256 thr
#pragma unroll
    for (int i = 0; i < 32; i += 8) {
        int k = k0 + ty + i, n = n0 + tx;
        tile[ty + i][tx] = (n < N) ? in[(size_t)k * N + n] : 0.f;
    }
    __syncthreads();
#pragma unroll
    for (int i = 0; i < 32; i += 8) {
        int n = n0 + ty + i;
        if (n < N) out[(size_t)n * K + k0 + tx] = __float2half(tile[tx][ty + i]);
    }
}

// ---------------- precompute embeddings for all timesteps ------------------------
__global__ void emb_all_kernel(const float* __restrict__ emb_table) {
    int b = blockIdx.x, t = blockIdx.y;  // 128 threads, float4
    int tok = g_seqs[b * Sc + t];
    float4 v = ((const float4*)(emb_table + (size_t)tok * Ec))[threadIdx.x];
    ((float4*)(g_embAll + ((size_t)t * Bc + b) * Ec))[threadIdx.x] = v;
}

// ---------------- mean over pixels (from fp16 copy, fp32 accum) -------------------
__global__ void mean_kernel() {
    int b = blockIdx.x;
    int e0 = blockIdx.y * 1024 + threadIdx.x * 4;
    const __half* encb = g_ench + (size_t)b * Pc * ENCc + e0;
    float4 a0 = {0,0,0,0}, a1 = {0,0,0,0};
#pragma unroll 2
    for (int p = 0; p < Pc; p += 2) {
        uint2 r0 = *(const uint2*)(encb + (size_t)(p + 0) * ENCc);
        uint2 r1 = *(const uint2*)(encb + (size_t)(p + 1) * ENCc);
        float2 f;
        f = __half22float2(*(__half2*)&r0.x); a0.x += f.x; a0.y += f.y;
        f = __half22float2(*(__half2*)&r0.y); a0.z += f.x; a0.w += f.y;
        f = __half22float2(*(__half2*)&r1.x); a1.x += f.x; a1.y += f.y;
        f = __half22float2(*(__half2*)&r1.y); a1.z += f.x; a1.w += f.y;
    }
    float4 r;
    r.x = (a0.x + a1.x) * (1.0f / Pc);
    r.y = (a0.y + a1.y) * (1.0f / Pc);
    r.z = (a0.z + a1.z) * (1.0f / Pc);
    r.w = (a0.w + a1.w) * (1.0f / Pc);
    *(float4*)(g_mean + (size_t)b * ENCc + e0) = r;
}

// ---------------- fp16 MMA helper --------------------------------------------------
__device__ __forceinline__ void mma_fp16(float* c, const uint32_t* a, const uint32_t* b) {
    asm volatile(
        "mma.sync.aligned.m16n8k16.row.col.f32.f16.f16.f32 "
        "{%0,%1,%2,%3}, {%4,%5,%6,%7}, {%8,%9}, {%0,%1,%2,%3};"
        : "+f"(c[0]), "+f"(c[1]), "+f"(c[2]), "+f"(c[3])
        : "r"(a[0]), "r"(a[1]), "r"(a[2]), "r"(a[3]), "r"(b[0]), "r"(b[1]));
}

// ---- 64x128-tile fp16 block GEMM (256 threads). smem passed in. -------------------
// AH: A is fp16[64][lda]; else fp32 (converted on load). HOUT: +bias, fp16 store.
template <bool HOUT, bool AH>
__device__ void fp16_block(const void* __restrict__ Av, int lda,
                           const __half* __restrict__ Wt, int ldk,
                           void* __restrict__ Cv, int ldc,
                           int K, int nguard, const float* __restrict__ bias,
                           __half* __restrict__ sA, __half* __restrict__ sW) {
    const int tid = threadIdx.x;
    const int warp = tid >> 5, lane = tid & 31;
    const int wm = (warp & 1) << 5;
    const int wn = (warp >> 1) << 5;

    float acc[2][4][4];
#pragma unroll
    for (int i = 0; i < 2; i++)
#pragma unroll
        for (int j = 0; j < 4; j++)
#pragma unroll
            for (int q = 0; q < 4; q++) acc[i][j][q] = 0.f;

    const int nr = tid >> 1, koff = (tid & 1) << 4;
    const bool wok = nr < nguard;

    for (int k0 = 0; k0 < K; k0 += 32) {
        __syncthreads();
        if (AH) {
            const __half* Ah = (const __half*)Av;
            int r = tid >> 2, kq = (tid & 3) << 3;
            *(uint4*)&sA[r * 40 + kq] = *(const uint4*)(Ah + (size_t)r * lda + k0 + kq);
        } else {
            const float* Af = (const float*)Av;
#pragma unroll
            for (int j = 0; j < 2; j++) {
                int idx = tid + j * 256;
                int r = idx >> 3, kq = (idx & 7) << 2;
                float4 v = *(const float4*)(Af + (size_t)r * lda + k0 + kq);
                *(__half2*)&sA[r * 40 + kq]     = __floats2half2_rn(v.x, v.y);
                *(__half2*)&sA[r * 40 + kq + 2] = __floats2half2_rn(v.z, v.w);
            }
        }
        if (wok) {
            const __half* wp = Wt + (size_t)nr * ldk + k0 + koff;
            *(uint4*)&sW[nr * 40 + koff]     = *(const uint4*)wp;
            *(uint4*)&sW[nr * 40 + koff + 8] = *(const uint4*)(wp + 8);
        } else {
            uint4 z = {0, 0, 0, 0};
            *(uint4*)&sW[nr * 40 + koff] = z;
            *(uint4*)&sW[nr * 40 + koff + 8] = z;
        }
        __syncthreads();
#pragma unroll
        for (int ks = 0; ks < 32; ks += 16) {
            const int gr = lane >> 2, gc = (lane & 3) << 1;
            uint32_t a[2][4], bb[4][2];
#pragma unroll
            for (int mi = 0; mi < 2; mi++) {
                int row = wm + mi * 16 + gr;
                a[mi][0] = *(const uint32_t*)&sA[row * 40 + ks + gc];
                a[mi][1] = *(const uint32_t*)&sA[(row + 8) * 40 + ks + gc];
                a[mi][2] = *(const uint32_t*)&sA[row * 40 + ks + gc + 8];
                a[mi][3] = *(const uint32_t*)&sA[(row + 8) * 40 + ks + gc + 8];
            }
#pragma unroll
            for (int nj = 0; nj < 4; nj++) {
                int n = wn + nj * 8 + gr;
                bb[nj][0] = *(const uint32_t*)&sW[n * 40 + ks + gc];
                bb[nj][1] = *(const uint32_t*)&sW[n * 40 + ks + gc + 8];
            }
#pragma unroll
            for (int mi = 0; mi < 2; mi++)
#pragma unroll
                for (int nj = 0; nj < 4; nj++)
                    mma_fp16(acc[mi][nj], a[mi], bb[nj]);
        }
    }
    const int gr = lane >> 2, cc = (lane & 3) << 1;
#pragma unroll
    for (int mi = 0; mi < 2; mi++) {
#pragma unroll
        for (int nj = 0; nj < 4; nj++) {
            int row = wm + mi * 16 + gr;
            int col = wn + nj * 8 + cc;
            if (col + 1 < nguard) {
                if (HOUT) {
                    float b0 = bias[col], b1 = bias[col + 1];
                    __half* Ch = (__half*)Cv;
                    *(__half2*)&Ch[(size_t)row * ldc + col] =
                        __floats2half2_rn(acc[mi][nj][0] + b0, acc[mi][nj][1] + b1);
                    *(__half2*)&Ch[(size_t)(row + 8) * ldc + col] =
                        __floats2half2_rn(acc[mi][nj][2] + b0, acc[mi][nj][3] + b1);
                } else {
                    float* C = (float*)Cv;
                    float2 o0 = {acc[mi][nj][0], acc[mi][nj][1]};
                    float2 o1 = {acc[mi][nj][2], acc[mi][nj][3]};
                    *(float2*)&C[(size_t)row * ldc + col] = o0;
                    *(float2*)&C[(size_t)(row + 8) * ldc + col] = o1;
                }
            }
        }
    }
}

// ---------------- att1 = ench @ W_ae + b_ae -> fp16 (standalone) -------------------
__global__ __launch_bounds__(256) void att1h_kernel(const float* __restrict__ bae) {
    __shared__ __align__(16) __half sA[64 * 40];
    __shared__ __align__(16) __half sW[128 * 40];
    int n0 = blockIdx.x * 128;
    int m0 = blockIdx.y * 64;
    fp16_block<true, true>(g_ench + (size_t)m0 * ENCc, ENCc,
                           g_Waet + (size_t)n0 * ENCc, ENCc,
                           g_att1h + (size_t)m0 * Ac + n0, Ac, ENCc, 128, bae + n0,
                           sA, sW);
}

// ---------------- fp32 GEMM for h0/c0 init (partials) -----------------------------
__global__ __launch_bounds__(256) void gemm_k(
    const float* __restrict__ A, int lda,
    const float* __restrict__ W,
    float* __restrict__ out,
    int K, int N, size_t part_stride) {
    __shared__ float As[16][68];
    __shared__ float Ws[16][68];
    const int tid = threadIdx.x;
    const int tx = tid & 15, ty = tid >> 4;
    const int n0 = blockIdx.x * 64;
    const int kchunk = K / gridDim.z;
    const int kbeg = blockIdx.z * kchunk;
    float* ob = out + (size_t)blockIdx.z * part_stride;

    const int lm = tid >> 2;
    const int lq = (tid & 3) << 2;
    const int wk = tid >> 4;
    const int wn = (tid & 15) << 2;

    float acc[4][4] = {};

    for (int k0 = kbeg; k0 < kbeg + kchunk; k0 += 16) {
        float4 av = *(const float4*)(A + (size_t)lm * lda + k0 + lq);
        float4 wv = *(const float4*)(W + (size_t)(k0 + wk) * N + n0 + wn);
        __syncthreads();
        As[lq + 0][lm] = av.x; As[lq + 1][lm] = av.y;
        As[lq + 2][lm] = av.z; As[lq + 3][lm] = av.w;
        *(float4*)&Ws[wk][wn] = wv;
        __syncthreads();
#pragma unroll
        for (int kk = 0; kk < 16; kk++) {
            float4 a = *(const float4*)&As[kk][ty << 2];
            float4 w = *(const float4*)&Ws[kk][tx << 2];
            acc[0][0] = fmaf(a.x, w.x, acc[0][0]); acc[0][1] = fmaf(a.x, w.y, acc[0][1]);
            acc[0][2] = fmaf(a.x, w.z, acc[0][2]); acc[0][3] = fmaf(a.x, w.w, acc[0][3]);
            acc[1][0] = fmaf(a.y, w.x, acc[1][0]); acc[1][1] = fmaf(a.y, w.y, acc[1][1]);
            acc[1][2] = fmaf(a.y, w.z, acc[1][2]); acc[1][3] = fmaf(a.y, w.w, acc[1][3]);
            acc[2][0] = fmaf(a.z, w.x, acc[2][0]); acc[2][1] = fmaf(a.z, w.y, acc[2][1]);
            acc[2][2] = fmaf(a.z, w.z, acc[2][2]); acc[2][3] = fmaf(a.z, w.w, acc[2][3]);
            acc[3][0] = fmaf(a.w, w.x, acc[3][0]); acc[3][1] = fmaf(a.w, w.y, acc[3][1]);
            acc[3][2] = fmaf(a.w, w.z, acc[3][2]); acc[3][3] = fmaf(a.w, w.w, acc[3][3]);
        }
    }
    const int c0 = n0 + (tx << 2);
#pragma unroll
    for (int i = 0; i < 4; i++) {
        int r = (ty << 2) + i;
        float4 o = {acc[i][0], acc[i][1], acc[i][2], acc[i][3]};
        *(float4*)&ob[(size_t)r * N + c0] = o;
    }
}

// ---------------- init h0/c0 from split-K partials + bias ------------------------
__global__ void init_hc_kernel(const float* __restrict__ bm, const float* __restrict__ bc) {
    int b = blockIdx.x, n = threadIdx.x;  // 512
    float h = bm[n], c = bc[n];
#pragma unroll
    for (int s = 0; s < 8; s++) {
        h += g_zp[((size_t)s * Bc + b) * Uc + n];
        c += g_zp[((size_t)(8 + s) * Bc + b) * Uc + n];
    }
    g_h[b * Uc + n] = h;
    g_c[b * Uc + n] = c;
}

// ---------------- device: attention + softmax + awe (fused, one block per b) ------
__device__ void attn_awe_dev(int b, char* smem,
                             const float* __restrict__ bag,
                             const float* __restrict__ wf,
                             const float* __restrict__ bf,
                             const float* __restrict__ bbeta,
                             float* __restrict__ out_alpha, int t) {
    int tid = threadIdx.x;  // 256
    if (t >= g_ilen[b]) {
        if (tid < Pc) out_alpha[((size_t)b * Tc + t) * Pc + tid] = 0.f;
        return;
    }
    float* s_att2 = (float*)smem;           // 512
    float* s_wf   = s_att2 + 512;           // 512
    float* s_e    = s_wf + 512;             // 200
    float* s_red  = s_e + 200;              // 8
    for (int a = tid; a < Ac; a += 256) {
        s_att2[a] = g_cb[(size_t)b * CBN + a] + bag[a];
        s_wf[a] = wf[a];
    }
    __syncthreads();
    int warp = tid >> 5, lane = tid & 31;
    float bfull = bf[0];
    for (int p = warp; p < Pc; p += 8) {
        const __half* rowp = g_att1h + ((size_t)b * Pc + p) * Ac;
        float s = 0.f;
#pragma unroll
        for (int i = 0; i < 2; i++) {
            int q = lane + i * 32;
            uint4 v = *(const uint4*)(rowp + q * 8);
            const __half2* hp = (const __half2*)&v;
            int a = q * 8;
#pragma unroll
            for (int j = 0; j < 4; j++) {
                float2 f = __half22float2(hp[j]);
                float x0 = f.x + s_att2[a + j * 2];
                float x1 = f.y + s_att2[a + j * 2 + 1];
                if (x0 > 0.f) s = fmaf(x0, s_wf[a + j * 2], s);
                if (x1 > 0.f) s = fmaf(x1, s_wf[a + j * 2 + 1], s);
            }
        }
#pragma unroll
        for (int o = 16; o; o >>= 1) s += __shfl_xor_sync(0xffffffff, s, o);
        if (lane == 0) s_e[p] = s + bfull;
    }
    __syncthreads();
    float e = (tid < Pc) ? s_e[tid] : -1e30f;
    float m = e;
#pragma unroll
    for (int o = 16; o; o >>= 1) m = fmaxf(m, __shfl_xor_sync(0xffffffff, m, o));
    if (lane == 0) s_red[warp] = m;
    __syncthreads();
    m = s_red[0];
#pragma unroll
    for (int w = 1; w < 8; w++) m = fmaxf(m, s_red[w]);
    float ex = (tid < Pc) ? expf(e - m) : 0.f;
    float sm = ex;
#pragma unroll
    for (int o = 16; o; o >>= 1) sm += __shfl_xor_sync(0xffffffff, sm, o);
    __syncthreads();
    if (lane == 0) s_red[warp] = sm;
    __syncthreads();
    sm = 0.f;
#pragma unroll
    for (int w = 0; w < 8; w++) sm += s_red[w];
    float inv = 1.0f / sm;
    __syncthreads();
    if (tid < Pc) {
        float al = ex * inv;
        s_e[tid] = al;
        out_alpha[((size_t)b * Tc + t) * Pc + tid] = al;
    }
    __syncthreads();
    // awe: each thread owns 8 contiguous ENC elements
    int e0 = tid * 8;
    const __half* encb = g_ench + (size_t)b * Pc * ENCc + e0;
    float acc[8] = {};
#pragma unroll 2
    for (int p = 0; p < Pc; p += 2) {
        float l0 = s_e[p], l1 = s_e[p + 1];
        uint4 v0 = *(const uint4*)(encb + (size_t)p * ENCc);
        uint4 v1 = *(const uint4*)(encb + (size_t)(p + 1) * ENCc);
        const __half2* h0 = (const __half2*)&v0;
        const __half2* h1 = (const __half2*)&v1;
#pragma unroll
        for (int j = 0; j < 4; j++) {
            float2 f0 = __half22float2(h0[j]);
            float2 f1 = __half22float2(h1[j]);
            acc[2*j]   = fmaf(l0, f0.x, acc[2*j]);
            acc[2*j+1] = fmaf(l0, f0.y, acc[2*j+1]);
            acc[2*j]   = fmaf(l1, f1.x, acc[2*j]);
            acc[2*j+1] = fmaf(l1, f1.y, acc[2*j+1]);
        }
    }
#pragma unroll
    for (int j = 0; j < 8; j += 4) {
        float4 bl = *(const float4*)&bbeta[e0 + j];
        float4 cbv = *(const float4*)&g_cb[(size_t)b * CBN + Ac + e0 + j];
        bl.x += cbv.x; bl.y += cbv.y; bl.z += cbv.z; bl.w += cbv.w;
        float4 o;
        o.x = acc[j+0] / (1.0f + expf(-bl.x));
        o.y = acc[j+1] / (1.0f + expf(-bl.y));
        o.z = acc[j+2] / (1.0f + expf(-bl.z));
        o.w = acc[j+3] / (1.0f + expf(-bl.w));
        *(float4*)&g_awe[(size_t)b * ENCc + e0 + j] = o;
    }
}

// ---------------- device: vocab softmax (bias added here), masked -----------------
__device__ void softmax_dev(int b, char* smem, const float* __restrict__ bo,
                            float* __restrict__ out_pred, int tsoft) {
    int tid = threadIdx.x;  // 256
    float4* dst = (float4*)(out_pred + ((size_t)b * Tc + tsoft) * Vc);
    const int NV4 = Vc / 4;
    if (tsoft >= g_ilen[b]) {
        float4 z = {0, 0, 0, 0};
        for (int i = tid; i < NV4; i += 256) dst[i] = z;
        return;
    }
    const float4* lg = (const float4*)(g_logits + (size_t)b * Vc);
    const float4* bo4 = (const float4*)bo;
    float* s_red = (float*)smem;
    int warp = tid >> 5, lane = tid & 31;
    float m = -1e30f;
    for (int i = tid; i < NV4; i += 256) {
        float4 a = lg[i], bb = bo4[i];
        float4 v = {a.x + bb.x, a.y + bb.y, a.z + bb.z, a.w + bb.w};
        dst[i] = v;
        m = fmaxf(m, fmaxf(fmaxf(v.x, v.y), fmaxf(v.z, v.w)));
    }
#pragma unroll
    for (int o = 16; o; o >>= 1) m = fmaxf(m, __shfl_xor_sync(0xffffffff, m, o));
    if (lane == 0) s_red[warp] = m;
    __syncthreads();
    m = s_red[0];
#pragma unroll
    for (int w = 1; w < 8; w++) m = fmaxf(m, s_red[w]);
    float sum = 0.f;
    for (int i = tid; i < NV4; i += 256) {
        float4 v = dst[i];
        v.x = expf(v.x - m); v.y = expf(v.y - m);
        v.z = expf(v.z - m); v.w = expf(v.w - m);
        dst[i] = v;
        sum += v.x + v.y + v.z + v.w;
    }
#pragma unroll
    for (int o = 16; o; o >>= 1) sum += __shfl_xor_sync(0xffffffff, sum, o);
    __syncthreads();
    if (lane == 0) s_red[warp] = sum;
    __syncthreads();
    sum = 0.f;
#pragma unroll
    for (int w = 0; w < 8; w++) sum += s_red[w];
    float inv = 1.0f / sum;
    for (int i = tid; i < NV4; i += 256) {
        float4 v = dst[i];
        v.x *= inv; v.y *= inv; v.z *= inv; v.w *= inv;
        dst[i] = v;
    }
}

// ================= persistent loop kernel (131 blocks, 256 threads) ===============
__global__ __launch_bounds__(256) void loop_kernel(
    const float* __restrict__ bag, const float* __restrict__ wf,
    const float* __restrict__ bf, const float* __restrict__ bbeta,
    const float* __restrict__ bl, const float* __restrict__ bo,
    float* __restrict__ out_alpha, float* __restrict__ out_pred) {
    __shared__ __align__(16) char smem[15872];
    __half* sA = (__half*)smem;                 // 64*40 halves
    __half* sW = (__half*)(smem + 64 * 40 * 2); // 128*40 halves
    const int blk = blockIdx.x;
    const int tid = threadIdx.x;

    for (int t = 0; t < Tc; t++) {
        // ---- Phase 1: cb | logits(t-1) | z_emb | z_h ----
        if (blk < 20) {
            int n0 = blk * 128;
            fp16_block<false, false>(g_c, Uc, g_Wcbt + (size_t)n0 * Uc, Uc,
                                     g_cb + n0, CBN, Uc, 128, nullptr, sA, sW);
        } else if (blk < 99) {
            if (t > 0) {
                int n0 = (blk - 20) * 128;
                int ng = Vc - n0; if (ng > 128) ng = 128;
                fp16_block<false, false>(g_c, Uc, g_Woutt + (size_t)n0 * Uc, Uc,
                                         g_logits + n0, Vc, Uc, ng, nullptr, sA, sW);
            }
        } else if (blk < 115) {
            int n0 = (blk - 99) * 128;
            fp16_block<false, false>(g_embAll + (size_t)t * Bc * Ec, Ec,
                                     g_Wxt + (size_t)n0 * KX, KX,
                                     g_zp + 0 * (size_t)Bc * N4U + n0, N4U, Ec, 128,
                                     nullptr, sA, sW);
        } else {
            int n0 = (blk - 115) * 128;
            fp16_block<false, false>(g_h, Uc, g_Wht + (size_t)n0 * Uc, Uc,
                                     g_zp + 1 * (size_t)Bc * N4U + n0, N4U, Uc, 128,
                                     nullptr, sA, sW);
        }
        grid_bar();
        // ---- Phase 2: attn+awe(t) | softmax(t-1) ----
        if (blk < 64) {
            attn_awe_dev(blk, smem, bag, wf, bf, bbeta, out_alpha, t);
        } else if (blk < 128) {
            if (t > 0) softmax_dev(blk - 64, smem, bo, out_pred, t - 1);
        }
        grid_bar();
        // ---- Phase 3: z_awe, 8 k-splits x 16 n-tiles ----
        if (blk < 128) {
            int sp = blk >> 4, n0 = (blk & 15) * 128;
            fp16_block<false, false>(g_awe + sp * 256, ENCc,
                                     g_Wxt + (size_t)n0 * KX + Ec + sp * 256, KX,
                                     g_zp + (size_t)(2 + sp) * Bc * N4U + n0, N4U,
                                     256, 128, nullptr, sA, sW);
        }
        grid_bar();
        // ---- Phase 4: gates ----
        if (blk < 64) {
            int b = blk;
#pragma unroll
            for (int i = 0; i < 2; i++) {
                int n = tid + i * 256;
                float zi = bl[n], zf = bl[Uc + n], zg = bl[2 * Uc + n], zo = bl[3 * Uc + n];
#pragma unroll
                for (int s = 0; s < 10; s++) {
                    const float* zp = g_zp + ((size_t)s * Bc + b) * N4U;
                    zi += zp[n];
                    zf += zp[Uc + n];
                    zg += zp[2 * Uc + n];
                    zo += zp[3 * Uc + n];
                }
                float c_old = g_c[b * Uc + n], h_old = g_h[b * Uc + n];
                float si = 1.0f / (1.0f + expf(-zi));
                float sf = 1.0f / (1.0f + expf(-zf));
                float so = 1.0f / (1.0f + expf(-zo));
                float c_new = sf * c_old + si * tanhf(zg);
                float h_new = so * tanhf(c_new);
                bool mask = t < g_ilen[b];
                g_c[b * Uc + n] = mask ? c_new : c_old;
                g_h[b * Uc + n] = mask ? h_new : h_old;
            }
        }
        grid_bar();
    }
    // ---- tail: logits + softmax for the final step ----
    if (blk >= 20 && blk < 99) {
        int n0 = (blk - 20) * 128;
        int ng = Vc - n0; if (ng > 128) ng = 128;
        fp16_block<false, false>(g_c, Uc, g_Woutt + (size_t)n0 * Uc, Uc,
                                 g_logits + n0, Vc, Uc, ng, nullptr, sA, sW);
    }
    grid_bar();
    if (blk >= 64 && blk < 128) softmax_dev(blk - 64, smem, bo, out_pred, Tc - 1);
}

// ---------------- launcher ---------------------------------------------------------
extern "C" void kernel_launch(void* const* d_in, const int* in_sizes, int n_in,
                              void* d_out, int out_size) {
    const float* enc      = (const float*)d_in[0];
    const int*   seqs     = (const int*)  d_in[1];
    const int*   lens     = (const int*)  d_in[2];
    const float* emb_tab  = (const float*)d_in[3];
    const float* W_ae     = (const float*)d_in[4];
    const float* b_ae     = (const float*)d_in[5];
    const float* W_ag     = (const float*)d_in[6];
    const float* b_ag     = (const float*)d_in[7];
    const float* W_af     = (const float*)d_in[8];
    const float* b_af     = (const float*)d_in[9];
    const float* W_x      = (const float*)d_in[10];
    const float* W_h      = (const float*)d_in[11];
    const float* b_lstm   = (const float*)d_in[12];
    const float* W_im     = (const float*)d_in[13];
    const float* b_im     = (const float*)d_in[14];
    const float* W_ic     = (const float*)d_in[15];
    const float* b_ic     = (const float*)d_in[16];
    const float* W_beta   = (const float*)d_in[17];
    const float* b_beta   = (const float*)d_in[18];
    const float* W_out    = (const float*)d_in[19];
    const float* b_out    = (const float*)d_in[20];

    float* out       = (float*)d_out;
    float* out_pred  = out;                                   // [B,T,V]
    float* out_alpha = out_pred + (size_t)Bc * Tc * Vc;       // [B,T,P]
    float* out_seqs  = out_alpha + (size_t)Bc * Tc * Pc;      // [B,S]
    float* out_ilen  = out_seqs + (size_t)Bc * Sc;            // [B]
    float* out_order = out_ilen + Bc;                         // [B]

    float *p_mean, *p_zp;
    __half *p_Waet, *p_Wcbt, *p_Woutt, *p_Wxt, *p_Wht;
    cudaGetSymbolAddress((void**)&p_mean, g_mean);
    cudaGetSymbolAddress((void**)&p_zp, g_zp);
    cudaGetSymbolAddress((void**)&p_Waet, g_Waet);
    cudaGetSymbolAddress((void**)&p_Wcbt, g_Wcbt);
    cudaGetSymbolAddress((void**)&p_Woutt, g_Woutt);
    cudaGetSymbolAddress((void**)&p_Wxt, g_Wxt);
    cudaGetSymbolAddress((void**)&p_Wht, g_Wht);

    // ---- setup ----
    sort_kernel<<<1, Bc>>>(lens, seqs, out_seqs, out_ilen, out_order);
    permute_kernel<<<dim3(Bc, Pc), 256>>>(enc);
    emb_all_kernel<<<dim3(Bc, Tc), 128>>>(emb_tab);
    mean_kernel<<<dim3(Bc, 2), 256>>>();
    convT_kernel<<<dim3(16, 64), 256>>>(W_ae, p_Waet, ENCc, Ac);
    convT_kernel<<<dim3(16, 16), 256>>>(W_ag, p_Wcbt, Uc, Ac);
    convT_kernel<<<dim3(64, 16), 256>>>(W_beta, p_Wcbt + (size_t)Ac * Uc, Uc, ENCc);
    convT_kernel<<<dim3(313, 16), 256>>>(W_out, p_Woutt, Uc, Vc);
    convT_kernel<<<dim3(64, 80), 256>>>(W_x, p_Wxt, KX, N4U);
    convT_kernel<<<dim3(64, 16), 256>>>(W_h, p_Wht, Uc, N4U);
    gemm_k<<<dim3(Uc / 64, 1, 8), 256>>>(p_mean, ENCc, W_im, p_zp, ENCc, Uc, (size_t)Bc * Uc);
    gemm_k<<<dim3(Uc / 64, 1, 8), 256>>>(p_mean, ENCc, W_ic, p_zp + (size_t)8 * Bc * Uc, ENCc, Uc, (size_t)Bc * Uc);
    init_hc_kernel<<<Bc, Uc>>>(b_im, b_ic);
    att1h_kernel<<<dim3(Ac / 128, (Bc * Pc) / 64), 256>>>(b_ae);

    // ---- whole time loop in ONE persistent kernel ----
    loop_kernel<<<NB, 256>>>(b_ag, W_af, b_af, b_beta, b_lstm, b_out,
                             out_alpha, out_pred);
}

// round 7
// speedup vs baseline: 2.8203x; 1.2022x over previous
#include <cuda_runtime.h>
#include <cuda_fp16.h>
#include <math.h>
#include <stdint.h>

// Problem dims
#define Bc   64
#define Pc   196
#define Sc   22
#define Tc   21
#define Vc   10000
#define Ec   512
#define Ac   512
#define Uc   512
#define ENCc 2048
#define N4U  2048   // 4*U
#define CBN  2560   // A + ENC (att2 | beta combined)
#define KX   2560   // E + ENC (W_x K dim)
#define NB   131    // persistent grid size (single wave on 148 SMs)

// ---------------- scratch (static __device__ arrays; no allocation) -------------
__device__ __half g_ench[Bc * Pc * ENCc];     // sorted encoder fp16 (51.4 MB)
__device__ __half g_att1h[Bc * Pc * Ac];      // att1 fp16 (12.8 MB)
__device__ __half g_Waet[Ac * ENCc];          // W_att_enc^T
__device__ __half g_Wcbt[CBN * Uc];           // [Wag|Wbeta]^T
__device__ __half g_Woutt[Vc * Uc];           // W_out^T
__device__ __half g_Wxt[N4U * KX];            // W_x^T
__device__ __half g_Wht[N4U * Uc];            // W_h^T
__device__ __half g_embh[Tc * Bc * Ec];       // embeddings fp16, all steps
__device__ __half g_ch[Bc * Uc];              // c fp16 (GEMM A operand)
__device__ __half g_hh[Bc * Uc];              // h fp16
__device__ __half g_aweh[Bc * ENCc];          // gated context fp16
__device__ float g_mean[Bc * ENCc];
__device__ float g_h[Bc * Uc];
__device__ float g_c[Bc * Uc];
__device__ float g_alpha[Bc * Pc];
__device__ float g_cb[Bc * CBN];              // [att2 | beta-logits] (no bias)
__device__ float g_zp[16 * Bc * Uc > 10 * Bc * N4U ? 16 * Bc * Uc : 10 * Bc * N4U];
__device__ float g_logits[Bc * Vc];           // logits (no bias)
__device__ int   g_order[Bc];
__device__ int   g_ilen[Bc];
__device__ int   g_seqs[Bc * Sc];

// ---------------- software grid barrier -------------------------------------------
__device__ int          g_bar_cnt = 0;
__device__ volatile int g_bar_gen = 0;

__device__ __forceinline__ void grid_bar() {
    __syncthreads();
    if (threadIdx.x == 0) {
        __threadfence();
        int gen = g_bar_gen;
        if (atomicAdd(&g_bar_cnt, 1) == NB - 1) {
            g_bar_cnt = 0;
            __threadfence();
            g_bar_gen = gen + 1;
        } else {
            while (g_bar_gen == gen) __nanosleep(16);
        }
        __threadfence();
    }
    __syncthreads();
}

// ---------------- sort: stable argsort(-lens) ------------------------------------
__global__ void sort_kernel(const int* __restrict__ lens,
                            const int* __restrict__ seqs,
                            float* __restrict__ out_seqs,
                            float* __restrict__ out_ilen,
                            float* __restrict__ out_order) {
    int tid = threadIdx.x;  // 64 threads
    __shared__ int s_len[Bc];
    s_len[tid] = lens[tid];
    __syncthreads();
    int myL = s_len[tid];
    int rank = 0;
    for (int j = 0; j < Bc; j++) {
        int lj = s_len[j];
        rank += (lj > myL) || (lj == myL && j < tid);
    }
    g_order[rank] = tid;
    __syncthreads();
    int src = g_order[tid];
    int il = s_len[src] - 1;
    g_ilen[tid] = il;
    out_ilen[tid] = (float)il;
    out_order[tid] = (float)src;
    for (int s = 0; s < Sc; s++) {
        int v = seqs[src * Sc + s];
        g_seqs[tid * Sc + s] = v;
        out_seqs[tid * Sc + s] = (float)v;
    }
}

// ---------------- permute encoder rows -> fp16 sorted copy ------------------------
__global__ void permute_kernel(const float* __restrict__ enc) {
    int b = blockIdx.x, p = blockIdx.y;
    int src = g_order[b];
    const float4* s = (const float4*)&enc[((size_t)src * Pc + p) * ENCc];
    __half2* dh = (__half2*)&g_ench[((size_t)b * Pc + p) * ENCc];
    for (int i = threadIdx.x; i < ENCc / 4; i += 256) {
        float4 v = s[i];
        dh[i * 2 + 0] = __floats2half2_rn(v.x, v.y);
        dh[i * 2 + 1] = __floats2half2_rn(v.z, v.w);
    }
}

// ---------------- transpose-convert weight fp32[K,N] -> fp16[N,K] ----------------
__global__ void convT_kernel(const float* __restrict__ in, __half* __restrict__ out,
                             int K, int N) {
    __shared__ float tile[32][33];
    int n0 = blockIdx.x * 32, k0 = blockIdx.y * 32;
    int tx = threadIdx.x & 31, ty = threadIdx.x >> 5;  // 256 thr
#pragma unroll
    for (int i = 0; i < 32; i += 8) {
        int k = k0 + ty + i, n = n0 + tx;
        tile[ty + i][tx] = (n < N) ? in[(size_t)k * N + n] : 0.f;
    }
    __syncthreads();
#pragma unroll
    for (int i = 0; i < 32; i += 8) {
        int n = n0 + ty + i;
        if (n < N) out[(size_t)n * K + k0 + tx] = __float2half(tile[tx][ty + i]);
    }
}

// ---------------- precompute embeddings (fp16) for all timesteps ------------------
__global__ void emb_all_kernel(const float* __restrict__ emb_table) {
    int b = blockIdx.x, t = blockIdx.y;  // 128 threads
    int tok = g_seqs[b * Sc + t];
    float4 v = ((const float4*)(emb_table + (size_t)tok * Ec))[threadIdx.x];
    __half2 h0 = __floats2half2_rn(v.x, v.y);
    __half2 h1 = __floats2half2_rn(v.z, v.w);
    __half2* dst = (__half2*)(g_embh + ((size_t)t * Bc + b) * Ec);
    dst[threadIdx.x * 2 + 0] = h0;
    dst[threadIdx.x * 2 + 1] = h1;
}

// ---------------- mean over pixels (from fp16 copy, fp32 accum) -------------------
__global__ void mean_kernel() {
    int b = blockIdx.x;
    int e0 = blockIdx.y * 1024 + threadIdx.x * 4;
    const __half* encb = g_ench + (size_t)b * Pc * ENCc + e0;
    float4 a0 = {0,0,0,0}, a1 = {0,0,0,0};
#pragma unroll 2
    for (int p = 0; p < Pc; p += 2) {
        uint2 r0 = *(const uint2*)(encb + (size_t)(p + 0) * ENCc);
        uint2 r1 = *(const uint2*)(encb + (size_t)(p + 1) * ENCc);
        float2 f;
        f = __half22float2(*(__half2*)&r0.x); a0.x += f.x; a0.y += f.y;
        f = __half22float2(*(__half2*)&r0.y); a0.z += f.x; a0.w += f.y;
        f = __half22float2(*(__half2*)&r1.x); a1.x += f.x; a1.y += f.y;
        f = __half22float2(*(__half2*)&r1.y); a1.z += f.x; a1.w += f.y;
    }
    float4 r;
    r.x = (a0.x + a1.x) * (1.0f / Pc);
    r.y = (a0.y + a1.y) * (1.0f / Pc);
    r.z = (a0.z + a1.z) * (1.0f / Pc);
    r.w = (a0.w + a1.w) * (1.0f / Pc);
    *(float4*)(g_mean + (size_t)b * ENCc + e0) = r;
}

// ---------------- fp16 MMA helper --------------------------------------------------
__device__ __forceinline__ void mma_fp16(float* c, const uint32_t* a, const uint32_t* b) {
    asm volatile(
        "mma.sync.aligned.m16n8k16.row.col.f32.f16.f16.f32 "
        "{%0,%1,%2,%3}, {%4,%5,%6,%7}, {%8,%9}, {%0,%1,%2,%3};"
        : "+f"(c[0]), "+f"(c[1]), "+f"(c[2]), "+f"(c[3])
        : "r"(a[0]), "r"(a[1]), "r"(a[2]), "r"(a[3]), "r"(b[0]), "r"(b[1]));
}

// ---- 64x128-tile fp16 GEMM, register-prefetch double-buffered --------------------
// C[64, nguard] = A(fp16)[64][lda] @ Wt(fp16)[n][ldk].  256 threads.
template <bool HOUT>
__device__ void fp16_gemm(const __half* __restrict__ A, int lda,
                          const __half* __restrict__ Wt, int ldk,
                          void* __restrict__ Cv, int ldc,
                          int K, int nguard, const float* __restrict__ bias,
                          __half* __restrict__ sA, __half* __restrict__ sW) {
    const int tid = threadIdx.x;
    const int warp = tid >> 5, lane = tid & 31;
    const int wm = (warp & 1) << 5;
    const int wn = (warp >> 1) << 5;

    float acc[2][4][4];
#pragma unroll
    for (int i = 0; i < 2; i++)
#pragma unroll
        for (int j = 0; j < 4; j++)
#pragma unroll
            for (int q = 0; q < 4; q++) acc[i][j][q] = 0.f;

    const int ar = tid >> 2, akq = (tid & 3) << 3;   // A row, k-offset (uint4 = 8 halves)
    const int nr = tid >> 1, koff = (tid & 1) << 4;  // W n-row, k-offset (2 uint4)
    const bool wok = nr < nguard;

    uint4 a_reg = *(const uint4*)(A + (size_t)ar * lda + akq);
    uint4 w_reg0 = {0, 0, 0, 0}, w_reg1 = {0, 0, 0, 0};
    if (wok) {
        const __half* wp = Wt + (size_t)nr * ldk + koff;
        w_reg0 = *(const uint4*)wp;
        w_reg1 = *(const uint4*)(wp + 8);
    }

    for (int k0 = 0; k0 < K; k0 += 32) {
        __syncthreads();
        *(uint4*)&sA[ar * 40 + akq] = a_reg;
        *(uint4*)&sW[nr * 40 + koff] = w_reg0;
        *(uint4*)&sW[nr * 40 + koff + 8] = w_reg1;
        __syncthreads();
        int k1 = k0 + 32;
        if (k1 < K) {
            a_reg = *(const uint4*)(A + (size_t)ar * lda + k1 + akq);
            if (wok) {
                const __half* wp = Wt + (size_t)nr * ldk + k1 + koff;
                w_reg0 = *(const uint4*)wp;
                w_reg1 = *(const uint4*)(wp + 8);
            }
        }
#pragma unroll
        for (int ks = 0; ks < 32; ks += 16) {
            const int gr = lane >> 2, gc = (lane & 3) << 1;
            uint32_t a[2][4], bb[4][2];
#pragma unroll
            for (int mi = 0; mi < 2; mi++) {
                int row = wm + mi * 16 + gr;
                a[mi][0] = *(const uint32_t*)&sA[row * 40 + ks + gc];
                a[mi][1] = *(const uint32_t*)&sA[(row + 8) * 40 + ks + gc];
                a[mi][2] = *(const uint32_t*)&sA[row * 40 + ks + gc + 8];
                a[mi][3] = *(const uint32_t*)&sA[(row + 8) * 40 + ks + gc + 8];
            }
#pragma unroll
            for (int nj = 0; nj < 4; nj++) {
                int n = wn + nj * 8 + gr;
                bb[nj][0] = *(const uint32_t*)&sW[n * 40 + ks + gc];
                bb[nj][1] = *(const uint32_t*)&sW[n * 40 + ks + gc + 8];
            }
#pragma unroll
            for (int mi = 0; mi < 2; mi++)
#pragma unroll
                for (int nj = 0; nj < 4; nj++)
                    mma_fp16(acc[mi][nj], a[mi], bb[nj]);
        }
    }
    const int gr = lane >> 2, cc = (lane & 3) << 1;
#pragma unroll
    for (int mi = 0; mi < 2; mi++) {
#pragma unroll
        for (int nj = 0; nj < 4; nj++) {
            int row = wm + mi * 16 + gr;
            int col = wn + nj * 8 + cc;
            if (col + 1 < nguard) {
                if (HOUT) {
                    float b0 = bias[col], b1 = bias[col + 1];
                    __half* Ch = (__half*)Cv;
                    *(__half2*)&Ch[(size_t)row * ldc + col] =
                        __floats2half2_rn(acc[mi][nj][0] + b0, acc[mi][nj][1] + b1);
                    *(__half2*)&Ch[(size_t)(row + 8) * ldc + col] =
                        __floats2half2_rn(acc[mi][nj][2] + b0, acc[mi][nj][3] + b1);
                } else {
                    float* C = (float*)Cv;
                    float2 o0 = {acc[mi][nj][0], acc[mi][nj][1]};
                    float2 o1 = {acc[mi][nj][2], acc[mi][nj][3]};
                    *(float2*)&C[(size_t)row * ldc + col] = o0;
                    *(float2*)&C[(size_t)(row + 8) * ldc + col] = o1;
                }
            }
        }
    }
}

// ---------------- att1 = ench @ W_ae + b_ae -> fp16 (standalone) -------------------
__global__ __launch_bounds__(256) void att1h_kernel(const float* __restrict__ bae) {
    __shared__ __align__(16) __half sA[64 * 40];
    __shared__ __align__(16) __half sW[128 * 40];
    int n0 = blockIdx.x * 128;
    int m0 = blockIdx.y * 64;
    fp16_gemm<true>(g_ench + (size_t)m0 * ENCc, ENCc,
                    g_Waet + (size_t)n0 * ENCc, ENCc,
                    g_att1h + (size_t)m0 * Ac + n0, Ac, ENCc, 128, bae + n0,
                    sA, sW);
}

// ---------------- fp32 GEMM for h0/c0 init (partials) -----------------------------
__global__ __launch_bounds__(256) void gemm_k(
    const float* __restrict__ A, int lda,
    const float* __restrict__ W,
    float* __restrict__ out,
    int K, int N, size_t part_stride) {
    __shared__ float As[16][68];
    __shared__ float Ws[16][68];
    const int tid = threadIdx.x;
    const int tx = tid & 15, ty = tid >> 4;
    const int n0 = blockIdx.x * 64;
    const int kchunk = K / gridDim.z;
    const int kbeg = blockIdx.z * kchunk;
    float* ob = out + (size_t)blockIdx.z * part_stride;

    const int lm = tid >> 2;
    const int lq = (tid & 3) << 2;
    const int wk = tid >> 4;
    const int wn = (tid & 15) << 2;

    float acc[4][4] = {};

    for (int k0 = kbeg; k0 < kbeg + kchunk; k0 += 16) {
        float4 av = *(const float4*)(A + (size_t)lm * lda + k0 + lq);
        float4 wv = *(const float4*)(W + (size_t)(k0 + wk) * N + n0 + wn);
        __syncthreads();
        As[lq + 0][lm] = av.x; As[lq + 1][lm] = av.y;
        As[lq + 2][lm] = av.z; As[lq + 3][lm] = av.w;
        *(float4*)&Ws[wk][wn] = wv;
        __syncthreads();
#pragma unroll
        for (int kk = 0; kk < 16; kk++) {
            float4 a = *(const float4*)&As[kk][ty << 2];
            float4 w = *(const float4*)&Ws[kk][tx << 2];
            acc[0][0] = fmaf(a.x, w.x, acc[0][0]); acc[0][1] = fmaf(a.x, w.y, acc[0][1]);
            acc[0][2] = fmaf(a.x, w.z, acc[0][2]); acc[0][3] = fmaf(a.x, w.w, acc[0][3]);
            acc[1][0] = fmaf(a.y, w.x, acc[1][0]); acc[1][1] = fmaf(a.y, w.y, acc[1][1]);
            acc[1][2] = fmaf(a.y, w.z, acc[1][2]); acc[1][3] = fmaf(a.y, w.w, acc[1][3]);
            acc[2][0] = fmaf(a.z, w.x, acc[2][0]); acc[2][1] = fmaf(a.z, w.y, acc[2][1]);
            acc[2][2] = fmaf(a.z, w.z, acc[2][2]); acc[2][3] = fmaf(a.z, w.w, acc[2][3]);
            acc[3][0] = fmaf(a.w, w.x, acc[3][0]); acc[3][1] = fmaf(a.w, w.y, acc[3][1]);
            acc[3][2] = fmaf(a.w, w.z, acc[3][2]); acc[3][3] = fmaf(a.w, w.w, acc[3][3]);
        }
    }
    const int c0 = n0 + (tx << 2);
#pragma unroll
    for (int i = 0; i < 4; i++) {
        int r = (ty << 2) + i;
        float4 o = {acc[i][0], acc[i][1], acc[i][2], acc[i][3]};
        *(float4*)&ob[(size_t)r * N + c0] = o;
    }
}

// ---------------- init h0/c0 from split-K partials + bias (also fp16 copies) ------
__global__ void init_hc_kernel(const float* __restrict__ bm, const float* __restrict__ bc) {
    int b = blockIdx.x, n = threadIdx.x;  // 512
    float h = bm[n], c = bc[n];
#pragma unroll
    for (int s = 0; s < 8; s++) {
        h += g_zp[((size_t)s * Bc + b) * Uc + n];
        c += g_zp[((size_t)(8 + s) * Bc + b) * Uc + n];
    }
    g_h[b * Uc + n] = h;
    g_c[b * Uc + n] = c;
    g_hh[b * Uc + n] = __float2half(h);
    g_ch[b * Uc + n] = __float2half(c);
}

// ---------------- device: attention scores + softmax (thread-per-pixel) -----------
__device__ void attn_dev(int b, char* smem,
                         const float* __restrict__ bag,
                         const float* __restrict__ wf,
                         const float* __restrict__ bf,
                         float* __restrict__ out_alpha, int t) {
    int tid = threadIdx.x;  // 256
    if (t >= g_ilen[b]) {
        if (tid < Pc) out_alpha[((size_t)b * Tc + t) * Pc + tid] = 0.f;
        return;
    }
    float* s_att2 = (float*)smem;           // 512
    float* s_wf   = s_att2 + 512;           // 512
    float* s_red  = s_wf + 512;             // 8
    for (int a = tid; a < Ac; a += 256) {
        s_att2[a] = g_cb[(size_t)b * CBN + a] + bag[a];
        s_wf[a] = wf[a];
    }
    __syncthreads();
    int warp = tid >> 5, lane = tid & 31;
    float e = -1e30f;
    if (tid < Pc) {
        const __half* rowp = g_att1h + ((size_t)b * Pc + tid) * Ac;
        float s = 0.f;
#pragma unroll 4
        for (int i = 0; i < 64; i++) {
            uint4 v = *(const uint4*)(rowp + i * 8);
            const __half2* hp = (const __half2*)&v;
            int a = i * 8;
#pragma unroll
            for (int j = 0; j < 4; j++) {
                float2 f = __half22float2(hp[j]);
                float x0 = f.x + s_att2[a + j * 2];
                float x1 = f.y + s_att2[a + j * 2 + 1];
                if (x0 > 0.f) s = fmaf(x0, s_wf[a + j * 2], s);
                if (x1 > 0.f) s = fmaf(x1, s_wf[a + j * 2 + 1], s);
            }
        }
        e = s + bf[0];
    }
    // softmax over 196 values (one per thread)
    float m = e;
#pragma unroll
    for (int o = 16; o; o >>= 1) m = fmaxf(m, __shfl_xor_sync(0xffffffff, m, o));
    if (lane == 0) s_red[warp] = m;
    __syncthreads();
    m = s_red[0];
#pragma unroll
    for (int w = 1; w < 8; w++) m = fmaxf(m, s_red[w]);
    float ex = (tid < Pc) ? expf(e - m) : 0.f;
    float sm = ex;
#pragma unroll
    for (int o = 16; o; o >>= 1) sm += __shfl_xor_sync(0xffffffff, sm, o);
    __syncthreads();
    if (lane == 0) s_red[warp] = sm;
    __syncthreads();
    sm = 0.f;
#pragma unroll
    for (int w = 0; w < 8; w++) sm += s_red[w];
    float inv = 1.0f / sm;
    if (tid < Pc) {
        float al = ex * inv;
        g_alpha[b * Pc + tid] = al;
        out_alpha[((size_t)b * Tc + t) * Pc + tid] = al;
    }
}

// ---------------- device: awe chunk = (alpha . enc) * sigmoid(beta) -> fp16 -------
// task = b * 2 + chunk(1024 cols); 256 threads, 4 cols each.
__device__ void awe_dev(int task, char* smem, const float* __restrict__ bbeta, int t) {
    int b = task >> 1, ch = task & 1;
    int tid = threadIdx.x;
    if (t >= g_ilen[b]) return;  // stale g_aweh unused (z masked in gates)
    float* s_al = (float*)smem;  // 196
    if (tid < Pc) s_al[tid] = g_alpha[b * Pc + tid];
    __syncthreads();
    int col = ch * 1024 + tid * 4;
    const __half* encb = g_ench + (size_t)b * Pc * ENCc + col;
    float a0 = 0.f, a1 = 0.f, a2 = 0.f, a3 = 0.f;
#pragma unroll 2
    for (int p = 0; p < Pc; p += 2) {
        float l0 = s_al[p], l1 = s_al[p + 1];
        uint2 v0 = *(const uint2*)(encb + (size_t)p * ENCc);
        uint2 v1 = *(const uint2*)(encb + (size_t)(p + 1) * ENCc);
        float2 f;
        f = __half22float2(*(__half2*)&v0.x); a0 = fmaf(l0, f.x, a0); a1 = fmaf(l0, f.y, a1);
        f = __half22float2(*(__half2*)&v0.y); a2 = fmaf(l0, f.x, a2); a3 = fmaf(l0, f.y, a3);
        f = __half22float2(*(__half2*)&v1.x); a0 = fmaf(l1, f.x, a0); a1 = fmaf(l1, f.y, a1);
        f = __half22float2(*(__half2*)&v1.y); a2 = fmaf(l1, f.x, a2); a3 = fmaf(l1, f.y, a3);
    }
    float4 bl = *(const float4*)&bbeta[col];
    float4 cbv = *(const float4*)&g_cb[(size_t)b * CBN + Ac + col];
    bl.x += cbv.x; bl.y += cbv.y; bl.z += cbv.z; bl.w += cbv.w;
    float o0 = a0 / (1.0f + expf(-bl.x));
    float o1 = a1 / (1.0f + expf(-bl.y));
    float o2 = a2 / (1.0f + expf(-bl.z));
    float o3 = a3 / (1.0f + expf(-bl.w));
    __half2 h0 = __floats2half2_rn(o0, o1);
    __half2 h1 = __floats2half2_rn(o2, o3);
    uint2 pack;
    pack.x = *(uint32_t*)&h0;
    pack.y = *(uint32_t*)&h1;
    *(uint2*)&g_aweh[(size_t)b * ENCc + col] = pack;
}

// ---------------- device: vocab softmax, masked -----------------------------------
__device__ void softmax_dev(int b, char* smem, const float* __restrict__ bo,
                            float* __restrict__ out_pred, int tsoft) {
    int tid = threadIdx.x;  // 256
    float4* dst = (float4*)(out_pred + ((size_t)b * Tc + tsoft) * Vc);
    const int NV4 = Vc / 4;
    if (tsoft >= g_ilen[b]) {
        float4 z = {0, 0, 0, 0};
        for (int i = tid; i < NV4; i += 256) dst[i] = z;
        return;
    }
    const float4* lg = (const float4*)(g_logits + (size_t)b * Vc);
    const float4* bo4 = (const float4*)bo;
    float* s_red = (float*)smem;
    int warp = tid >> 5, lane = tid & 31;
    float m = -1e30f;
    for (int i = tid; i < NV4; i += 256) {
        float4 a = lg[i], bb = bo4[i];
        float4 v = {a.x + bb.x, a.y + bb.y, a.z + bb.z, a.w + bb.w};
        dst[i] = v;
        m = fmaxf(m, fmaxf(fmaxf(v.x, v.y), fmaxf(v.z, v.w)));
    }
#pragma unroll
    for (int o = 16; o; o >>= 1) m = fmaxf(m, __shfl_xor_sync(0xffffffff, m, o));
    if (lane == 0) s_red[warp] = m;
    __syncthreads();
    m = s_red[0];
#pragma unroll
    for (int w = 1; w < 8; w++) m = fmaxf(m, s_red[w]);
    float sum = 0.f;
    for (int i = tid; i < NV4; i += 256) {
        float4 v = dst[i];
        v.x = expf(v.x - m); v.y = expf(v.y - m);
        v.z = expf(v.z - m); v.w = expf(v.w - m);
        dst[i] = v;
        sum += v.x + v.y + v.z + v.w;
    }
#pragma unroll
    for (int o = 16; o; o >>= 1) sum += __shfl_xor_sync(0xffffffff, sum, o);
    __syncthreads();
    if (lane == 0) s_red[warp] = sum;
    __syncthreads();
    sum = 0.f;
#pragma unroll
    for (int w = 0; w < 8; w++) sum += s_red[w];
    float inv = 1.0f / sum;
    for (int i = tid; i < NV4; i += 256) {
        float4 v = dst[i];
        v.x *= inv; v.y *= inv; v.z *= inv; v.w *= inv;
        dst[i] = v;
    }
}

// ================= persistent loop kernel (131 blocks, 256 threads) ===============
__global__ __launch_bounds__(256) void loop_kernel(
    const float* __restrict__ bag, const float* __restrict__ wf,
    const float* __restrict__ bf, const float* __restrict__ bbeta,
    const float* __restrict__ bl, const float* __restrict__ bo,
    float* __restrict__ out_alpha, float* __restrict__ out_pred) {
    __shared__ __align__(16) char smem[15872];
    __half* sA = (__half*)smem;                 // 64*40 halves
    __half* sW = (__half*)(smem + 64 * 40 * 2); // 128*40 halves
    const int blk = blockIdx.x;
    const int tid = threadIdx.x;

    for (int t = 0; t < Tc; t++) {
        // ---- Phase 1: cb | logits(t-1) | z_emb | z_h ----
        if (blk < 20) {
            int n0 = blk * 128;
            fp16_gemm<false>(g_ch, Uc, g_Wcbt + (size_t)n0 * Uc, Uc,
                             g_cb + n0, CBN, Uc, 128, nullptr, sA, sW);
        } else if (blk < 99) {
            if (t > 0) {
                int n0 = (blk - 20) * 128;
                int ng = Vc - n0; if (ng > 128) ng = 128;
                fp16_gemm<false>(g_ch, Uc, g_Woutt + (size_t)n0 * Uc, Uc,
                                 g_logits + n0, Vc, Uc, ng, nullptr, sA, sW);
            }
        } else if (blk < 115) {
            int n0 = (blk - 99) * 128;
            fp16_gemm<false>(g_embh + (size_t)t * Bc * Ec, Ec,
                             g_Wxt + (size_t)n0 * KX, KX,
                             g_zp + 0 * (size_t)Bc * N4U + n0, N4U, Ec, 128,
                             nullptr, sA, sW);
        } else {
            int n0 = (blk - 115) * 128;
            fp16_gemm<false>(g_hh, Uc, g_Wht + (size_t)n0 * Uc, Uc,
                             g_zp + 1 * (size_t)Bc * N4U + n0, N4U, Uc, 128,
                             nullptr, sA, sW);
        }
        grid_bar();
        // ---- Phase 2: attn(t) | softmax(t-1) ----
        if (blk < 64) {
            attn_dev(blk, smem, bag, wf, bf, out_alpha, t);
        } else if (blk < 128) {
            if (t > 0) softmax_dev(blk - 64, smem, bo, out_pred, t - 1);
        }
        grid_bar();
        // ---- Phase 2b: awe distributed (128 tasks) ----
        if (blk < 128) awe_dev(blk, smem, bbeta, t);
        grid_bar();
        // ---- Phase 3: z_awe, 8 k-splits x 16 n-tiles ----
        if (blk < 128) {
            int sp = blk >> 4, n0 = (blk & 15) * 128;
            fp16_gemm<false>(g_aweh + sp * 256, ENCc,
                             g_Wxt + (size_t)n0 * KX + Ec + sp * 256, KX,
                             g_zp + (size_t)(2 + sp) * Bc * N4U + n0, N4U,
                             256, 128, nullptr, sA, sW);
        }
        grid_bar();
        // ---- Phase 4: gates ----
        if (blk < 64) {
            int b = blk;
#pragma unroll
            for (int i = 0; i < 2; i++) {
                int n = tid + i * 256;
                float zi = bl[n], zf = bl[Uc + n], zg = bl[2 * Uc + n], zo = bl[3 * Uc + n];
#pragma unroll
                for (int s = 0; s < 10; s++) {
                    const float* zp = g_zp + ((size_t)s * Bc + b) * N4U;
                    zi += zp[n];
                    zf += zp[Uc + n];
                    zg += zp[2 * Uc + n];
                    zo += zp[3 * Uc + n];
                }
                float c_old = g_c[b * Uc + n], h_old = g_h[b * Uc + n];
                float si = 1.0f / (1.0f + expf(-zi));
                float sf = 1.0f / (1.0f + expf(-zf));
                float so = 1.0f / (1.0f + expf(-zo));
                float c_new = sf * c_old + si * tanhf(zg);
                float h_new = so * tanhf(c_new);
                bool mask = t < g_ilen[b];
                float c2 = mask ? c_new : c_old;
                float h2 = mask ? h_new : h_old;
                g_c[b * Uc + n] = c2;
                g_h[b * Uc + n] = h2;
                g_ch[b * Uc + n] = __float2half(c2);
                g_hh[b * Uc + n] = __float2half(h2);
            }
        }
        grid_bar();
    }
    // ---- tail: logits + softmax for the final step ----
    if (blk >= 20 && blk < 99) {
        int n0 = (blk - 20) * 128;
        int ng = Vc - n0; if (ng > 128) ng = 128;
        fp16_gemm<false>(g_ch, Uc, g_Woutt + (size_t)n0 * Uc, Uc,
                         g_logits + n0, Vc, Uc, ng, nullptr, sA, sW);
    }
    grid_bar();
    if (blk >= 64 && blk < 128) softmax_dev(blk - 64, smem, bo, out_pred, Tc - 1);
}

// ---------------- launcher ---------------------------------------------------------
extern "C" void kernel_launch(void* const* d_in, const int* in_sizes, int n_in,
                              void* d_out, int out_size) {
    const float* enc      = (const float*)d_in[0];
    const int*   seqs     = (const int*)  d_in[1];
    const int*   lens     = (const int*)  d_in[2];
    const float* emb_tab  = (const float*)d_in[3];
    const float* W_ae     = (const float*)d_in[4];
    const float* b_ae     = (const float*)d_in[5];
    const float* W_ag     = (const float*)d_in[6];
    const float* b_ag     = (const float*)d_in[7];
    const float* W_af     = (const float*)d_in[8];
    const float* b_af     = (const float*)d_in[9];
    const float* W_x      = (const float*)d_in[10];
    const float* W_h      = (const float*)d_in[11];
    const float* b_lstm   = (const float*)d_in[12];
    const float* W_im     = (const float*)d_in[13];
    const float* b_im     = (const float*)d_in[14];
    const float* W_ic     = (const float*)d_in[15];
    const float* b_ic     = (const float*)d_in[16];
    const float* W_beta   = (const float*)d_in[17];
    const float* b_beta   = (const float*)d_in[18];
    const float* W_out    = (const float*)d_in[19];
    const float* b_out    = (const float*)d_in[20];

    float* out       = (float*)d_out;
    float* out_pred  = out;                                   // [B,T,V]
    float* out_alpha = out_pred + (size_t)Bc * Tc * Vc;       // [B,T,P]
    float* out_seqs  = out_alpha + (size_t)Bc * Tc * Pc;      // [B,S]
    float* out_ilen  = out_seqs + (size_t)Bc * Sc;            // [B]
    float* out_order = out_ilen + Bc;                         // [B]

    float *p_mean, *p_zp;
    __half *p_Waet, *p_Wcbt, *p_Woutt, *p_Wxt, *p_Wht;
    cudaGetSymbolAddress((void**)&p_mean, g_mean);
    cudaGetSymbolAddress((void**)&p_zp, g_zp);
    cudaGetSymbolAddress((void**)&p_Waet, g_Waet);
    cudaGetSymbolAddress((void**)&p_Wcbt, g_Wcbt);
    cudaGetSymbolAddress((void**)&p_Woutt, g_Woutt);
    cudaGetSymbolAddress((void**)&p_Wxt, g_Wxt);
    cudaGetSymbolAddress((void**)&p_Wht, g_Wht);

    // ---- setup ----
    sort_kernel<<<1, Bc>>>(lens, seqs, out_seqs, out_ilen, out_order);
    permute_kernel<<<dim3(Bc, Pc), 256>>>(enc);
    emb_all_kernel<<<dim3(Bc, Tc), 128>>>(emb_tab);
    mean_kernel<<<dim3(Bc, 2), 256>>>();
    convT_kernel<<<dim3(16, 64), 256>>>(W_ae, p_Waet, ENCc, Ac);
    convT_kernel<<<dim3(16, 16), 256>>>(W_ag, p_Wcbt, Uc, Ac);
    convT_kernel<<<dim3(64, 16), 256>>>(W_beta, p_Wcbt + (size_t)Ac * Uc, Uc, ENCc);
    convT_kernel<<<dim3(313, 16), 256>>>(W_out, p_Woutt, Uc, Vc);
    convT_kernel<<<dim3(64, 80), 256>>>(W_x, p_Wxt, KX, N4U);
    convT_kernel<<<dim3(64, 16), 256>>>(W_h, p_Wht, Uc, N4U);
    gemm_k<<<dim3(Uc / 64, 1, 8), 256>>>(p_mean, ENCc, W_im, p_zp, ENCc, Uc, (size_t)Bc * Uc);
    gemm_k<<<dim3(Uc / 64, 1, 8), 256>>>(p_mean, ENCc, W_ic, p_zp + (size_t)8 * Bc * Uc, ENCc, Uc, (size_t)Bc * Uc);
    init_hc_kernel<<<Bc, Uc>>>(b_im, b_ic);
    att1h_kernel<<<dim3(Ac / 128, (Bc * Pc) / 64), 256>>>(b_ae);

    // ---- whole time loop in ONE persistent kernel ----
    loop_kernel<<<NB, 256>>>(b_ag, W_af, b_af, b_beta, b_lstm, b_out,
                             out_alpha, out_pred);
}

// round 8
// speedup vs baseline: 3.1285x; 1.1093x over previous
#include <cuda_runtime.h>
#include <cuda_fp16.h>
#include <math.h>
#include <stdint.h>

// Problem dims
#define Bc   64
#define Pc   196
#define Sc   22
#define Tc   21
#define Vc   10000
#define Ec   512
#define Ac   512
#define Uc   512
#define ENCc 2048
#define N4U  2048   // 4*U
#define CBN  2560   // A + ENC (att2 | beta combined)
#define KX   2560   // E + ENC (W_x K dim)
#define NB   131    // persistent grid size (single wave on 148 SMs)

// ---------------- scratch (static __device__ arrays; no allocation) -------------
__device__ __half g_ench[Bc * Pc * ENCc];     // sorted encoder fp16 (51.4 MB)
__device__ __half g_att1h[Bc * Pc * Ac];      // att1 fp16 (12.8 MB)
__device__ __half g_Waet[Ac * ENCc];          // W_att_enc^T
__device__ __half g_Wcbt[CBN * Uc];           // [Wag|Wbeta]^T
__device__ __half g_Woutt[Vc * Uc];           // W_out^T
__device__ __half g_Wxt[N4U * KX];            // W_x^T
__device__ __half g_Wht[N4U * Uc];            // W_h^T
__device__ __half g_embh[Tc * Bc * Ec];       // embeddings fp16, all steps
__device__ __half g_ch[Bc * Uc];              // c fp16 (GEMM A operand)
__device__ __half g_hh[Bc * Uc];              // h fp16
__device__ __half g_aweh[Bc * ENCc];          // gated context fp16
__device__ float g_mean[Bc * ENCc];
__device__ float g_h[Bc * Uc];
__device__ float g_c[Bc * Uc];
__device__ float g_alpha[Bc * Pc];
__device__ float g_cb[Bc * CBN];              // [att2 | beta-logits] (no bias)
__device__ float g_zp[16 * Bc * Uc > 10 * Bc * N4U ? 16 * Bc * Uc : 10 * Bc * N4U];
__device__ float g_logits[Bc * Vc];           // logits (no bias)
__device__ int   g_order[Bc];
__device__ int   g_ilen[Bc];
__device__ int   g_seqs[Bc * Sc];

// ---------------- parallel-flag grid barrier (replay-safe, monotonic) -------------
__device__ volatile int g_flags[NB];
__device__ volatile int g_gen;

__device__ __forceinline__ void grid_bar() {
    __syncthreads();
    int gen = g_gen;  // stable snapshot: only block 0 advances it, and every
                      // arriving block has already observed the current value
    if (blockIdx.x == 0) {
        if (threadIdx.x == 0) {
            __threadfence();
            g_flags[0] = gen + 1;
        }
        if (threadIdx.x < NB) {
            while (g_flags[threadIdx.x] < gen + 1) {}
        }
        __syncthreads();
        if (threadIdx.x == 0) {
            __threadfence();
            g_gen = gen + 1;
        }
    } else {
        if (threadIdx.x == 0) {
            __threadfence();
            g_flags[blockIdx.x] = gen + 1;
            while (g_gen < gen + 1) {}
            __threadfence();
        }
    }
    __syncthreads();
}

// ---------------- sort: stable argsort(-lens) ------------------------------------
__global__ void sort_kernel(const int* __restrict__ lens,
                            const int* __restrict__ seqs,
                            float* __restrict__ out_seqs,
                            float* __restrict__ out_ilen,
                            float* __restrict__ out_order) {
    int tid = threadIdx.x;  // 64 threads
    __shared__ int s_len[Bc];
    s_len[tid] = lens[tid];
    __syncthreads();
    int myL = s_len[tid];
    int rank = 0;
    for (int j = 0; j < Bc; j++) {
        int lj = s_len[j];
        rank += (lj > myL) || (lj == myL && j < tid);
    }
    g_order[rank] = tid;
    __syncthreads();
    int src = g_order[tid];
    int il = s_len[src] - 1;
    g_ilen[tid] = il;
    out_ilen[tid] = (float)il;
    out_order[tid] = (float)src;
    for (int s = 0; s < Sc; s++) {
        int v = seqs[src * Sc + s];
        g_seqs[tid * Sc + s] = v;
        out_seqs[tid * Sc + s] = (float)v;
    }
}

// ---------------- permute encoder rows -> fp16 sorted copy ------------------------
__global__ void permute_kernel(const float* __restrict__ enc) {
    int b = blockIdx.x, p = blockIdx.y;
    int src = g_order[b];
    const float4* s = (const float4*)&enc[((size_t)src * Pc + p) * ENCc];
    __half2* dh = (__half2*)&g_ench[((size_t)b * Pc + p) * ENCc];
    for (int i = threadIdx.x; i < ENCc / 4; i += 256) {
        float4 v = s[i];
        dh[i * 2 + 0] = __floats2half2_rn(v.x, v.y);
        dh[i * 2 + 1] = __floats2half2_rn(v.z, v.w);
    }
}

// ---------------- transpose-convert weight fp32[K,N] -> fp16[N,K] ----------------
__global__ void convT_kernel(const float* __restrict__ in, __half* __restrict__ out,
                             int K, int N) {
    __shared__ float tile[32][33];
    int n0 = blockIdx.x * 32, k0 = blockIdx.y * 32;
    int tx = threadIdx.x & 31, ty = threadIdx.x >> 5;  // 256 thr
#pragma unroll
    for (int i = 0; i < 32; i += 8) {
        int k = k0 + ty + i, n = n0 + tx;
        tile[ty + i][tx] = (n < N) ? in[(size_t)k * N + n] : 0.f;
    }
    __syncthreads();
#pragma unroll
    for (int i = 0; i < 32; i += 8) {
        int n = n0 + ty + i;
        if (n < N) out[(size_t)n * K + k0 + tx] = __float2half(tile[tx][ty + i]);
    }
}

// ---------------- precompute embeddings (fp16) for all timesteps ------------------
__global__ void emb_all_kernel(const float* __restrict__ emb_table) {
    int b = blockIdx.x, t = blockIdx.y;  // 128 threads
    int tok = g_seqs[b * Sc + t];
    float4 v = ((const float4*)(emb_table + (size_t)tok * Ec))[threadIdx.x];
    __half2 h0 = __floats2half2_rn(v.x, v.y);
    __half2 h1 = __floats2half2_rn(v.z, v.w);
    __half2* dst = (__half2*)(g_embh + ((size_t)t * Bc + b) * Ec);
    dst[threadIdx.x * 2 + 0] = h0;
    dst[threadIdx.x * 2 + 1] = h1;
}

// ---------------- mean over pixels (from fp16 copy, fp32 accum) -------------------
__global__ void mean_kernel() {
    int b = blockIdx.x;
    int e0 = blockIdx.y * 1024 + threadIdx.x * 4;
    const __half* encb = g_ench + (size_t)b * Pc * ENCc + e0;
    float4 a0 = {0,0,0,0}, a1 = {0,0,0,0}, a2 = {0,0,0,0}, a3 = {0,0,0,0};
    for (int p = 0; p < Pc; p += 4) {
        uint2 r0 = *(const uint2*)(encb + (size_t)(p + 0) * ENCc);
        uint2 r1 = *(const uint2*)(encb + (size_t)(p + 1) * ENCc);
        uint2 r2 = *(const uint2*)(encb + (size_t)(p + 2) * ENCc);
        uint2 r3 = *(const uint2*)(encb + (size_t)(p + 3) * ENCc);
        float2 f;
        f = __half22float2(*(__half2*)&r0.x); a0.x += f.x; a0.y += f.y;
        f = __half22float2(*(__half2*)&r0.y); a0.z += f.x; a0.w += f.y;
        f = __half22float2(*(__half2*)&r1.x); a1.x += f.x; a1.y += f.y;
        f = __half22float2(*(__half2*)&r1.y); a1.z += f.x; a1.w += f.y;
        f = __half22float2(*(__half2*)&r2.x); a2.x += f.x; a2.y += f.y;
        f = __half22float2(*(__half2*)&r2.y); a2.z += f.x; a2.w += f.y;
        f = __half22float2(*(__half2*)&r3.x); a3.x += f.x; a3.y += f.y;
        f = __half22float2(*(__half2*)&r3.y); a3.z += f.x; a3.w += f.y;
    }
    float4 r;
    r.x = (a0.x + a1.x + a2.x + a3.x) * (1.0f / Pc);
    r.y = (a0.y + a1.y + a2.y + a3.y) * (1.0f / Pc);
    r.z = (a0.z + a1.z + a2.z + a3.z) * (1.0f / Pc);
    r.w = (a0.w + a1.w + a2.w + a3.w) * (1.0f / Pc);
    *(float4*)(g_mean + (size_t)b * ENCc + e0) = r;
}

// ---------------- fp16 MMA helper --------------------------------------------------
__device__ __forceinline__ void mma_fp16(float* c, const uint32_t* a, const uint32_t* b) {
    asm volatile(
        "mma.sync.aligned.m16n8k16.row.col.f32.f16.f16.f32 "
        "{%0,%1,%2,%3}, {%4,%5,%6,%7}, {%8,%9}, {%0,%1,%2,%3};"
        : "+f"(c[0]), "+f"(c[1]), "+f"(c[2]), "+f"(c[3])
        : "r"(a[0]), "r"(a[1]), "r"(a[2]), "r"(a[3]), "r"(b[0]), "r"(b[1]));
}

// ---- 64x128-tile fp16 GEMM, smem double-buffered (one sync/iter) ------------------
// C[64, nguard] = A(fp16)[64][lda] @ Wt(fp16)[n][ldk].  256 threads.
// sA: 2 x 64*40 halves; sW: 2 x 128*40 halves. A loaded via __ldcg (dynamic data).
template <bool HOUT>
__device__ void fp16_gemm(const __half* __restrict__ A, int lda,
                          const __half* __restrict__ Wt, int ldk,
                          void* __restrict__ Cv, int ldc,
                          int K, int nguard, const float* __restrict__ bias,
                          __half* __restrict__ sA, __half* __restrict__ sW) {
    const int tid = threadIdx.x;
    const int warp = tid >> 5, lane = tid & 31;
    const int wm = (warp & 1) << 5;
    const int wn = (warp >> 1) << 5;

    float acc[2][4][4];
#pragma unroll
    for (int i = 0; i < 2; i++)
#pragma unroll
        for (int j = 0; j < 4; j++)
#pragma unroll
            for (int q = 0; q < 4; q++) acc[i][j][q] = 0.f;

    const int ar = tid >> 2, akq = (tid & 3) << 3;   // A row, k-offset (uint4 = 8 halves)
    const int nr = tid >> 1, koff = (tid & 1) << 4;  // W n-row, k-offset (2 uint4)
    const bool wok = nr < nguard;

    uint4 a_reg = __ldcg((const uint4*)(A + (size_t)ar * lda + akq));
    uint4 w_reg0 = {0, 0, 0, 0}, w_reg1 = {0, 0, 0, 0};
    if (wok) {
        const __half* wp = Wt + (size_t)nr * ldk + koff;
        w_reg0 = *(const uint4*)wp;
        w_reg1 = *(const uint4*)(wp + 8);
    }

    int buf = 0;
    for (int k0 = 0; k0 < K; k0 += 32) {
        __half* cA = sA + buf * (64 * 40);
        __half* cW = sW + buf * (128 * 40);
        *(uint4*)&cA[ar * 40 + akq] = a_reg;
        *(uint4*)&cW[nr * 40 + koff] = w_reg0;
        *(uint4*)&cW[nr * 40 + koff + 8] = w_reg1;
        __syncthreads();
        int k1 = k0 + 32;
        if (k1 < K) {
            a_reg = __ldcg((const uint4*)(A + (size_t)ar * lda + k1 + akq));
            if (wok) {
                const __half* wp = Wt + (size_t)nr * ldk + k1 + koff;
                w_reg0 = *(const uint4*)wp;
                w_reg1 = *(const uint4*)(wp + 8);
            }
        }
#pragma unroll
        for (int ks = 0; ks < 32; ks += 16) {
            const int gr = lane >> 2, gc = (lane & 3) << 1;
            uint32_t a[2][4], bb[4][2];
#pragma unroll
            for (int mi = 0; mi < 2; mi++) {
                int row = wm + mi * 16 + gr;
                a[mi][0] = *(const uint32_t*)&cA[row * 40 + ks + gc];
                a[mi][1] = *(const uint32_t*)&cA[(row + 8) * 40 + ks + gc];
                a[mi][2] = *(const uint32_t*)&cA[row * 40 + ks + gc + 8];
                a[mi][3] = *(const uint32_t*)&cA[(row + 8) * 40 + ks + gc + 8];
            }
#pragma unroll
            for (int nj = 0; nj < 4; nj++) {
                int n = wn + nj * 8 + gr;
                bb[nj][0] = *(const uint32_t*)&cW[n * 40 + ks + gc];
                bb[nj][1] = *(const uint32_t*)&cW[n * 40 + ks + gc + 8];
            }
#pragma unroll
            for (int mi = 0; mi < 2; mi++)
#pragma unroll
                for (int nj = 0; nj < 4; nj++)
                    mma_fp16(acc[mi][nj], a[mi], bb[nj]);
        }
        buf ^= 1;
    }
    const int gr = lane >> 2, cc = (lane & 3) << 1;
#pragma unroll
    for (int mi = 0; mi < 2; mi++) {
#pragma unroll
        for (int nj = 0; nj < 4; nj++) {
            int row = wm + mi * 16 + gr;
            int col = wn + nj * 8 + cc;
            if (col + 1 < nguard) {
                if (HOUT) {
                    float b0 = bias[col], b1 = bias[col + 1];
                    __half* Ch = (__half*)Cv;
                    *(__half2*)&Ch[(size_t)row * ldc + col] =
                        __floats2half2_rn(acc[mi][nj][0] + b0, acc[mi][nj][1] + b1);
                    *(__half2*)&Ch[(size_t)(row + 8) * ldc + col] =
                        __floats2half2_rn(acc[mi][nj][2] + b0, acc[mi][nj][3] + b1);
                } else {
                    float* C = (float*)Cv;
                    float2 o0 = {acc[mi][nj][0], acc[mi][nj][1]};
                    float2 o1 = {acc[mi][nj][2], acc[mi][nj][3]};
                    *(float2*)&C[(size_t)row * ldc + col] = o0;
                    *(float2*)&C[(size_t)(row + 8) * ldc + col] = o1;
                }
            }
        }
    }
}

#define SMEM_BYTES (2 * 64 * 40 * 2 + 2 * 128 * 40 * 2)   // 30720

// ---------------- att1 = ench @ W_ae + b_ae -> fp16 (standalone) -------------------
__global__ __launch_bounds__(256) void att1h_kernel(const float* __restrict__ bae) {
    __shared__ __align__(16) char smem[SMEM_BYTES];
    __half* sA = (__half*)smem;
    __half* sW = (__half*)(smem + 2 * 64 * 40 * 2);
    int n0 = blockIdx.x * 128;
    int m0 = blockIdx.y * 64;
    fp16_gemm<true>(g_ench + (size_t)m0 * ENCc, ENCc,
                    g_Waet + (size_t)n0 * ENCc, ENCc,
                    g_att1h + (size_t)m0 * Ac + n0, Ac, ENCc, 128, bae + n0,
                    sA, sW);
}

// ---------------- fp32 GEMM for h0/c0 init (partials) -----------------------------
__global__ __launch_bounds__(256) void gemm_k(
    const float* __restrict__ A, int lda,
    const float* __restrict__ W,
    float* __restrict__ out,
    int K, int N, size_t part_stride) {
    __shared__ float As[16][68];
    __shared__ float Ws[16][68];
    const int tid = threadIdx.x;
    const int tx = tid & 15, ty = tid >> 4;
    const int n0 = blockIdx.x * 64;
    const int kchunk = K / gridDim.z;
    const int kbeg = blockIdx.z * kchunk;
    float* ob = out + (size_t)blockIdx.z * part_stride;

    const int lm = tid >> 2;
    const int lq = (tid & 3) << 2;
    const int wk = tid >> 4;
    const int wn = (tid & 15) << 2;

    float acc[4][4] = {};

    for (int k0 = kbeg; k0 < kbeg + kchunk; k0 += 16) {
        float4 av = *(const float4*)(A + (size_t)lm * lda + k0 + lq);
        float4 wv = *(const float4*)(W + (size_t)(k0 + wk) * N + n0 + wn);
        __syncthreads();
        As[lq + 0][lm] = av.x; As[lq + 1][lm] = av.y;
        As[lq + 2][lm] = av.z; As[lq + 3][lm] = av.w;
        *(float4*)&Ws[wk][wn] = wv;
        __syncthreads();
#pragma unroll
        for (int kk = 0; kk < 16; kk++) {
            float4 a = *(const float4*)&As[kk][ty << 2];
            float4 w = *(const float4*)&Ws[kk][tx << 2];
            acc[0][0] = fmaf(a.x, w.x, acc[0][0]); acc[0][1] = fmaf(a.x, w.y, acc[0][1]);
            acc[0][2] = fmaf(a.x, w.z, acc[0][2]); acc[0][3] = fmaf(a.x, w.w, acc[0][3]);
            acc[1][0] = fmaf(a.y, w.x, acc[1][0]); acc[1][1] = fmaf(a.y, w.y, acc[1][1]);
            acc[1][2] = fmaf(a.y, w.z, acc[1][2]); acc[1][3] = fmaf(a.y, w.w, acc[1][3]);
            acc[2][0] = fmaf(a.z, w.x, acc[2][0]); acc[2][1] = fmaf(a.z, w.y, acc[2][1]);
            acc[2][2] = fmaf(a.z, w.z, acc[2][2]); acc[2][3] = fmaf(a.z, w.w, acc[2][3]);
            acc[3][0] = fmaf(a.w, w.x, acc[3][0]); acc[3][1] = fmaf(a.w, w.y, acc[3][1]);
            acc[3][2] = fmaf(a.w, w.z, acc[3][2]); acc[3][3] = fmaf(a.w, w.w, acc[3][3]);
        }
    }
    const int c0 = n0 + (tx << 2);
#pragma unroll
    for (int i = 0; i < 4; i++) {
        int r = (ty << 2) + i;
        float4 o = {acc[i][0], acc[i][1], acc[i][2], acc[i][3]};
        *(float4*)&ob[(size_t)r * N + c0] = o;
    }
}

// ---------------- init h0/c0 from split-K partials + bias (also fp16 copies) ------
__global__ void init_hc_kernel(const float* __restrict__ bm, const float* __restrict__ bc) {
    int b = blockIdx.x, n = threadIdx.x;  // 512
    float h = bm[n], c = bc[n];
#pragma unroll
    for (int s = 0; s < 8; s++) {
        h += g_zp[((size_t)s * Bc + b) * Uc + n];
        c += g_zp[((size_t)(8 + s) * Bc + b) * Uc + n];
    }
    g_h[b * Uc + n] = h;
    g_c[b * Uc + n] = c;
    g_hh[b * Uc + n] = __float2half(h);
    g_ch[b * Uc + n] = __float2half(c);
}

// ---------------- device: attention + softmax + awe (fused, block = b) -------------
__device__ void attn_awe_dev(int b, char* smem,
                             const float* __restrict__ bag,
                             const float* __restrict__ wf,
                             const float* __restrict__ bf,
                             const float* __restrict__ bbeta,
                             float* __restrict__ out_alpha, int t) {
    int tid = threadIdx.x;  // 256
    if (t >= g_ilen[b]) {
        if (tid < Pc) out_alpha[((size_t)b * Tc + t) * Pc + tid] = 0.f;
        return;
    }
    float* s_att2 = (float*)smem;           // 512
    float* s_wf   = s_att2 + 512;           // 512
    float* s_red  = s_wf + 512;             // 8
    float* s_al   = s_red + 8;              // 200
    for (int a = tid; a < Ac; a += 256) {
        s_att2[a] = __ldcg(&g_cb[(size_t)b * CBN + a]) + bag[a];
        s_wf[a] = wf[a];
    }
    __syncthreads();
    int warp = tid >> 5, lane = tid & 31;
    float e = -1e30f;
    if (tid < Pc) {
        const __half* rowp = g_att1h + ((size_t)b * Pc + tid) * Ac;
        float s0 = 0.f, s1 = 0.f;
#pragma unroll 4
        for (int i = 0; i < 64; i += 2) {
            uint4 v0 = *(const uint4*)(rowp + i * 8);
            uint4 v1 = *(const uint4*)(rowp + i * 8 + 8);
            const __half2* h0 = (const __half2*)&v0;
            const __half2* h1 = (const __half2*)&v1;
            int a0 = i * 8, a1 = i * 8 + 8;
#pragma unroll
            for (int j = 0; j < 4; j++) {
                float2 f0 = __half22float2(h0[j]);
                float2 f1 = __half22float2(h1[j]);
                float x;
                x = f0.x + s_att2[a0 + j * 2];     if (x > 0.f) s0 = fmaf(x, s_wf[a0 + j * 2], s0);
                x = f0.y + s_att2[a0 + j * 2 + 1]; if (x > 0.f) s0 = fmaf(x, s_wf[a0 + j * 2 + 1], s0);
                x = f1.x + s_att2[a1 + j * 2];     if (x > 0.f) s1 = fmaf(x, s_wf[a1 + j * 2], s1);
                x = f1.y + s_att2[a1 + j * 2 + 1]; if (x > 0.f) s1 = fmaf(x, s_wf[a1 + j * 2 + 1], s1);
            }
        }
        e = s0 + s1 + bf[0];
    }
    float m = e;
#pragma unroll
    for (int o = 16; o; o >>= 1) m = fmaxf(m, __shfl_xor_sync(0xffffffff, m, o));
    if (lane == 0) s_red[warp] = m;
    __syncthreads();
    m = s_red[0];
#pragma unroll
    for (int w = 1; w < 8; w++) m = fmaxf(m, s_red[w]);
    float ex = (tid < Pc) ? expf(e - m) : 0.f;
    float sm = ex;
#pragma unroll
    for (int o = 16; o; o >>= 1) sm += __shfl_xor_sync(0xffffffff, sm, o);
    __syncthreads();
    if (lane == 0) s_red[warp] = sm;
    __syncthreads();
    sm = 0.f;
#pragma unroll
    for (int w = 0; w < 8; w++) sm += s_red[w];
    float inv = 1.0f / sm;
    if (tid < Pc) {
        float al = ex * inv;
        s_al[tid] = al;
        out_alpha[((size_t)b * Tc + t) * Pc + tid] = al;
    }
    __syncthreads();
    // awe: each thread owns 8 contiguous ENC cols; p unrolled x4 (MLP 4)
    int e0 = tid * 8;
    const __half* encb = g_ench + (size_t)b * Pc * ENCc + e0;
    float acc[8] = {};
    for (int p = 0; p < Pc; p += 4) {
        float l0 = s_al[p], l1 = s_al[p + 1], l2 = s_al[p + 2], l3 = s_al[p + 3];
        uint4 v0 = *(const uint4*)(encb + (size_t)(p + 0) * ENCc);
        uint4 v1 = *(const uint4*)(encb + (size_t)(p + 1) * ENCc);
        uint4 v2 = *(const uint4*)(encb + (size_t)(p + 2) * ENCc);
        uint4 v3 = *(const uint4*)(encb + (size_t)(p + 3) * ENCc);
        const __half2* h0 = (const __half2*)&v0;
        const __half2* h1 = (const __half2*)&v1;
        const __half2* h2 = (const __half2*)&v2;
        const __half2* h3 = (const __half2*)&v3;
#pragma unroll
        for (int j = 0; j < 4; j++) {
            float2 f;
            f = __half22float2(h0[j]); acc[2*j] = fmaf(l0, f.x, acc[2*j]); acc[2*j+1] = fmaf(l0, f.y, acc[2*j+1]);
            f = __half22float2(h1[j]); acc[2*j] = fmaf(l1, f.x, acc[2*j]); acc[2*j+1] = fmaf(l1, f.y, acc[2*j+1]);
            f = __half22float2(h2[j]); acc[2*j] = fmaf(l2, f.x, acc[2*j]); acc[2*j+1] = fmaf(l2, f.y, acc[2*j+1]);
            f = __half22float2(h3[j]); acc[2*j] = fmaf(l3, f.x, acc[2*j]); acc[2*j+1] = fmaf(l3, f.y, acc[2*j+1]);
        }
    }
#pragma unroll
    for (int j = 0; j < 8; j += 4) {
        float4 bl = *(const float4*)&bbeta[e0 + j];
        float4 cbv = __ldcg((const float4*)&g_cb[(size_t)b * CBN + Ac + e0 + j]);
        bl.x += cbv.x; bl.y += cbv.y; bl.z += cbv.z; bl.w += cbv.w;
        float o0 = acc[j+0] / (1.0f + expf(-bl.x));
        float o1 = acc[j+1] / (1.0f + expf(-bl.y));
        float o2 = acc[j+2] / (1.0f + expf(-bl.z));
        float o3 = acc[j+3] / (1.0f + expf(-bl.w));
        __half2 p0 = __floats2half2_rn(o0, o1);
        __half2 p1 = __floats2half2_rn(o2, o3);
        uint2 pack;
        pack.x = *(uint32_t*)&p0;
        pack.y = *(uint32_t*)&p1;
        *(uint2*)&g_aweh[(size_t)b * ENCc + e0 + j] = pack;
    }
}

// ---------------- device: vocab softmax, masked -----------------------------------
__device__ void softmax_dev(int b, char* smem, const float* __restrict__ bo,
                            float* __restrict__ out_pred, int tsoft) {
    int tid = threadIdx.x;  // 256
    float4* dst = (float4*)(out_pred + ((size_t)b * Tc + tsoft) * Vc);
    const int NV4 = Vc / 4;
    if (tsoft >= g_ilen[b]) {
        float4 z = {0, 0, 0, 0};
        for (int i = tid; i < NV4; i += 256) dst[i] = z;
        return;
    }
    const float4* lg = (const float4*)(g_logits + (size_t)b * Vc);
    const float4* bo4 = (const float4*)bo;
    float* s_red = (float*)smem;
    int warp = tid >> 5, lane = tid & 31;
    float m = -1e30f;
    for (int i = tid; i < NV4; i += 256) {
        float4 a = __ldcg(lg + i);
        float4 bb = bo4[i];
        float4 v = {a.x + bb.x, a.y + bb.y, a.z + bb.z, a.w + bb.w};
        dst[i] = v;
        m = fmaxf(m, fmaxf(fmaxf(v.x, v.y), fmaxf(v.z, v.w)));
    }
#pragma unroll
    for (int o = 16; o; o >>= 1) m = fmaxf(m, __shfl_xor_sync(0xffffffff, m, o));
    if (lane == 0) s_red[warp] = m;
    __syncthreads();
    m = s_red[0];
#pragma unroll
    for (int w = 1; w < 8; w++) m = fmaxf(m, s_red[w]);
    float sum = 0.f;
    for (int i = tid; i < NV4; i += 256) {
        float4 v = dst[i];
        v.x = expf(v.x - m); v.y = expf(v.y - m);
        v.z = expf(v.z - m); v.w = expf(v.w - m);
        dst[i] = v;
        sum += v.x + v.y + v.z + v.w;
    }
#pragma unroll
    for (int o = 16; o; o >>= 1) sum += __shfl_xor_sync(0xffffffff, sum, o);
    __syncthreads();
    if (lane == 0) s_red[warp] = sum;
    __syncthreads();
    sum = 0.f;
#pragma unroll
    for (int w = 0; w < 8; w++) sum += s_red[w];
    float inv = 1.0f / sum;
    for (int i = tid; i < NV4; i += 256) {
        float4 v = dst[i];
        v.x *= inv; v.y *= inv; v.z *= inv; v.w *= inv;
        dst[i] = v;
    }
}

// ================= persistent loop kernel (131 blocks, 256 threads) ===============
__global__ __launch_bounds__(256) void loop_kernel(
    const float* __restrict__ bag, const float* __restrict__ wf,
    const float* __restrict__ bf, const float* __restrict__ bbeta,
    const float* __restrict__ bl, const float* __restrict__ bo,
    float* __restrict__ out_alpha, float* __restrict__ out_pred) {
    __shared__ __align__(16) char smem[SMEM_BYTES];
    __half* sA = (__half*)smem;
    __half* sW = (__half*)(smem + 2 * 64 * 40 * 2);
    const int blk = blockIdx.x;
    const int tid = threadIdx.x;

    for (int t = 0; t < Tc; t++) {
        // ---- Phase 1: cb | logits(t-1) | z_emb | z_h ----
        if (blk < 20) {
            int n0 = blk * 128;
            fp16_gemm<false>(g_ch, Uc, g_Wcbt + (size_t)n0 * Uc, Uc,
                             g_cb + n0, CBN, Uc, 128, nullptr, sA, sW);
        } else if (blk < 99) {
            if (t > 0) {
                int n0 = (blk - 20) * 128;
                int ng = Vc - n0; if (ng > 128) ng = 128;
                fp16_gemm<false>(g_ch, Uc, g_Woutt + (size_t)n0 * Uc, Uc,
                                 g_logits + n0, Vc, Uc, ng, nullptr, sA, sW);
            }
        } else if (blk < 115) {
            int n0 = (blk - 99) * 128;
            fp16_gemm<false>(g_embh + (size_t)t * Bc * Ec, Ec,
                             g_Wxt + (size_t)n0 * KX, KX,
                             g_zp + 0 * (size_t)Bc * N4U + n0, N4U, Ec, 128,
                             nullptr, sA, sW);
        } else {
            int n0 = (blk - 115) * 128;
            fp16_gemm<false>(g_hh, Uc, g_Wht + (size_t)n0 * Uc, Uc,
                             g_zp + 1 * (size_t)Bc * N4U + n0, N4U, Uc, 128,
                             nullptr, sA, sW);
        }
        grid_bar();
        // ---- Phase 2: attn+awe(t) | softmax(t-1) ----
        if (blk < 64) {
            attn_awe_dev(blk, smem, bag, wf, bf, bbeta, out_alpha, t);
        } else if (blk < 128) {
            if (t > 0) softmax_dev(blk - 64, smem, bo, out_pred, t - 1);
        }
        grid_bar();
        // ---- Phase 3: z_awe, 8 k-splits x 16 n-tiles ----
        if (blk < 128) {
            int sp = blk >> 4, n0 = (blk & 15) * 128;
            fp16_gemm<false>(g_aweh + sp * 256, ENCc,
                             g_Wxt + (size_t)n0 * KX + Ec + sp * 256, KX,
                             g_zp + (size_t)(2 + sp) * Bc * N4U + n0, N4U,
                             256, 128, nullptr, sA, sW);
        }
        grid_bar();
        // ---- Phase 4: gates ----
        if (blk < 64) {
            int b = blk;
#pragma unroll
            for (int i = 0; i < 2; i++) {
                int n = tid + i * 256;
                float zi = bl[n], zf = bl[Uc + n], zg = bl[2 * Uc + n], zo = bl[3 * Uc + n];
#pragma unroll
                for (int s = 0; s < 10; s++) {
                    const float* zp = g_zp + ((size_t)s * Bc + b) * N4U;
                    zi += __ldcg(zp + n);
                    zf += __ldcg(zp + Uc + n);
                    zg += __ldcg(zp + 2 * Uc + n);
                    zo += __ldcg(zp + 3 * Uc + n);
                }
                float c_old = g_c[b * Uc + n], h_old = g_h[b * Uc + n];
                float si = 1.0f / (1.0f + expf(-zi));
                float sf = 1.0f / (1.0f + expf(-zf));
                float so = 1.0f / (1.0f + expf(-zo));
                float c_new = sf * c_old + si * tanhf(zg);
                float h_new = so * tanhf(c_new);
                bool mask = t < g_ilen[b];
                float c2 = mask ? c_new : c_old;
                float h2 = mask ? h_new : h_old;
                g_c[b * Uc + n] = c2;
                g_h[b * Uc + n] = h2;
                g_ch[b * Uc + n] = __float2half(c2);
                g_hh[b * Uc + n] = __float2half(h2);
            }
        }
        grid_bar();
    }
    // ---- tail: logits + softmax for the final step ----
    if (blk >= 20 && blk < 99) {
        int n0 = (blk - 20) * 128;
        int ng = Vc - n0; if (ng > 128) ng = 128;
        fp16_gemm<false>(g_ch, Uc, g_Woutt + (size_t)n0 * Uc, Uc,
                         g_logits + n0, Vc, Uc, ng, nullptr, sA, sW);
    }
    grid_bar();
    if (blk >= 64 && blk < 128) softmax_dev(blk - 64, smem, bo, out_pred, Tc - 1);
}

// ---------------- launcher ---------------------------------------------------------
extern "C" void kernel_launch(void* const* d_in, const int* in_sizes, int n_in,
                              void* d_out, int out_size) {
    const float* enc      = (const float*)d_in[0];
    const int*   seqs     = (const int*)  d_in[1];
    const int*   lens     = (const int*)  d_in[2];
    const float* emb_tab  = (const float*)d_in[3];
    const float* W_ae     = (const float*)d_in[4];
    const float* b_ae     = (const float*)d_in[5];
    const float* W_ag     = (const float*)d_in[6];
    const float* b_ag     = (const float*)d_in[7];
    const float* W_af     = (const float*)d_in[8];
    const float* b_af     = (const float*)d_in[9];
    const float* W_x      = (const float*)d_in[10];
    const float* W_h      = (const float*)d_in[11];
    const float* b_lstm   = (const float*)d_in[12];
    const float* W_im     = (const float*)d_in[13];
    const float* b_im     = (const float*)d_in[14];
    const float* W_ic     = (const float*)d_in[15];
    const float* b_ic     = (const float*)d_in[16];
    const float* W_beta   = (const float*)d_in[17];
    const float* b_beta   = (const float*)d_in[18];
    const float* W_out    = (const float*)d_in[19];
    const float* b_out    = (const float*)d_in[20];

    float* out       = (float*)d_out;
    float* out_pred  = out;                                   // [B,T,V]
    float* out_alpha = out_pred + (size_t)Bc * Tc * Vc;       // [B,T,P]
    float* out_seqs  = out_alpha + (size_t)Bc * Tc * Pc;      // [B,S]
    float* out_ilen  = out_seqs + (size_t)Bc * Sc;            // [B]
    float* out_order = out_ilen + Bc;                         // [B]

    float *p_mean, *p_zp;
    __half *p_Waet, *p_Wcbt, *p_Woutt, *p_Wxt, *p_Wht;
    cudaGetSymbolAddress((void**)&p_mean, g_mean);
    cudaGetSymbolAddress((void**)&p_zp, g_zp);
    cudaGetSymbolAddress((void**)&p_Waet, g_Waet);
    cudaGetSymbolAddress((void**)&p_Wcbt, g_Wcbt);
    cudaGetSymbolAddress((void**)&p_Woutt, g_Woutt);
    cudaGetSymbolAddress((void**)&p_Wxt, g_Wxt);
    cudaGetSymbolAddress((void**)&p_Wht, g_Wht);

    // ---- setup ----
    sort_kernel<<<1, Bc>>>(lens, seqs, out_seqs, out_ilen, out_order);
    permute_kernel<<<dim3(Bc, Pc), 256>>>(enc);
    emb_all_kernel<<<dim3(Bc, Tc), 128>>>(emb_tab);
    mean_kernel<<<dim3(Bc, 2), 256>>>();
    convT_kernel<<<dim3(16, 64), 256>>>(W_ae, p_Waet, ENCc, Ac);
    convT_kernel<<<dim3(16, 16), 256>>>(W_ag, p_Wcbt, Uc, Ac);
    convT_kernel<<<dim3(64, 16), 256>>>(W_beta, p_Wcbt + (size_t)Ac * Uc, Uc, ENCc);
    convT_kernel<<<dim3(313, 16), 256>>>(W_out, p_Woutt, Uc, Vc);
    convT_kernel<<<dim3(64, 80), 256>>>(W_x, p_Wxt, KX, N4U);
    convT_kernel<<<dim3(64, 16), 256>>>(W_h, p_Wht, Uc, N4U);
    gemm_k<<<dim3(Uc / 64, 1, 8), 256>>>(p_mean, ENCc, W_im, p_zp, ENCc, Uc, (size_t)Bc * Uc);
    gemm_k<<<dim3(Uc / 64, 1, 8), 256>>>(p_mean, ENCc, W_ic, p_zp + (size_t)8 * Bc * Uc, ENCc, Uc, (size_t)Bc * Uc);
    init_hc_kernel<<<Bc, Uc>>>(b_im, b_ic);
    att1h_kernel<<<dim3(Ac / 128, (Bc * Pc) / 64), 256>>>(b_ae);

    // ---- whole time loop in ONE persistent kernel ----
    loop_kernel<<<NB, 256>>>(b_ag, W_af, b_af, b_beta, b_lstm, b_out,
                             out_alpha, out_pred);
}